// round 2
// baseline (speedup 1.0000x reference)
#include <cuda_runtime.h>
#include <math.h>

#define B_    8
#define C_    512
#define N_    4096          // H*W = 64*64
#define MTOT  32768         // B_*N_
#define HEADS_ 8
#define DH    64
#define NSLICE 16           // n-range splits for MSA kernels

// ---------------- scratch (device globals; no allocs allowed) ----------------
__device__ float g_q    [MTOT * C_];
__device__ float g_k    [MTOT * C_];
__device__ float g_v    [MTOT * C_];
__device__ float g_kn   [MTOT * C_];
__device__ float g_qn   [MTOT * C_];
__device__ float g_vs   [MTOT * C_];
__device__ float g_prior[MTOT * C_];
__device__ float g_o    [MTOT * C_];
__device__ float g_p1   [MTOT * C_];
__device__ float g_ab   [B_ * C_ * C_];
__device__ float g_abT  [B_ * C_ * C_];
__device__ float g_Gp   [NSLICE * 64 * 64 * 64];   // slice, bh, d, e
__device__ float g_nkp  [NSLICE * 64 * 64];        // slice, bh, d
__device__ float g_nqp  [NSLICE * 64 * 64];
__device__ float g_attn [64 * 64 * 64];            // bh, d, e

// =============================================================================
// Generic NN SGEMM: C = alpha*(A[MxK] @ B[KxN]) (+bias) (+add), batched via z
// BM=128, BN=64, BK=16, 256 threads, 8x4 per thread.
// Requires M%128==0, N%64==0, K%16==0 (true for all uses here).
// =============================================================================
__global__ void sgemm_nn(const float* __restrict__ A, const float* __restrict__ Bm,
                         float* __restrict__ Cc, int M, int N, int K,
                         long sA, long sB, long sC,
                         const float* __restrict__ bias,
                         const float* __restrict__ add, float alpha)
{
    A  += (long)blockIdx.z * sA;
    Bm += (long)blockIdx.z * sB;
    Cc += (long)blockIdx.z * sC;
    const float* addp = add ? add + (long)blockIdx.z * sC : nullptr;

    int m0 = blockIdx.y * 128;
    int n0 = blockIdx.x * 64;

    __shared__ float As[16][128];
    __shared__ float Bs[16][64];

    int t  = threadIdx.x;
    int ty = t >> 4, tx = t & 15;

    float acc[8][4];
#pragma unroll
    for (int i = 0; i < 8; i++)
#pragma unroll
        for (int j = 0; j < 4; j++) acc[i][j] = 0.f;

    for (int k0 = 0; k0 < K; k0 += 16) {
#pragma unroll
        for (int l = 0; l < 2; l++) {
            int idx = t + l * 256;
            int row = idx >> 2;           // 0..127
            int f4  = idx & 3;            // 0..3
            float4 a = *(const float4*)(A + (long)(m0 + row) * K + k0 + f4 * 4);
            As[f4 * 4 + 0][row] = a.x;
            As[f4 * 4 + 1][row] = a.y;
            As[f4 * 4 + 2][row] = a.z;
            As[f4 * 4 + 3][row] = a.w;
        }
        {
            int kk = t >> 4, f4 = t & 15;
            *(float4*)&Bs[kk][f4 * 4] =
                *(const float4*)(Bm + (long)(k0 + kk) * N + n0 + f4 * 4);
        }
        __syncthreads();
#pragma unroll
        for (int kk = 0; kk < 16; kk++) {
            float a[8], bv[4];
            *(float4*)(a)     = *(float4*)&As[kk][ty * 8];
            *(float4*)(a + 4) = *(float4*)&As[kk][ty * 8 + 4];
            *(float4*)(bv)    = *(float4*)&Bs[kk][tx * 4];
#pragma unroll
            for (int i = 0; i < 8; i++)
#pragma unroll
                for (int j = 0; j < 4; j++) acc[i][j] += a[i] * bv[j];
        }
        __syncthreads();
    }

#pragma unroll
    for (int i = 0; i < 8; i++) {
        int m = m0 + ty * 8 + i;
        int n = n0 + tx * 4;
        float4 r;
        r.x = acc[i][0] * alpha; r.y = acc[i][1] * alpha;
        r.z = acc[i][2] * alpha; r.w = acc[i][3] * alpha;
        if (bias) {
            float4 b4 = *(const float4*)(bias + n);
            r.x += b4.x; r.y += b4.y; r.z += b4.z; r.w += b4.w;
        }
        if (addp) {
            float4 a4 = *(const float4*)(addp + (long)m * N + n);
            r.x += a4.x; r.y += a4.y; r.z += a4.z; r.w += a4.w;
        }
        *(float4*)(Cc + (long)m * N + n) = r;
    }
}

// =============================================================================
// TN SGEMM for SIF: C[i,j] = alpha * sum_k A[k*LDA+i] * B[k*LDB+j], batched z.
// M=N=512, K=4096. BM=128,BN=64,BK=16, 256 threads.
// =============================================================================
__global__ void sgemm_tn(const float* __restrict__ A, const float* __restrict__ Bm,
                         float* __restrict__ Cc, int M, int N, int K,
                         int LDA, int LDB, long sA, long sB, long sC, float alpha)
{
    A  += (long)blockIdx.z * sA;
    Bm += (long)blockIdx.z * sB;
    Cc += (long)blockIdx.z * sC;

    int m0 = blockIdx.y * 128;
    int n0 = blockIdx.x * 64;

    __shared__ float As[16][128];
    __shared__ float Bs[16][64];

    int t  = threadIdx.x;
    int ty = t >> 4, tx = t & 15;

    float acc[8][4];
#pragma unroll
    for (int i = 0; i < 8; i++)
#pragma unroll
        for (int j = 0; j < 4; j++) acc[i][j] = 0.f;

    for (int k0 = 0; k0 < K; k0 += 16) {
#pragma unroll
        for (int l = 0; l < 2; l++) {
            int idx = t + l * 256;
            int kk  = idx >> 5;           // 0..15
            int f4  = idx & 31;           // 0..31
            *(float4*)&As[kk][f4 * 4] =
                *(const float4*)(A + (long)(k0 + kk) * LDA + m0 + f4 * 4);
        }
        {
            int kk = t >> 4, f4 = t & 15;
            *(float4*)&Bs[kk][f4 * 4] =
                *(const float4*)(Bm + (long)(k0 + kk) * LDB + n0 + f4 * 4);
        }
        __syncthreads();
#pragma unroll
        for (int kk = 0; kk < 16; kk++) {
            float a[8], bv[4];
            *(float4*)(a)     = *(float4*)&As[kk][ty * 8];
            *(float4*)(a + 4) = *(float4*)&As[kk][ty * 8 + 4];
            *(float4*)(bv)    = *(float4*)&Bs[kk][tx * 4];
#pragma unroll
            for (int i = 0; i < 8; i++)
#pragma unroll
                for (int j = 0; j < 4; j++) acc[i][j] += a[i] * bv[j];
        }
        __syncthreads();
    }

#pragma unroll
    for (int i = 0; i < 8; i++) {
        int m = m0 + ty * 8 + i;
        int n = n0 + tx * 4;
        float4 r;
        r.x = acc[i][0] * alpha; r.y = acc[i][1] * alpha;
        r.z = acc[i][2] * alpha; r.w = acc[i][3] * alpha;
        *(float4*)(Cc + (long)m * N + n) = r;
    }
}

// =============================================================================
// Row LayerNorm (in-place): rows of length 512, one block (128 thr) per row.
// =============================================================================
__global__ void ln_rows(float* __restrict__ X, const float* __restrict__ gg,
                        const float* __restrict__ bb)
{
    long row = blockIdx.x;
    float* x = X + row * (long)C_;
    int t = threadIdx.x;
    float4 v = *(float4*)(x + t * 4);
    float s = v.x + v.y + v.z + v.w;
    float q = v.x * v.x + v.y * v.y + v.z * v.z + v.w * v.w;
#pragma unroll
    for (int o = 16; o; o >>= 1) {
        s += __shfl_xor_sync(0xffffffffu, s, o);
        q += __shfl_xor_sync(0xffffffffu, q, o);
    }
    __shared__ float ss[4], sq[4];
    if ((t & 31) == 0) { ss[t >> 5] = s; sq[t >> 5] = q; }
    __syncthreads();
    s = ss[0] + ss[1] + ss[2] + ss[3];
    q = sq[0] + sq[1] + sq[2] + sq[3];
    float mu  = s * (1.f / C_);
    float var = q * (1.f / C_) - mu * mu;
    float inv = rsqrtf(var + 1e-5f);
    float4 g4 = *(const float4*)(gg + t * 4);
    float4 b4 = *(const float4*)(bb + t * 4);
    v.x = (v.x - mu) * inv * g4.x + b4.x;
    v.y = (v.y - mu) * inv * g4.y + b4.y;
    v.z = (v.z - mu) * inv * g4.z + b4.z;
    v.w = (v.w - mu) * inv * g4.w + b4.w;
    *(float4*)(x + t * 4) = v;
}

// =============================================================================
// SIF softmax over rows of Ab (length 512), writing TRANSPOSED result
// AbT[b][j][i] = softmax_j(Ab[b][i][:])[j].  One block (128 thr) per row.
// =============================================================================
__global__ void softmax_ab(const float* __restrict__ Ab, float* __restrict__ AbT)
{
    int bi = blockIdx.x;           // b*512 + i
    int b  = bi >> 9;
    int i  = bi & 511;
    const float* row = Ab + (long)bi * 512;
    int t = threadIdx.x;
    float4 v = *(const float4*)(row + t * 4);
    float m = fmaxf(fmaxf(v.x, v.y), fmaxf(v.z, v.w));
#pragma unroll
    for (int o = 16; o; o >>= 1) m = fmaxf(m, __shfl_xor_sync(0xffffffffu, m, o));
    __shared__ float rm[4], rs[4];
    if ((t & 31) == 0) rm[t >> 5] = m;
    __syncthreads();
    m = fmaxf(fmaxf(rm[0], rm[1]), fmaxf(rm[2], rm[3]));
    float4 e;
    e.x = expf(v.x - m); e.y = expf(v.y - m);
    e.z = expf(v.z - m); e.w = expf(v.w - m);
    float s = e.x + e.y + e.z + e.w;
#pragma unroll
    for (int o = 16; o; o >>= 1) s += __shfl_xor_sync(0xffffffffu, s, o);
    if ((t & 31) == 0) rs[t >> 5] = s;
    __syncthreads();
    s = rs[0] + rs[1] + rs[2] + rs[3];
    float inv = 1.f / s;
    float* o = AbT + (long)b * 512 * 512 + i;
    o[(long)(t * 4 + 0) * 512] = e.x * inv;
    o[(long)(t * 4 + 1) * 512] = e.y * inv;
    o[(long)(t * 4 + 2) * 512] = e.z * inv;
    o[(long)(t * 4 + 3) * 512] = e.w * inv;
}

// =============================================================================
// MSA phase 1: per (bh, slice) partial Gram G[d,e]=sum_n k[n,d]q[n,e] + norms.
// Deterministic partials (no atomics). grid (64, NSLICE), 256 threads.
// =============================================================================
__global__ void msa_g()
{
    int bh = blockIdx.x;           // b*8 + h
    int sl = blockIdx.y;
    int b = bh >> 3, h = bh & 7;
    const int NS = N_ / NSLICE;    // 256
    int n0 = sl * NS;

    __shared__ float ks[16][64];
    __shared__ float qs[16][64];

    int t = threadIdx.x;
    int ty = t >> 4, tx = t & 15;

    const float* kb = g_k + (long)b * N_ * C_ + h * DH;
    const float* qb = g_q + (long)b * N_ * C_ + h * DH;

    float acc[4][4];
#pragma unroll
    for (int i = 0; i < 4; i++)
#pragma unroll
        for (int j = 0; j < 4; j++) acc[i][j] = 0.f;
    float ssk = 0.f, ssq = 0.f;

    int lkk = t >> 4;
    int lc4 = (t & 15) << 2;

    for (int nb = 0; nb < NS; nb += 16) {
        long roff = (long)(n0 + nb + lkk) * C_ + lc4;
        *(float4*)&ks[lkk][lc4] = *(const float4*)(kb + roff);
        *(float4*)&qs[lkk][lc4] = *(const float4*)(qb + roff);
        __syncthreads();
#pragma unroll
        for (int kk = 0; kk < 16; kk++) {
            float a[4], bv[4];
#pragma unroll
            for (int i = 0; i < 4; i++) a[i]  = ks[kk][ty * 4 + i];
#pragma unroll
            for (int j = 0; j < 4; j++) bv[j] = qs[kk][tx * 4 + j];
#pragma unroll
            for (int i = 0; i < 4; i++)
#pragma unroll
                for (int j = 0; j < 4; j++) acc[i][j] += a[i] * bv[j];
        }
        if (t < 64) {
#pragma unroll
            for (int kk = 0; kk < 16; kk++) {
                float kv = ks[kk][t], qv = qs[kk][t];
                ssk += kv * kv; ssq += qv * qv;
            }
        }
        __syncthreads();
    }

    float* Gb = g_Gp + ((long)sl * 64 + bh) * 4096;
#pragma unroll
    for (int i = 0; i < 4; i++)
#pragma unroll
        for (int j = 0; j < 4; j++)
            Gb[(ty * 4 + i) * 64 + tx * 4 + j] = acc[i][j];
    if (t < 64) {
        g_nkp[((long)sl * 64 + bh) * 64 + t] = ssk;
        g_nqp[((long)sl * 64 + bh) * 64 + t] = ssq;
    }
}

// =============================================================================
// MSA phase 2: reduce partials, scale by 1/(||k_d|| ||q_e||) * rescale[h],
// softmax over e.  grid = 64*64 (bh,d), 64 threads (e).
// =============================================================================
__global__ void msa_soft(const float* __restrict__ rescale)
{
    int r  = blockIdx.x;
    int bh = r >> 6;
    int d  = r & 63;
    int h  = bh & 7;
    int t  = threadIdx.x;

    float gsum = 0.f, nks = 0.f, nqs = 0.f;
#pragma unroll
    for (int sl = 0; sl < NSLICE; sl++) {
        gsum += g_Gp[((long)sl * 64 + bh) * 4096 + d * 64 + t];
        nks  += g_nkp[((long)sl * 64 + bh) * 64 + d];
        nqs  += g_nqp[((long)sl * 64 + bh) * 64 + t];
    }
    float nk = fmaxf(sqrtf(nks), 1e-12f);
    float nq = fmaxf(sqrtf(nqs), 1e-12f);
    float val = gsum * (rescale[h] / (nk * nq));

    float m = val;
#pragma unroll
    for (int o = 16; o; o >>= 1) m = fmaxf(m, __shfl_xor_sync(0xffffffffu, m, o));
    __shared__ float rm[2], rs[2];
    if ((t & 31) == 0) rm[t >> 5] = m;
    __syncthreads();
    m = fmaxf(rm[0], rm[1]);
    float e = expf(val - m);
    float s = e;
#pragma unroll
    for (int o = 16; o; o >>= 1) s += __shfl_xor_sync(0xffffffffu, s, o);
    if ((t & 31) == 0) rs[t >> 5] = s;
    __syncthreads();
    s = rs[0] + rs[1];
    g_attn[(long)bh * 4096 + d * 64 + t] = e / s;
}

// =============================================================================
// MSA phase 3: o[n, h*64+d] = sum_e attn[d,e] * (v[n,e]*prior[n,e]).
// grid (64, NSLICE), 256 threads.
// =============================================================================
__global__ void msa_o()
{
    int bh = blockIdx.x;
    int b = bh >> 3, h = bh & 7;
    int n0 = blockIdx.y * (N_ / NSLICE);   // 256-row range

    __shared__ float at[64][65];
    __shared__ float vg[16][64];

    int t = threadIdx.x;
#pragma unroll
    for (int l = 0; l < 16; l++) {
        int idx = l * 256 + t;
        at[idx >> 6][idx & 63] = g_attn[(long)bh * 4096 + idx];
    }
    __syncthreads();

    const float* vb = g_v     + (long)b * N_ * C_ + h * DH;
    const float* pb = g_prior + (long)b * N_ * C_ + h * DH;
    float*       ob = g_o     + (long)b * N_ * C_ + h * DH;

    int lkk = t >> 4;
    int lc4 = (t & 15) << 2;
    int ty = t >> 4;      // n within chunk (0..15)
    int tx = t & 15;      // d group: d = tx*4..tx*4+3

    for (int nb = 0; nb < 256; nb += 16) {
        long roff = (long)(n0 + nb + lkk) * C_ + lc4;
        float4 v4 = *(const float4*)(vb + roff);
        float4 p4 = *(const float4*)(pb + roff);
        float4 w4;
        w4.x = v4.x * p4.x; w4.y = v4.y * p4.y;
        w4.z = v4.z * p4.z; w4.w = v4.w * p4.w;
        *(float4*)&vg[lkk][lc4] = w4;
        __syncthreads();

        float s0 = 0.f, s1 = 0.f, s2 = 0.f, s3 = 0.f;
#pragma unroll
        for (int e = 0; e < 64; e++) {
            float vv = vg[ty][e];
            s0 += at[tx * 4 + 0][e] * vv;
            s1 += at[tx * 4 + 1][e] * vv;
            s2 += at[tx * 4 + 2][e] * vv;
            s3 += at[tx * 4 + 3][e] * vv;
        }
        float4 r; r.x = s0; r.y = s1; r.z = s2; r.w = s3;
        *(float4*)(ob + (long)(n0 + nb + ty) * C_ + tx * 4) = r;
        __syncthreads();
    }
}

// =============================================================================
// Depthwise 3x3 conv (NHWC), zero padding. Optional exact GELU, optional
// accumulate-into-output. One block = 8 pixels, 128 threads (c in float4).
// =============================================================================
__device__ __forceinline__ float gelu_exact(float x)
{
    return 0.5f * x * (1.f + erff(x * 0.70710678118654752f));
}

template <bool GELU, bool ACCUM>
__global__ void dwconv3x3(const float* __restrict__ in, const float* __restrict__ w,
                          float* __restrict__ out)
{
    int t = threadIdx.x;
    int c = t * 4;
    float wr[3][3][4];
#pragma unroll
    for (int ky = 0; ky < 3; ky++)
#pragma unroll
        for (int kx = 0; kx < 3; kx++)
#pragma unroll
            for (int i = 0; i < 4; i++)
                wr[ky][kx][i] = w[(long)(c + i) * 9 + ky * 3 + kx];

    long p0 = (long)blockIdx.x * 8;
    int b   = (int)(p0 >> 12);
    int yx0 = (int)(p0 & 4095);

#pragma unroll
    for (int px = 0; px < 8; px++) {
        int yx = yx0 + px;
        int y = yx >> 6, x = yx & 63;
        float ax = 0.f, ay = 0.f, az = 0.f, aw = 0.f;
#pragma unroll
        for (int ky = 0; ky < 3; ky++) {
            int yy = y + ky - 1;
            if (yy < 0 || yy > 63) continue;
#pragma unroll
            for (int kx = 0; kx < 3; kx++) {
                int xx = x + kx - 1;
                if (xx < 0 || xx > 63) continue;
                float4 v = *(const float4*)(in + ((long)(b << 12) + (yy << 6) + xx) * C_ + c);
                ax += v.x * wr[ky][kx][0];
                ay += v.y * wr[ky][kx][1];
                az += v.z * wr[ky][kx][2];
                aw += v.w * wr[ky][kx][3];
            }
        }
        if (GELU) {
            ax = gelu_exact(ax); ay = gelu_exact(ay);
            az = gelu_exact(az); aw = gelu_exact(aw);
        }
        long off = ((long)(b << 12) + yx) * C_ + c;
        if (ACCUM) {
            float4 o = *(float4*)(out + off);
            o.x += ax; o.y += ay; o.z += az; o.w += aw;
            *(float4*)(out + off) = o;
        } else {
            float4 o; o.x = ax; o.y = ay; o.z = az; o.w = aw;
            *(float4*)(out + off) = o;
        }
    }
}

// =============================================================================
// Host launcher
// =============================================================================
extern "C" void kernel_launch(void* const* d_in, const int* in_sizes, int n_in,
                              void* d_out, int out_size)
{
    const float* x       = (const float*)d_in[0];
    const float* illu    = (const float*)d_in[1];
    const float* sem     = (const float*)d_in[2];
    const float* Wk_sif  = (const float*)d_in[3];
    const float* Wq_sif  = (const float*)d_in[4];
    const float* Wv_sif  = (const float*)d_in[5];
    const float* ln_g    = (const float*)d_in[6];
    const float* ln_b    = (const float*)d_in[7];
    const float* Wq      = (const float*)d_in[8];
    const float* Wk      = (const float*)d_in[9];
    const float* Wv      = (const float*)d_in[10];
    const float* rescale = (const float*)d_in[11];
    const float* proj_w  = (const float*)d_in[12];
    const float* proj_b  = (const float*)d_in[13];
    const float* dw1     = (const float*)d_in[14];
    const float* dw2     = (const float*)d_in[15];
    float* out = (float*)d_out;

    float *q, *k, *v, *kn, *qn, *vs, *prior, *o, *p1, *ab, *abT;
    cudaGetSymbolAddress((void**)&q,     g_q);
    cudaGetSymbolAddress((void**)&k,     g_k);
    cudaGetSymbolAddress((void**)&v,     g_v);
    cudaGetSymbolAddress((void**)&kn,    g_kn);
    cudaGetSymbolAddress((void**)&qn,    g_qn);
    cudaGetSymbolAddress((void**)&vs,    g_vs);
    cudaGetSymbolAddress((void**)&prior, g_prior);
    cudaGetSymbolAddress((void**)&o,     g_o);
    cudaGetSymbolAddress((void**)&p1,    g_p1);
    cudaGetSymbolAddress((void**)&ab,    g_ab);
    cudaGetSymbolAddress((void**)&abT,   g_abT);

    dim3 blk(256);
    dim3 gA(C_ / 64, MTOT / 128, 1);

    // Stage A: six (32768x512)@(512x512) GEMMs
    sgemm_nn<<<gA, blk>>>(x,    Wq,     q,  MTOT, C_, C_, 0, 0, 0, nullptr, nullptr, 1.f);
    sgemm_nn<<<gA, blk>>>(x,    Wk,     k,  MTOT, C_, C_, 0, 0, 0, nullptr, nullptr, 1.f);
    sgemm_nn<<<gA, blk>>>(x,    Wv,     v,  MTOT, C_, C_, 0, 0, 0, nullptr, nullptr, 1.f);
    sgemm_nn<<<gA, blk>>>(illu, Wk_sif, kn, MTOT, C_, C_, 0, 0, 0, nullptr, nullptr, 1.f);
    sgemm_nn<<<gA, blk>>>(sem,  Wq_sif, qn, MTOT, C_, C_, 0, 0, 0, nullptr, nullptr, 1.f);
    sgemm_nn<<<gA, blk>>>(illu, Wv_sif, vs, MTOT, C_, C_, 0, 0, 0, nullptr, nullptr, 1.f);

    // LayerNorm of Kn, Qn
    ln_rows<<<MTOT, 128>>>(kn, ln_g, ln_b);
    ln_rows<<<MTOT, 128>>>(qn, ln_g, ln_b);

    // SIF channel attention: Ab[b] = (Qn^T Kn)/sqrt(C), softmax, prior = V AbT + V
    dim3 gAb(C_ / 64, C_ / 128, B_);
    sgemm_tn<<<gAb, blk>>>(qn, kn, ab, C_, C_, N_, C_, C_,
                           (long)N_ * C_, (long)N_ * C_, (long)C_ * C_,
                           0.044194173824159216f /* 1/sqrt(512) */);
    softmax_ab<<<B_ * C_, 128>>>(ab, abT);
    dim3 gPr(C_ / 64, N_ / 128, B_);
    sgemm_nn<<<gPr, blk>>>(vs, abT, prior, N_, C_, C_,
                           (long)N_ * C_, (long)C_ * C_, (long)N_ * C_,
                           nullptr, vs, 1.f);

    // FG-MSA (per b,head 64x64 channel attention)
    msa_g<<<dim3(64, NSLICE), 256>>>();
    msa_soft<<<64 * 64, 64>>>(rescale);
    msa_o<<<dim3(64, NSLICE), 256>>>();

    // Output projection directly into d_out
    sgemm_nn<<<gA, blk>>>(o, proj_w, out, MTOT, C_, C_, 0, 0, 0, proj_b, nullptr, 1.f);

    // Positional branch: dwconv -> GELU -> dwconv, accumulated into d_out
    dwconv3x3<true,  false><<<MTOT / 8, 128>>>(v,  dw1, p1);
    dwconv3x3<false, true ><<<MTOT / 8, 128>>>(p1, dw2, out);
}

// round 4
// speedup vs baseline: 1.9614x; 1.9614x over previous
#include <cuda_runtime.h>
#include <cuda_fp16.h>
#include <math.h>
#include <stdint.h>

#define B_    8
#define C_    512
#define N_    4096
#define MTOT  32768
#define DH    64
#define NSLICE 16

// ---------------------------------------------------------------------------
// helpers (portable PTX only: cp.async, ldmatrix, mma.sync — NO tcgen05)
// ---------------------------------------------------------------------------
__device__ __forceinline__ uint32_t smem_u32(const void* p) {
    uint32_t a;
    asm("{ .reg .u64 t; cvta.to.shared.u64 t, %1; cvt.u32.u64 %0, t; }" : "=r"(a) : "l"(p));
    return a;
}
__device__ __forceinline__ void cp_async16(uint32_t dst, const void* src) {
    asm volatile("cp.async.cg.shared.global [%0], [%1], 16;" :: "r"(dst), "l"(src));
}
#define CP_COMMIT() asm volatile("cp.async.commit_group;" ::: "memory")
#define CP_WAIT(n)  asm volatile("cp.async.wait_group %0;" :: "n"(n) : "memory")

#define LDSM_X4(r, a)                                                          \
    asm volatile("ldmatrix.sync.aligned.m8n8.x4.shared.b16 {%0,%1,%2,%3},[%4];"\
        : "=r"((r)[0]), "=r"((r)[1]), "=r"((r)[2]), "=r"((r)[3]) : "r"(a))

__device__ __forceinline__ void mma16816(float* d, const uint32_t* a, const uint32_t* b) {
    asm volatile("mma.sync.aligned.m16n8k16.row.col.f32.f16.f16.f32 "
        "{%0,%1,%2,%3},{%4,%5,%6,%7},{%8,%9},{%0,%1,%2,%3};"
        : "+f"(d[0]), "+f"(d[1]), "+f"(d[2]), "+f"(d[3])
        : "r"(a[0]), "r"(a[1]), "r"(a[2]), "r"(a[3]), "r"(b[0]), "r"(b[1]));
}

// ---------------------------------------------------------------------------
// scratch
// ---------------------------------------------------------------------------
__device__ float g_qkv  [MTOT * 1536];
__device__ float g_knvs [MTOT * 1024];
__device__ float g_qn   [MTOT * C_];
__device__ float g_prior[MTOT * C_];
__device__ float g_p1   [MTOT * C_];
__device__ float g_ab   [B_ * C_ * C_];
__device__ __half g_xh[MTOT * C_],  g_xl[MTOT * C_];
__device__ __half g_ih[MTOT * C_],  g_il[MTOT * C_];
__device__ __half g_sh[MTOT * C_],  g_sl[MTOT * C_];
__device__ __half g_vsh[MTOT * C_], g_vsl[MTOT * C_];
__device__ __half g_oh[MTOT * C_],  g_ol[MTOT * C_];
__device__ __half g_knTh[B_ * C_ * N_], g_knTl[B_ * C_ * N_];
__device__ __half g_qnTh[B_ * C_ * N_], g_qnTl[B_ * C_ * N_];
__device__ __half g_abh[B_ * C_ * C_],  g_abl[B_ * C_ * C_];
__device__ __half g_w3h[1536 * C_], g_w3l[1536 * C_];
__device__ __half g_w2h[1024 * C_], g_w2l[1024 * C_];
__device__ __half g_wqh[C_ * C_],   g_wql[C_ * C_];
__device__ __half g_wph[C_ * C_],   g_wpl[C_ * C_];
__device__ float g_Gp [NSLICE * 64 * 64 * 64];
__device__ float g_nkp[NSLICE * 64 * 64];
__device__ float g_nqp[NSLICE * 64 * 64];
__device__ float g_attn[64 * 64 * 64];

// ---------------------------------------------------------------------------
// HMMA GEMM: C[m,n] = alpha * sum_k (Ah+Al)[m,k]*(Bh+Bl)[n,k]  (3-pass)
// CTA tile 128x128, BK=32, 8 warps (2Mx4N), double-buffered cp.async.
// Tiles in smem: rows padded to 80B (5 chunks of 16B) -> conflict-free LDSM.
// ---------------------------------------------------------------------------
#define TILE_B   10240            // 128 rows * 80 B
#define STAGE_B  (4 * TILE_B)     // Ah, Al, Bh, Bl
#define GEMM_SMEM (2 * STAGE_B)   // 81920

__global__ __launch_bounds__(256, 1) void gemm_h3(
    const __half* __restrict__ Ah, const __half* __restrict__ Al,
    const __half* __restrict__ Bh, const __half* __restrict__ Bl,
    float* __restrict__ C, int K, int ldA, int ldB, int ldC,
    long sA, long sB, long sC,
    const float* __restrict__ bias,
    const float* __restrict__ res, int ldRes, long sRes, float alpha)
{
    extern __shared__ char smem[];
    const int m0 = blockIdx.y * 128, n0 = blockIdx.x * 128;
    Ah += blockIdx.z * sA; Al += blockIdx.z * sA;
    Bh += blockIdx.z * sB; Bl += blockIdx.z * sB;
    C  += blockIdx.z * sC;
    if (res) res += blockIdx.z * sRes;

    const int tid = threadIdx.x;
    const int wid = tid >> 5, lane = tid & 31;
    const int wm = (wid & 1) * 64;
    const int wn = (wid >> 1) * 32;
    const uint32_t sbase = smem_u32(smem);

    // copy mapping: 512 chunks (16B) per tile; 2 per thread
    const int r0c = tid >> 2, c0c = tid & 3;           // chunk tid
    const int r1c = (tid + 256) >> 2, c1c = tid & 3;   // chunk tid+256

    float acc[4][4][4];
#pragma unroll
    for (int i = 0; i < 4; i++)
#pragma unroll
        for (int j = 0; j < 4; j++)
#pragma unroll
            for (int p = 0; p < 4; p++) acc[i][j][p] = 0.f;

    const int KB = K >> 5;

#define STAGE_LOAD(kb, buf) do {                                               \
    int k0 = (kb) << 5;                                                        \
    uint32_t st = sbase + (buf) * STAGE_B;                                     \
    {                                                                          \
        uint32_t so = (uint32_t)(r0c * 80 + c0c * 16);                         \
        long ga = (long)(m0 + r0c) * ldA + k0 + c0c * 8;                       \
        long gb = (long)(n0 + r0c) * ldB + k0 + c0c * 8;                       \
        cp_async16(st + so,              Ah + ga);                             \
        cp_async16(st + TILE_B + so,     Al + ga);                             \
        cp_async16(st + 2 * TILE_B + so, Bh + gb);                             \
        cp_async16(st + 3 * TILE_B + so, Bl + gb);                             \
    }                                                                          \
    {                                                                          \
        uint32_t so = (uint32_t)(r1c * 80 + c1c * 16);                         \
        long ga = (long)(m0 + r1c) * ldA + k0 + c1c * 8;                       \
        long gb = (long)(n0 + r1c) * ldB + k0 + c1c * 8;                       \
        cp_async16(st + so,              Ah + ga);                             \
        cp_async16(st + TILE_B + so,     Al + ga);                             \
        cp_async16(st + 2 * TILE_B + so, Bh + gb);                             \
        cp_async16(st + 3 * TILE_B + so, Bl + gb);                             \
    }                                                                          \
    CP_COMMIT();                                                               \
} while (0)

    STAGE_LOAD(0, 0);

    const int lg = lane >> 3, lr = lane & 7;

    for (int kb = 0; kb < KB; kb++) {
        if (kb + 1 < KB) {
            STAGE_LOAD(kb + 1, (kb + 1) & 1);
            CP_WAIT(1);
        } else {
            CP_WAIT(0);
        }
        __syncthreads();
        uint32_t st = sbase + (kb & 1) * STAGE_B;

#pragma unroll
        for (int ks = 0; ks < 2; ks++) {
            const int cb = ks * 2;
            uint32_t ah[4][4], al[4][4], bh[4][2], bl[4][2];
            // A fragments: lanes 0-7 rows m..m+7 @cb, 8-15 rows+8 @cb,
            //              16-23 rows @cb+1, 24-31 rows+8 @cb+1
#pragma unroll
            for (int mi = 0; mi < 4; mi++) {
                int row = wm + mi * 16 + lr + (lg & 1) * 8;
                int ch  = cb + (lg >> 1);
                uint32_t a = st + (uint32_t)(row * 80 + ch * 16);
                LDSM_X4(ah[mi], a);
                LDSM_X4(al[mi], a + TILE_B);
            }
            // B fragments (two n-frags per x4):
            // lanes 0-7 rows n..n+7 @cb, 8-15 same rows @cb+1,
            // 16-23 rows+8 @cb, 24-31 rows+8 @cb+1
#pragma unroll
            for (int np = 0; np < 2; np++) {
                int row = wn + np * 16 + lr + (lg >> 1) * 8;
                int ch  = cb + (lg & 1);
                uint32_t a = st + 2 * TILE_B + (uint32_t)(row * 80 + ch * 16);
                uint32_t t4[4];
                LDSM_X4(t4, a);
                bh[np * 2][0] = t4[0]; bh[np * 2][1] = t4[1];
                bh[np * 2 + 1][0] = t4[2]; bh[np * 2 + 1][1] = t4[3];
                LDSM_X4(t4, a + TILE_B);
                bl[np * 2][0] = t4[0]; bl[np * 2][1] = t4[1];
                bl[np * 2 + 1][0] = t4[2]; bl[np * 2 + 1][1] = t4[3];
            }
#pragma unroll
            for (int mi = 0; mi < 4; mi++)
#pragma unroll
                for (int nj = 0; nj < 4; nj++) {
                    mma16816(acc[mi][nj], ah[mi], bh[nj]);
                    mma16816(acc[mi][nj], ah[mi], bl[nj]);
                    mma16816(acc[mi][nj], al[mi], bh[nj]);
                }
        }
        __syncthreads();
    }

    // epilogue
    const int er = lane >> 2, ec = (lane & 3) * 2;
#pragma unroll
    for (int mi = 0; mi < 4; mi++)
#pragma unroll
        for (int nj = 0; nj < 4; nj++) {
            int col = n0 + wn + nj * 8 + ec;
#pragma unroll
            for (int p = 0; p < 2; p++) {
                int row = m0 + wm + mi * 16 + er + p * 8;
                float2 v;
                v.x = acc[mi][nj][p * 2 + 0] * alpha;
                v.y = acc[mi][nj][p * 2 + 1] * alpha;
                if (bias) { v.x += bias[col]; v.y += bias[col + 1]; }
                if (res) {
                    float2 rv = *(const float2*)(res + (long)row * ldRes + col);
                    v.x += rv.x; v.y += rv.y;
                }
                *(float2*)(C + (long)row * ldC + col) = v;
            }
        }
}

// ---------------------------------------------------------------------------
// fp32 -> fp16 hi/lo split (contiguous)
// ---------------------------------------------------------------------------
__global__ void split_k(const float* __restrict__ in, __half* __restrict__ h,
                        __half* __restrict__ l, long n4)
{
    long i = ((long)blockIdx.x * blockDim.x + threadIdx.x);
    if (i >= n4) return;
    i *= 4;
    float4 v = *(const float4*)(in + i);
    __half hx = __float2half_rn(v.x), hy = __float2half_rn(v.y);
    __half hz = __float2half_rn(v.z), hw = __float2half_rn(v.w);
    *(__half2*)(h + i)     = __halves2half2(hx, hy);
    *(__half2*)(h + i + 2) = __halves2half2(hz, hw);
    *(__half2*)(l + i) = __halves2half2(
        __float2half_rn(v.x - __half2float(hx)),
        __float2half_rn(v.y - __half2float(hy)));
    *(__half2*)(l + i + 2) = __halves2half2(
        __float2half_rn(v.z - __half2float(hz)),
        __float2half_rn(v.w - __half2float(hw)));
}

// strided rows (512 cols) -> compact split
__global__ void split_str(const float* __restrict__ in, int ldIn,
                          __half* __restrict__ h, __half* __restrict__ l)
{
    long t = (long)blockIdx.x * 256 + threadIdx.x;
    long row = t >> 7;
    int c = (int)(t & 127) * 4;
    float4 v = *(const float4*)(in + row * ldIn + c);
    long o = row * C_ + c;
    __half hx = __float2half_rn(v.x), hy = __float2half_rn(v.y);
    __half hz = __float2half_rn(v.z), hw = __float2half_rn(v.w);
    *(__half2*)(h + o)     = __halves2half2(hx, hy);
    *(__half2*)(h + o + 2) = __halves2half2(hz, hw);
    *(__half2*)(l + o) = __halves2half2(
        __float2half_rn(v.x - __half2float(hx)),
        __float2half_rn(v.y - __half2float(hy)));
    *(__half2*)(l + o + 2) = __halves2half2(
        __float2half_rn(v.z - __half2float(hz)),
        __float2half_rn(v.w - __half2float(hw)));
}

// ---------------------------------------------------------------------------
// transpose + split: fp32 [R,C](ldIn) -> fp16 hi/lo [C,R](ldOut), batched z
// ---------------------------------------------------------------------------
__global__ void transpose_split(const float* __restrict__ in, int ldIn, long sIn,
                                __half* __restrict__ oh, __half* __restrict__ ol,
                                int ldOut, long sOut)
{
    in += blockIdx.z * sIn; oh += blockIdx.z * sOut; ol += blockIdx.z * sOut;
    __shared__ float tile[32][33];
    int c0 = blockIdx.x * 32, r0 = blockIdx.y * 32;
    int tx = threadIdx.x, ty = threadIdx.y;
#pragma unroll
    for (int i = 0; i < 4; i++)
        tile[ty + 8 * i][tx] = in[(long)(r0 + ty + 8 * i) * ldIn + c0 + tx];
    __syncthreads();
#pragma unroll
    for (int i = 0; i < 4; i++) {
        float v = tile[tx][ty + 8 * i];
        __half hh = __float2half_rn(v);
        long o = (long)(c0 + ty + 8 * i) * ldOut + r0 + tx;
        oh[o] = hh;
        ol[o] = __float2half_rn(v - __half2float(hh));
    }
}

// ---------------------------------------------------------------------------
// LayerNorm rows (512), strided, in place
// ---------------------------------------------------------------------------
__global__ void ln_rows(float* __restrict__ X, int ld,
                        const float* __restrict__ gg, const float* __restrict__ bb)
{
    long row = blockIdx.x;
    float* x = X + row * (long)ld;
    int t = threadIdx.x;
    float4 v = *(float4*)(x + t * 4);
    float s = v.x + v.y + v.z + v.w;
    float q = v.x * v.x + v.y * v.y + v.z * v.z + v.w * v.w;
#pragma unroll
    for (int o = 16; o; o >>= 1) {
        s += __shfl_xor_sync(0xffffffffu, s, o);
        q += __shfl_xor_sync(0xffffffffu, q, o);
    }
    __shared__ float ss[4], sq[4];
    if ((t & 31) == 0) { ss[t >> 5] = s; sq[t >> 5] = q; }
    __syncthreads();
    s = ss[0] + ss[1] + ss[2] + ss[3];
    q = sq[0] + sq[1] + sq[2] + sq[3];
    float mu = s * (1.f / C_);
    float var = q * (1.f / C_) - mu * mu;
    float inv = rsqrtf(var + 1e-5f);
    float4 g4 = *(const float4*)(gg + t * 4);
    float4 b4 = *(const float4*)(bb + t * 4);
    v.x = (v.x - mu) * inv * g4.x + b4.x;
    v.y = (v.y - mu) * inv * g4.y + b4.y;
    v.z = (v.z - mu) * inv * g4.z + b4.z;
    v.w = (v.w - mu) * inv * g4.w + b4.w;
    *(float4*)(x + t * 4) = v;
}

// ---------------------------------------------------------------------------
// SIF softmax rows -> fp16 hi/lo (row-major)
// ---------------------------------------------------------------------------
__global__ void softmax_ab(const float* __restrict__ Ab,
                           __half* __restrict__ oh, __half* __restrict__ ol)
{
    long bi = blockIdx.x;
    const float* row = Ab + bi * 512;
    int t = threadIdx.x;
    float4 v = *(const float4*)(row + t * 4);
    float m = fmaxf(fmaxf(v.x, v.y), fmaxf(v.z, v.w));
#pragma unroll
    for (int o = 16; o; o >>= 1) m = fmaxf(m, __shfl_xor_sync(0xffffffffu, m, o));
    __shared__ float rm[4], rs[4];
    if ((t & 31) == 0) rm[t >> 5] = m;
    __syncthreads();
    m = fmaxf(fmaxf(rm[0], rm[1]), fmaxf(rm[2], rm[3]));
    float4 e;
    e.x = expf(v.x - m); e.y = expf(v.y - m);
    e.z = expf(v.z - m); e.w = expf(v.w - m);
    float s = e.x + e.y + e.z + e.w;
#pragma unroll
    for (int o = 16; o; o >>= 1) s += __shfl_xor_sync(0xffffffffu, s, o);
    if ((t & 31) == 0) rs[t >> 5] = s;
    __syncthreads();
    s = rs[0] + rs[1] + rs[2] + rs[3];
    float inv = 1.f / s;
    e.x *= inv; e.y *= inv; e.z *= inv; e.w *= inv;
    long o = bi * 512 + t * 4;
    __half hx = __float2half_rn(e.x), hy = __float2half_rn(e.y);
    __half hz = __float2half_rn(e.z), hw = __float2half_rn(e.w);
    *(__half2*)(oh + o)     = __halves2half2(hx, hy);
    *(__half2*)(oh + o + 2) = __halves2half2(hz, hw);
    *(__half2*)(ol + o) = __halves2half2(
        __float2half_rn(e.x - __half2float(hx)),
        __float2half_rn(e.y - __half2float(hy)));
    *(__half2*)(ol + o + 2) = __halves2half2(
        __float2half_rn(e.z - __half2float(hz)),
        __float2half_rn(e.w - __half2float(hw)));
}

// ---------------------------------------------------------------------------
// FG-MSA (fp32 SIMT)
// ---------------------------------------------------------------------------
__global__ void msa_g()
{
    int bh = blockIdx.x, sl = blockIdx.y;
    int b = bh >> 3, h = bh & 7;
    const int NS = N_ / NSLICE;
    int n0 = sl * NS;
    __shared__ float ks[16][64];
    __shared__ float qs[16][64];
    int t = threadIdx.x;
    int ty = t >> 4, tx = t & 15;
    const float* qb = g_qkv + (long)b * N_ * 1536 + h * DH;
    const float* kb = qb + 512;
    float acc[4][4];
#pragma unroll
    for (int i = 0; i < 4; i++)
#pragma unroll
        for (int j = 0; j < 4; j++) acc[i][j] = 0.f;
    float ssk = 0.f, ssq = 0.f;
    int lkk = t >> 4, lc4 = (t & 15) << 2;
    for (int nb = 0; nb < NS; nb += 16) {
        long roff = (long)(n0 + nb + lkk) * 1536 + lc4;
        *(float4*)&ks[lkk][lc4] = *(const float4*)(kb + roff);
        *(float4*)&qs[lkk][lc4] = *(const float4*)(qb + roff);
        __syncthreads();
#pragma unroll
        for (int kk = 0; kk < 16; kk++) {
            float a[4], bv[4];
#pragma unroll
            for (int i = 0; i < 4; i++) a[i] = ks[kk][ty * 4 + i];
#pragma unroll
            for (int j = 0; j < 4; j++) bv[j] = qs[kk][tx * 4 + j];
#pragma unroll
            for (int i = 0; i < 4; i++)
#pragma unroll
                for (int j = 0; j < 4; j++) acc[i][j] += a[i] * bv[j];
        }
        if (t < 64) {
#pragma unroll
            for (int kk = 0; kk < 16; kk++) {
                float kv = ks[kk][t], qv = qs[kk][t];
                ssk += kv * kv; ssq += qv * qv;
            }
        }
        __syncthreads();
    }
    float* Gb = g_Gp + ((long)sl * 64 + bh) * 4096;
#pragma unroll
    for (int i = 0; i < 4; i++)
#pragma unroll
        for (int j = 0; j < 4; j++)
            Gb[(ty * 4 + i) * 64 + tx * 4 + j] = acc[i][j];
    if (t < 64) {
        g_nkp[((long)sl * 64 + bh) * 64 + t] = ssk;
        g_nqp[((long)sl * 64 + bh) * 64 + t] = ssq;
    }
}

__global__ void msa_soft(const float* __restrict__ rescale)
{
    int r = blockIdx.x;
    int bh = r >> 6, d = r & 63, h = bh & 7;
    int t = threadIdx.x;
    float gsum = 0.f, nks = 0.f, nqs = 0.f;
#pragma unroll
    for (int sl = 0; sl < NSLICE; sl++) {
        gsum += g_Gp[((long)sl * 64 + bh) * 4096 + d * 64 + t];
        nks  += g_nkp[((long)sl * 64 + bh) * 64 + d];
        nqs  += g_nqp[((long)sl * 64 + bh) * 64 + t];
    }
    float nk = fmaxf(sqrtf(nks), 1e-12f);
    float nq = fmaxf(sqrtf(nqs), 1e-12f);
    float val = gsum * (rescale[h] / (nk * nq));
    float m = val;
#pragma unroll
    for (int o = 16; o; o >>= 1) m = fmaxf(m, __shfl_xor_sync(0xffffffffu, m, o));
    __shared__ float rm[2], rs[2];
    if ((t & 31) == 0) rm[t >> 5] = m;
    __syncthreads();
    m = fmaxf(rm[0], rm[1]);
    float e = expf(val - m);
    float s = e;
#pragma unroll
    for (int o = 16; o; o >>= 1) s += __shfl_xor_sync(0xffffffffu, s, o);
    if ((t & 31) == 0) rs[t >> 5] = s;
    __syncthreads();
    s = rs[0] + rs[1];
    g_attn[(long)bh * 4096 + d * 64 + t] = e / s;
}

__global__ void msa_o()
{
    int bh = blockIdx.x;
    int b = bh >> 3, h = bh & 7;
    int n0 = blockIdx.y * (N_ / NSLICE);
    __shared__ float at[64][65];
    __shared__ float vg[16][64];
    int t = threadIdx.x;
#pragma unroll
    for (int l = 0; l < 16; l++) {
        int idx = l * 256 + t;
        at[idx >> 6][idx & 63] = g_attn[(long)bh * 4096 + idx];
    }
    __syncthreads();
    const float* vb = g_qkv + (long)b * N_ * 1536 + 1024 + h * DH;
    const float* pb = g_prior + (long)b * N_ * C_ + h * DH;
    long obase = (long)b * N_ * C_ + h * DH;
    int lkk = t >> 4, lc4 = (t & 15) << 2;
    int ty = t >> 4, tx = t & 15;
    for (int nb = 0; nb < 256; nb += 16) {
        {
            long rv = (long)(n0 + nb + lkk) * 1536 + lc4;
            long rp = (long)(n0 + nb + lkk) * C_ + lc4;
            float4 v4 = *(const float4*)(vb + rv);
            float4 p4 = *(const float4*)(pb + rp);
            float4 w4;
            w4.x = v4.x * p4.x; w4.y = v4.y * p4.y;
            w4.z = v4.z * p4.z; w4.w = v4.w * p4.w;
            *(float4*)&vg[lkk][lc4] = w4;
        }
        __syncthreads();
        float s0 = 0.f, s1 = 0.f, s2 = 0.f, s3 = 0.f;
#pragma unroll
        for (int e = 0; e < 64; e++) {
            float vv = vg[ty][e];
            s0 += at[tx * 4 + 0][e] * vv;
            s1 += at[tx * 4 + 1][e] * vv;
            s2 += at[tx * 4 + 2][e] * vv;
            s3 += at[tx * 4 + 3][e] * vv;
        }
        long off = obase + (long)(n0 + nb + ty) * C_ + tx * 4;
        __half hx = __float2half_rn(s0), hy = __float2half_rn(s1);
        __half hz = __float2half_rn(s2), hw = __float2half_rn(s3);
        *(__half2*)(g_oh + off)     = __halves2half2(hx, hy);
        *(__half2*)(g_oh + off + 2) = __halves2half2(hz, hw);
        *(__half2*)(g_ol + off) = __halves2half2(
            __float2half_rn(s0 - __half2float(hx)),
            __float2half_rn(s1 - __half2float(hy)));
        *(__half2*)(g_ol + off + 2) = __halves2half2(
            __float2half_rn(s2 - __half2float(hz)),
            __float2half_rn(s3 - __half2float(hw)));
        __syncthreads();
    }
}

// ---------------------------------------------------------------------------
// depthwise conv
// ---------------------------------------------------------------------------
__device__ __forceinline__ float gelu_exact(float x)
{
    return 0.5f * x * (1.f + erff(x * 0.70710678118654752f));
}
template <bool GELU, bool ACCUM>
__global__ void dwconv3x3(const float* __restrict__ in, int ldIn,
                          const float* __restrict__ w, float* __restrict__ out)
{
    int t = threadIdx.x;
    int c = t * 4;
    float wr[3][3][4];
#pragma unroll
    for (int ky = 0; ky < 3; ky++)
#pragma unroll
        for (int kx = 0; kx < 3; kx++)
#pragma unroll
            for (int i = 0; i < 4; i++)
                wr[ky][kx][i] = w[(long)(c + i) * 9 + ky * 3 + kx];
    long p0 = (long)blockIdx.x * 8;
    int b = (int)(p0 >> 12);
    int yx0 = (int)(p0 & 4095);
#pragma unroll
    for (int px = 0; px < 8; px++) {
        int yx = yx0 + px;
        int y = yx >> 6, x = yx & 63;
        float ax = 0.f, ay = 0.f, az = 0.f, aw = 0.f;
#pragma unroll
        for (int ky = 0; ky < 3; ky++) {
            int yy = y + ky - 1;
            if (yy < 0 || yy > 63) continue;
#pragma unroll
            for (int kx = 0; kx < 3; kx++) {
                int xx = x + kx - 1;
                if (xx < 0 || xx > 63) continue;
                float4 v = *(const float4*)(in + ((long)(b << 12) + (yy << 6) + xx) * ldIn + c);
                ax += v.x * wr[ky][kx][0];
                ay += v.y * wr[ky][kx][1];
                az += v.z * wr[ky][kx][2];
                aw += v.w * wr[ky][kx][3];
            }
        }
        if (GELU) {
            ax = gelu_exact(ax); ay = gelu_exact(ay);
            az = gelu_exact(az); aw = gelu_exact(aw);
        }
        long off = ((long)(b << 12) + yx) * C_ + c;
        if (ACCUM) {
            float4 o = *(float4*)(out + off);
            o.x += ax; o.y += ay; o.z += az; o.w += aw;
            *(float4*)(out + off) = o;
        } else {
            float4 o; o.x = ax; o.y = ay; o.z = az; o.w = aw;
            *(float4*)(out + off) = o;
        }
    }
}

// ---------------------------------------------------------------------------
// host
// ---------------------------------------------------------------------------
extern "C" void kernel_launch(void* const* d_in, const int* in_sizes, int n_in,
                              void* d_out, int out_size)
{
    const float* x       = (const float*)d_in[0];
    const float* illu    = (const float*)d_in[1];
    const float* sem     = (const float*)d_in[2];
    const float* Wk_sif  = (const float*)d_in[3];
    const float* Wq_sif  = (const float*)d_in[4];
    const float* Wv_sif  = (const float*)d_in[5];
    const float* ln_g    = (const float*)d_in[6];
    const float* ln_b    = (const float*)d_in[7];
    const float* Wq      = (const float*)d_in[8];
    const float* Wk      = (const float*)d_in[9];
    const float* Wv      = (const float*)d_in[10];
    const float* rescale = (const float*)d_in[11];
    const float* proj_w  = (const float*)d_in[12];
    const float* proj_b  = (const float*)d_in[13];
    const float* dw1     = (const float*)d_in[14];
    const float* dw2     = (const float*)d_in[15];
    float* out = (float*)d_out;

    cudaFuncSetAttribute(gemm_h3, cudaFuncAttributeMaxDynamicSharedMemorySize, GEMM_SMEM);

#define SYM(p, s) do { void* _t; cudaGetSymbolAddress(&_t, s); p = (decltype(p))_t; } while (0)
    float *qkv, *knvs, *qn, *prior, *p1, *ab;
    __half *xh, *xl, *ih, *il, *sh, *sl, *vsh, *vsl, *oh, *ol;
    __half *knTh, *knTl, *qnTh, *qnTl, *abh, *abl;
    __half *w3h, *w3l, *w2h, *w2l, *wqh, *wql, *wph, *wpl;
    SYM(qkv, g_qkv);   SYM(knvs, g_knvs); SYM(qn, g_qn); SYM(prior, g_prior);
    SYM(p1, g_p1);     SYM(ab, g_ab);
    SYM(xh, g_xh); SYM(xl, g_xl); SYM(ih, g_ih); SYM(il, g_il);
    SYM(sh, g_sh); SYM(sl, g_sl); SYM(vsh, g_vsh); SYM(vsl, g_vsl);
    SYM(oh, g_oh); SYM(ol, g_ol);
    SYM(knTh, g_knTh); SYM(knTl, g_knTl); SYM(qnTh, g_qnTh); SYM(qnTl, g_qnTl);
    SYM(abh, g_abh); SYM(abl, g_abl);
    SYM(w3h, g_w3h); SYM(w3l, g_w3l); SYM(w2h, g_w2h); SYM(w2l, g_w2l);
    SYM(wqh, g_wqh); SYM(wql, g_wql); SYM(wph, g_wph); SYM(wpl, g_wpl);

    dim3 tb(32, 8);
    dim3 tw(16, 16, 1);
    transpose_split<<<tw, tb>>>(Wq,     C_, 0, w3h,               w3l,               C_, 0);
    transpose_split<<<tw, tb>>>(Wk,     C_, 0, w3h + C_ * C_,     w3l + C_ * C_,     C_, 0);
    transpose_split<<<tw, tb>>>(Wv,     C_, 0, w3h + 2 * C_ * C_, w3l + 2 * C_ * C_, C_, 0);
    transpose_split<<<tw, tb>>>(Wk_sif, C_, 0, w2h,               w2l,               C_, 0);
    transpose_split<<<tw, tb>>>(Wv_sif, C_, 0, w2h + C_ * C_,     w2l + C_ * C_,     C_, 0);
    transpose_split<<<tw, tb>>>(Wq_sif, C_, 0, wqh,               wql,               C_, 0);
    transpose_split<<<tw, tb>>>(proj_w, C_, 0, wph,               wpl,               C_, 0);

    long n4 = (long)MTOT * C_ / 4;
    split_k<<<(unsigned)((n4 + 255) / 256), 256>>>(x,    xh, xl, n4);
    split_k<<<(unsigned)((n4 + 255) / 256), 256>>>(illu, ih, il, n4);
    split_k<<<(unsigned)((n4 + 255) / 256), 256>>>(sem,  sh, sl, n4);

    // GEMM1: qkv = x @ [Wq|Wk|Wv]
    gemm_h3<<<dim3(12, 256, 1), 256, GEMM_SMEM>>>(xh, xl, w3h, w3l, qkv,
        C_, C_, C_, 1536, 0, 0, 0, nullptr, nullptr, 0, 0, 1.f);
    // GEMM2: [kn|vs] = illu @ [Wk_sif|Wv_sif]
    gemm_h3<<<dim3(8, 256, 1), 256, GEMM_SMEM>>>(ih, il, w2h, w2l, knvs,
        C_, C_, C_, 1024, 0, 0, 0, nullptr, nullptr, 0, 0, 1.f);
    // GEMM3: qn = sem @ Wq_sif
    gemm_h3<<<dim3(4, 256, 1), 256, GEMM_SMEM>>>(sh, sl, wqh, wql, qn,
        C_, C_, C_, C_, 0, 0, 0, nullptr, nullptr, 0, 0, 1.f);

    ln_rows<<<MTOT, 128>>>(knvs, 1024, ln_g, ln_b);
    ln_rows<<<MTOT, 128>>>(qn, 512, ln_g, ln_b);

    split_str<<<MTOT * 128 / 256, 256>>>(knvs + 512, 1024, vsh, vsl);

    transpose_split<<<dim3(16, 128, 8), tb>>>(knvs, 1024, (long)N_ * 1024,
        knTh, knTl, N_, (long)C_ * N_);
    transpose_split<<<dim3(16, 128, 8), tb>>>(qn, 512, (long)N_ * 512,
        qnTh, qnTl, N_, (long)C_ * N_);

    // GEMM4: Ab[b] = (Qn^T Kn)/sqrt(C)   (M=N=512, K=4096)
    gemm_h3<<<dim3(4, 4, 8), 256, GEMM_SMEM>>>(qnTh, qnTl, knTh, knTl, ab,
        N_, N_, N_, C_, (long)C_ * N_, (long)C_ * N_, (long)C_ * C_,
        nullptr, nullptr, 0, 0, 0.044194173824159216f);

    softmax_ab<<<B_ * C_, 128>>>(ab, abh, abl);

    // GEMM5: prior = V @ Ab^T + V   (per batch M=4096, N=512, K=512)
    gemm_h3<<<dim3(4, 32, 8), 256, GEMM_SMEM>>>(vsh, vsl, abh, abl, prior,
        C_, C_, C_, C_, (long)N_ * C_, (long)C_ * C_, (long)N_ * C_,
        nullptr, knvs + 512, 1024, (long)N_ * 1024, 1.f);

    // FG-MSA
    msa_g<<<dim3(64, NSLICE), 256>>>();
    msa_soft<<<64 * 64, 64>>>(rescale);
    msa_o<<<dim3(64, NSLICE), 256>>>();

    // GEMM6: out = o @ proj_w + proj_b
    gemm_h3<<<dim3(4, 256, 1), 256, GEMM_SMEM>>>(oh, ol, wph, wpl, out,
        C_, C_, C_, C_, 0, 0, 0, proj_b, nullptr, 0, 0, 1.f);

    // positional branch
    dwconv3x3<true,  false><<<MTOT / 8, 128>>>(qkv + 1024, 1536, dw1, p1);
    dwconv3x3<false, true ><<<MTOT / 8, 128>>>(p1, 512, dw2, out);
}

// round 6
// speedup vs baseline: 2.3186x; 1.1821x over previous
#include <cuda_runtime.h>
#include <cuda_fp16.h>
#include <math.h>
#include <stdint.h>

#define B_    8
#define C_    512
#define N_    4096
#define MTOT  32768
#define DH    64
#define NSLICE 16

// ---------------------------------------------------------------------------
// helpers (portable PTX only: cp.async, ldmatrix, mma.sync)
// ---------------------------------------------------------------------------
__device__ __forceinline__ uint32_t smem_u32(const void* p) {
    uint32_t a;
    asm("{ .reg .u64 t; cvta.to.shared.u64 t, %1; cvt.u32.u64 %0, t; }" : "=r"(a) : "l"(p));
    return a;
}
__device__ __forceinline__ void cp_async16(uint32_t dst, const void* src) {
    asm volatile("cp.async.cg.shared.global [%0], [%1], 16;" :: "r"(dst), "l"(src));
}
#define CP_COMMIT() asm volatile("cp.async.commit_group;" ::: "memory")
#define CP_WAIT(n)  asm volatile("cp.async.wait_group %0;" :: "n"(n) : "memory")

#define LDSM_X4(r, a)                                                          \
    asm volatile("ldmatrix.sync.aligned.m8n8.x4.shared.b16 {%0,%1,%2,%3},[%4];"\
        : "=r"((r)[0]), "=r"((r)[1]), "=r"((r)[2]), "=r"((r)[3]) : "r"(a))

__device__ __forceinline__ void mma16816(float* d, const uint32_t* a, const uint32_t* b) {
    asm volatile("mma.sync.aligned.m16n8k16.row.col.f32.f16.f16.f32 "
        "{%0,%1,%2,%3},{%4,%5,%6,%7},{%8,%9},{%0,%1,%2,%3};"
        : "+f"(d[0]), "+f"(d[1]), "+f"(d[2]), "+f"(d[3])
        : "r"(a[0]), "r"(a[1]), "r"(a[2]), "r"(a[3]), "r"(b[0]), "r"(b[1]));
}

// ---------------------------------------------------------------------------
// scratch
// ---------------------------------------------------------------------------
__device__ float g_qkv  [MTOT * 1536];
__device__ float g_knvs [MTOT * 1024];
__device__ float g_qn   [MTOT * C_];
__device__ float g_prior[MTOT * C_];
__device__ float g_p1   [MTOT * C_];
__device__ float g_ab   [B_ * C_ * C_];
__device__ __half g_xh [MTOT * C_];
__device__ __half g_ih [MTOT * C_];
__device__ __half g_sh [MTOT * C_];
__device__ __half g_vsh[MTOT * C_];
__device__ __half g_oh [MTOT * C_];
__device__ __half g_knTh[B_ * C_ * N_], g_knTl[B_ * C_ * N_];
__device__ __half g_qnTh[B_ * C_ * N_], g_qnTl[B_ * C_ * N_];
__device__ __half g_abh[B_ * C_ * C_],  g_abl[B_ * C_ * C_];
__device__ __half g_w3h[1536 * C_], g_w3l[1536 * C_];
__device__ __half g_w2h[1024 * C_], g_w2l[1024 * C_];
__device__ __half g_wqh[C_ * C_],   g_wql[C_ * C_];
__device__ __half g_wph[C_ * C_],   g_wpl[C_ * C_];
__device__ float g_Gp [NSLICE * 64 * 64 * 64];
__device__ float g_nkp[NSLICE * 64 * 64];
__device__ float g_nqp[NSLICE * 64 * 64];
__device__ float g_attn[64 * 64 * 64];

// ---------------------------------------------------------------------------
// HMMA GEMM: C[m,n] = alpha*(sum_k A*(Bh+Bl)) (+AlBh when PASSES=3)
// CTA tile 128x128, BK=32, 8 warps (2Mx4N), double-buffered cp.async.
// smem tiles per stage: [Ah][Bh][Bl]([Al]); rows padded to 80B.
// Optional fp16-hi secondary output for cols >= colOff.
// ---------------------------------------------------------------------------
#define TILE_B   10240            // 128 rows * 80 B

template <int PASSES>
__global__ __launch_bounds__(256, 1) void gemm_h(
    const __half* __restrict__ Ah, const __half* __restrict__ Al,
    const __half* __restrict__ Bh, const __half* __restrict__ Bl,
    float* __restrict__ C, int K, int ldA, int ldB, int ldC,
    long sA, long sB, long sC,
    const float* __restrict__ bias,
    const float* __restrict__ res, int ldRes, long sRes, float alpha,
    __half* __restrict__ outH, int ldH, int colOff)
{
    constexpr int NT = (PASSES == 3) ? 4 : 3;
    constexpr int STAGE_B = NT * TILE_B;
    extern __shared__ char smem[];
    const int m0 = blockIdx.y * 128, n0 = blockIdx.x * 128;
    Ah += blockIdx.z * sA;
    if (PASSES == 3) Al += blockIdx.z * sA;
    Bh += blockIdx.z * sB; Bl += blockIdx.z * sB;
    C  += blockIdx.z * sC;
    if (res) res += blockIdx.z * sRes;

    const int tid = threadIdx.x;
    const int wid = tid >> 5, lane = tid & 31;
    const int wm = (wid & 1) * 64;
    const int wn = (wid >> 1) * 32;
    const uint32_t sbase = smem_u32(smem);

    float acc[4][4][4];
#pragma unroll
    for (int i = 0; i < 4; i++)
#pragma unroll
        for (int j = 0; j < 4; j++)
#pragma unroll
            for (int p = 0; p < 4; p++) acc[i][j][p] = 0.f;

    const int KB = K >> 5;

#define STAGE_LOAD(kb, buf) do {                                               \
    int k0 = (kb) << 5;                                                        \
    uint32_t st = sbase + (buf) * STAGE_B;                                     \
    _Pragma("unroll")                                                          \
    for (int pos = 0; pos < 2; pos++) {                                        \
        int idx = tid + pos * 256;                                             \
        int r = idx >> 2, cc = idx & 3;                                        \
        uint32_t so = (uint32_t)(r * 80 + cc * 16);                            \
        long ga = (long)(m0 + r) * ldA + k0 + cc * 8;                          \
        long gb = (long)(n0 + r) * ldB + k0 + cc * 8;                          \
        cp_async16(st + so,              Ah + ga);                             \
        cp_async16(st + TILE_B + so,     Bh + gb);                             \
        cp_async16(st + 2 * TILE_B + so, Bl + gb);                             \
        if (PASSES == 3) cp_async16(st + 3 * TILE_B + so, Al + ga);            \
    }                                                                          \
    CP_COMMIT();                                                               \
} while (0)

    STAGE_LOAD(0, 0);

    const int lg = lane >> 3, lr = lane & 7;

    for (int kb = 0; kb < KB; kb++) {
        if (kb + 1 < KB) {
            STAGE_LOAD(kb + 1, (kb + 1) & 1);
            CP_WAIT(1);
        } else {
            CP_WAIT(0);
        }
        __syncthreads();
        uint32_t st = sbase + (kb & 1) * STAGE_B;

#pragma unroll
        for (int ks = 0; ks < 2; ks++) {
            const int cb = ks * 2;
            uint32_t ah[4][4], al[4][4], bh[4][2], bl[4][2];
#pragma unroll
            for (int mi = 0; mi < 4; mi++) {
                int row = wm + mi * 16 + lr + (lg & 1) * 8;
                int ch  = cb + (lg >> 1);
                uint32_t a = st + (uint32_t)(row * 80 + ch * 16);
                LDSM_X4(ah[mi], a);
                if (PASSES == 3) LDSM_X4(al[mi], a + 3 * TILE_B);
            }
#pragma unroll
            for (int np = 0; np < 2; np++) {
                int row = wn + np * 16 + lr + (lg >> 1) * 8;
                int ch  = cb + (lg & 1);
                uint32_t a = st + TILE_B + (uint32_t)(row * 80 + ch * 16);
                uint32_t t4[4];
                LDSM_X4(t4, a);
                bh[np * 2][0] = t4[0]; bh[np * 2][1] = t4[1];
                bh[np * 2 + 1][0] = t4[2]; bh[np * 2 + 1][1] = t4[3];
                LDSM_X4(t4, a + TILE_B);
                bl[np * 2][0] = t4[0]; bl[np * 2][1] = t4[1];
                bl[np * 2 + 1][0] = t4[2]; bl[np * 2 + 1][1] = t4[3];
            }
#pragma unroll
            for (int mi = 0; mi < 4; mi++)
#pragma unroll
                for (int nj = 0; nj < 4; nj++) {
                    mma16816(acc[mi][nj], ah[mi], bh[nj]);
                    mma16816(acc[mi][nj], ah[mi], bl[nj]);
                    if (PASSES == 3) mma16816(acc[mi][nj], al[mi], bh[nj]);
                }
        }
        __syncthreads();
    }

    const int er = lane >> 2, ec = (lane & 3) * 2;
#pragma unroll
    for (int mi = 0; mi < 4; mi++)
#pragma unroll
        for (int nj = 0; nj < 4; nj++) {
            int col = n0 + wn + nj * 8 + ec;
#pragma unroll
            for (int p = 0; p < 2; p++) {
                int row = m0 + wm + mi * 16 + er + p * 8;
                float2 v;
                v.x = acc[mi][nj][p * 2 + 0] * alpha;
                v.y = acc[mi][nj][p * 2 + 1] * alpha;
                if (bias) { v.x += bias[col]; v.y += bias[col + 1]; }
                if (res) {
                    float2 rv = *(const float2*)(res + (long)row * ldRes + col);
                    v.x += rv.x; v.y += rv.y;
                }
                *(float2*)(C + (long)row * ldC + col) = v;
                if (outH && col >= colOff) {
                    *(__half2*)(outH + (long)row * ldH + (col - colOff)) =
                        __halves2half2(__float2half_rn(v.x), __float2half_rn(v.y));
                }
            }
        }
}

// ---------------------------------------------------------------------------
// fp32 -> fp16 hi (contiguous)
// ---------------------------------------------------------------------------
__global__ void split_hi(const float* __restrict__ in, __half* __restrict__ h, long n4)
{
    long i = ((long)blockIdx.x * blockDim.x + threadIdx.x);
    if (i >= n4) return;
    i *= 4;
    float4 v = *(const float4*)(in + i);
    *(__half2*)(h + i)     = __halves2half2(__float2half_rn(v.x), __float2half_rn(v.y));
    *(__half2*)(h + i + 2) = __halves2half2(__float2half_rn(v.z), __float2half_rn(v.w));
}

// ---------------------------------------------------------------------------
// transpose + split: fp32 [R,C](ldIn) -> fp16 hi/lo [C,R](ldOut), batched z
// ---------------------------------------------------------------------------
__global__ void transpose_split(const float* __restrict__ in, int ldIn, long sIn,
                                __half* __restrict__ oh, __half* __restrict__ ol,
                                int ldOut, long sOut)
{
    in += blockIdx.z * sIn; oh += blockIdx.z * sOut; ol += blockIdx.z * sOut;
    __shared__ float tile[32][33];
    int c0 = blockIdx.x * 32, r0 = blockIdx.y * 32;
    int tx = threadIdx.x, ty = threadIdx.y;
#pragma unroll
    for (int i = 0; i < 4; i++)
        tile[ty + 8 * i][tx] = in[(long)(r0 + ty + 8 * i) * ldIn + c0 + tx];
    __syncthreads();
#pragma unroll
    for (int i = 0; i < 4; i++) {
        float v = tile[tx][ty + 8 * i];
        __half hh = __float2half_rn(v);
        long o = (long)(c0 + ty + 8 * i) * ldOut + r0 + tx;
        oh[o] = hh;
        ol[o] = __float2half_rn(v - __half2float(hh));
    }
}

// ---------------------------------------------------------------------------
// LayerNorm rows (512), strided, in place
// ---------------------------------------------------------------------------
__global__ void ln_rows(float* __restrict__ X, int ld,
                        const float* __restrict__ gg, const float* __restrict__ bb)
{
    long row = blockIdx.x;
    float* x = X + row * (long)ld;
    int t = threadIdx.x;
    float4 v = *(float4*)(x + t * 4);
    float s = v.x + v.y + v.z + v.w;
    float q = v.x * v.x + v.y * v.y + v.z * v.z + v.w * v.w;
#pragma unroll
    for (int o = 16; o; o >>= 1) {
        s += __shfl_xor_sync(0xffffffffu, s, o);
        q += __shfl_xor_sync(0xffffffffu, q, o);
    }
    __shared__ float ss[4], sq[4];
    if ((t & 31) == 0) { ss[t >> 5] = s; sq[t >> 5] = q; }
    __syncthreads();
    s = ss[0] + ss[1] + ss[2] + ss[3];
    q = sq[0] + sq[1] + sq[2] + sq[3];
    float mu = s * (1.f / C_);
    float var = q * (1.f / C_) - mu * mu;
    float inv = rsqrtf(var + 1e-5f);
    float4 g4 = *(const float4*)(gg + t * 4);
    float4 b4 = *(const float4*)(bb + t * 4);
    v.x = (v.x - mu) * inv * g4.x + b4.x;
    v.y = (v.y - mu) * inv * g4.y + b4.y;
    v.z = (v.z - mu) * inv * g4.z + b4.z;
    v.w = (v.w - mu) * inv * g4.w + b4.w;
    *(float4*)(x + t * 4) = v;
}

// ---------------------------------------------------------------------------
// SIF softmax rows -> fp16 hi/lo (row-major)
// ---------------------------------------------------------------------------
__global__ void softmax_ab(const float* __restrict__ Ab,
                           __half* __restrict__ oh, __half* __restrict__ ol)
{
    long bi = blockIdx.x;
    const float* row = Ab + bi * 512;
    int t = threadIdx.x;
    float4 v = *(const float4*)(row + t * 4);
    float m = fmaxf(fmaxf(v.x, v.y), fmaxf(v.z, v.w));
#pragma unroll
    for (int o = 16; o; o >>= 1) m = fmaxf(m, __shfl_xor_sync(0xffffffffu, m, o));
    __shared__ float rm[4], rs[4];
    if ((t & 31) == 0) rm[t >> 5] = m;
    __syncthreads();
    m = fmaxf(fmaxf(rm[0], rm[1]), fmaxf(rm[2], rm[3]));
    float4 e;
    e.x = expf(v.x - m); e.y = expf(v.y - m);
    e.z = expf(v.z - m); e.w = expf(v.w - m);
    float s = e.x + e.y + e.z + e.w;
#pragma unroll
    for (int o = 16; o; o >>= 1) s += __shfl_xor_sync(0xffffffffu, s, o);
    if ((t & 31) == 0) rs[t >> 5] = s;
    __syncthreads();
    s = rs[0] + rs[1] + rs[2] + rs[3];
    float inv = 1.f / s;
    e.x *= inv; e.y *= inv; e.z *= inv; e.w *= inv;
    long o = bi * 512 + t * 4;
    __half hx = __float2half_rn(e.x), hy = __float2half_rn(e.y);
    __half hz = __float2half_rn(e.z), hw = __float2half_rn(e.w);
    *(__half2*)(oh + o)     = __halves2half2(hx, hy);
    *(__half2*)(oh + o + 2) = __halves2half2(hz, hw);
    *(__half2*)(ol + o) = __halves2half2(
        __float2half_rn(e.x - __half2float(hx)),
        __float2half_rn(e.y - __half2float(hy)));
    *(__half2*)(ol + o + 2) = __halves2half2(
        __float2half_rn(e.z - __half2float(hz)),
        __float2half_rn(e.w - __half2float(hw)));
}

// ---------------------------------------------------------------------------
// FG-MSA (fp32 SIMT)
// ---------------------------------------------------------------------------
__global__ void msa_g()
{
    int bh = blockIdx.x, sl = blockIdx.y;
    int b = bh >> 3, h = bh & 7;
    const int NS = N_ / NSLICE;
    int n0 = sl * NS;
    __shared__ float ks[16][64];
    __shared__ float qs[16][64];
    int t = threadIdx.x;
    int ty = t >> 4, tx = t & 15;
    const float* qb = g_qkv + (long)b * N_ * 1536 + h * DH;
    const float* kb = qb + 512;
    float acc[4][4];
#pragma unroll
    for (int i = 0; i < 4; i++)
#pragma unroll
        for (int j = 0; j < 4; j++) acc[i][j] = 0.f;
    float ssk = 0.f, ssq = 0.f;
    int lkk = t >> 4, lc4 = (t & 15) << 2;
    for (int nb = 0; nb < NS; nb += 16) {
        long roff = (long)(n0 + nb + lkk) * 1536 + lc4;
        *(float4*)&ks[lkk][lc4] = *(const float4*)(kb + roff);
        *(float4*)&qs[lkk][lc4] = *(const float4*)(qb + roff);
        __syncthreads();
#pragma unroll
        for (int kk = 0; kk < 16; kk++) {
            float a[4], bv[4];
#pragma unroll
            for (int i = 0; i < 4; i++) a[i] = ks[kk][ty * 4 + i];
#pragma unroll
            for (int j = 0; j < 4; j++) bv[j] = qs[kk][tx * 4 + j];
#pragma unroll
            for (int i = 0; i < 4; i++)
#pragma unroll
                for (int j = 0; j < 4; j++) acc[i][j] += a[i] * bv[j];
        }
        if (t < 64) {
#pragma unroll
            for (int kk = 0; kk < 16; kk++) {
                float kv = ks[kk][t], qv = qs[kk][t];
                ssk += kv * kv; ssq += qv * qv;
            }
        }
        __syncthreads();
    }
    float* Gb = g_Gp + ((long)sl * 64 + bh) * 4096;
#pragma unroll
    for (int i = 0; i < 4; i++)
#pragma unroll
        for (int j = 0; j < 4; j++)
            Gb[(ty * 4 + i) * 64 + tx * 4 + j] = acc[i][j];
    if (t < 64) {
        g_nkp[((long)sl * 64 + bh) * 64 + t] = ssk;
        g_nqp[((long)sl * 64 + bh) * 64 + t] = ssq;
    }
}

__global__ void msa_soft(const float* __restrict__ rescale)
{
    int r = blockIdx.x;
    int bh = r >> 6, d = r & 63, h = bh & 7;
    int t = threadIdx.x;
    float gsum = 0.f, nks = 0.f, nqs = 0.f;
#pragma unroll
    for (int sl = 0; sl < NSLICE; sl++) {
        gsum += g_Gp[((long)sl * 64 + bh) * 4096 + d * 64 + t];
        nks  += g_nkp[((long)sl * 64 + bh) * 64 + d];
        nqs  += g_nqp[((long)sl * 64 + bh) * 64 + t];
    }
    float nk = fmaxf(sqrtf(nks), 1e-12f);
    float nq = fmaxf(sqrtf(nqs), 1e-12f);
    float val = gsum * (rescale[h] / (nk * nq));
    float m = val;
#pragma unroll
    for (int o = 16; o; o >>= 1) m = fmaxf(m, __shfl_xor_sync(0xffffffffu, m, o));
    __shared__ float rm[2], rs[2];
    if ((t & 31) == 0) rm[t >> 5] = m;
    __syncthreads();
    m = fmaxf(rm[0], rm[1]);
    float e = expf(val - m);
    float s = e;
#pragma unroll
    for (int o = 16; o; o >>= 1) s += __shfl_xor_sync(0xffffffffu, s, o);
    if ((t & 31) == 0) rs[t >> 5] = s;
    __syncthreads();
    s = rs[0] + rs[1];
    g_attn[(long)bh * 4096 + d * 64 + t] = e / s;
}

__global__ void msa_o()
{
    int bh = blockIdx.x;
    int b = bh >> 3, h = bh & 7;
    int n0 = blockIdx.y * (N_ / NSLICE);
    __shared__ float at[64][65];
    __shared__ float vg[16][64];
    int t = threadIdx.x;
#pragma unroll
    for (int l = 0; l < 16; l++) {
        int idx = l * 256 + t;
        at[idx >> 6][idx & 63] = g_attn[(long)bh * 4096 + idx];
    }
    __syncthreads();
    const float* vb = g_qkv + (long)b * N_ * 1536 + 1024 + h * DH;
    const float* pb = g_prior + (long)b * N_ * C_ + h * DH;
    long obase = (long)b * N_ * C_ + h * DH;
    int lkk = t >> 4, lc4 = (t & 15) << 2;
    int ty = t >> 4, tx = t & 15;
    for (int nb = 0; nb < 256; nb += 16) {
        {
            long rv = (long)(n0 + nb + lkk) * 1536 + lc4;
            long rp = (long)(n0 + nb + lkk) * C_ + lc4;
            float4 v4 = *(const float4*)(vb + rv);
            float4 p4 = *(const float4*)(pb + rp);
            float4 w4;
            w4.x = v4.x * p4.x; w4.y = v4.y * p4.y;
            w4.z = v4.z * p4.z; w4.w = v4.w * p4.w;
            *(float4*)&vg[lkk][lc4] = w4;
        }
        __syncthreads();
        float s0 = 0.f, s1 = 0.f, s2 = 0.f, s3 = 0.f;
#pragma unroll
        for (int e = 0; e < 64; e++) {
            float vv = vg[ty][e];
            s0 += at[tx * 4 + 0][e] * vv;
            s1 += at[tx * 4 + 1][e] * vv;
            s2 += at[tx * 4 + 2][e] * vv;
            s3 += at[tx * 4 + 3][e] * vv;
        }
        long off = obase + (long)(n0 + nb + ty) * C_ + tx * 4;
        *(__half2*)(g_oh + off)     = __halves2half2(__float2half_rn(s0), __float2half_rn(s1));
        *(__half2*)(g_oh + off + 2) = __halves2half2(__float2half_rn(s2), __float2half_rn(s3));
        __syncthreads();
    }
}

// ---------------------------------------------------------------------------
// depthwise conv
// ---------------------------------------------------------------------------
__device__ __forceinline__ float gelu_exact(float x)
{
    return 0.5f * x * (1.f + erff(x * 0.70710678118654752f));
}
template <bool GELU, bool ACCUM>
__global__ void dwconv3x3(const float* __restrict__ in, int ldIn,
                          const float* __restrict__ w, float* __restrict__ out)
{
    int t = threadIdx.x;
    int c = t * 4;
    float wr[3][3][4];
#pragma unroll
    for (int ky = 0; ky < 3; ky++)
#pragma unroll
        for (int kx = 0; kx < 3; kx++)
#pragma unroll
            for (int i = 0; i < 4; i++)
                wr[ky][kx][i] = w[(long)(c + i) * 9 + ky * 3 + kx];
    long p0 = (long)blockIdx.x * 8;
    int b = (int)(p0 >> 12);
    int yx0 = (int)(p0 & 4095);
#pragma unroll
    for (int px = 0; px < 8; px++) {
        int yx = yx0 + px;
        int y = yx >> 6, x = yx & 63;
        float ax = 0.f, ay = 0.f, az = 0.f, aw = 0.f;
#pragma unroll
        for (int ky = 0; ky < 3; ky++) {
            int yy = y + ky - 1;
            if (yy < 0 || yy > 63) continue;
#pragma unroll
            for (int kx = 0; kx < 3; kx++) {
                int xx = x + kx - 1;
                if (xx < 0 || xx > 63) continue;
                float4 v = *(const float4*)(in + ((long)(b << 12) + (yy << 6) + xx) * ldIn + c);
                ax += v.x * wr[ky][kx][0];
                ay += v.y * wr[ky][kx][1];
                az += v.z * wr[ky][kx][2];
                aw += v.w * wr[ky][kx][3];
            }
        }
        if (GELU) {
            ax = gelu_exact(ax); ay = gelu_exact(ay);
            az = gelu_exact(az); aw = gelu_exact(aw);
        }
        long off = ((long)(b << 12) + yx) * C_ + c;
        if (ACCUM) {
            float4 o = *(float4*)(out + off);
            o.x += ax; o.y += ay; o.z += az; o.w += aw;
            *(float4*)(out + off) = o;
        } else {
            float4 o; o.x = ax; o.y = ay; o.z = az; o.w = aw;
            *(float4*)(out + off) = o;
        }
    }
}

// ---------------------------------------------------------------------------
// host
// ---------------------------------------------------------------------------
extern "C" void kernel_launch(void* const* d_in, const int* in_sizes, int n_in,
                              void* d_out, int out_size)
{
    const float* x       = (const float*)d_in[0];
    const float* illu    = (const float*)d_in[1];
    const float* sem     = (const float*)d_in[2];
    const float* Wk_sif  = (const float*)d_in[3];
    const float* Wq_sif  = (const float*)d_in[4];
    const float* Wv_sif  = (const float*)d_in[5];
    const float* ln_g    = (const float*)d_in[6];
    const float* ln_b    = (const float*)d_in[7];
    const float* Wq      = (const float*)d_in[8];
    const float* Wk      = (const float*)d_in[9];
    const float* Wv      = (const float*)d_in[10];
    const float* rescale = (const float*)d_in[11];
    const float* proj_w  = (const float*)d_in[12];
    const float* proj_b  = (const float*)d_in[13];
    const float* dw1     = (const float*)d_in[14];
    const float* dw2     = (const float*)d_in[15];
    float* out = (float*)d_out;

    cudaFuncSetAttribute(gemm_h<2>, cudaFuncAttributeMaxDynamicSharedMemorySize, 2 * 3 * TILE_B);
    cudaFuncSetAttribute(gemm_h<3>, cudaFuncAttributeMaxDynamicSharedMemorySize, 2 * 4 * TILE_B);

#define SYM(p, s) do { void* _t; cudaGetSymbolAddress(&_t, s); p = (decltype(p))_t; } while (0)
    float *qkv, *knvs, *qn, *prior, *p1, *ab;
    __half *xh, *ih, *sh, *vsh, *oh;
    __half *knTh, *knTl, *qnTh, *qnTl, *abh, *abl;
    __half *w3h, *w3l, *w2h, *w2l, *wqh, *wql, *wph, *wpl;
    SYM(qkv, g_qkv);   SYM(knvs, g_knvs); SYM(qn, g_qn); SYM(prior, g_prior);
    SYM(p1, g_p1);     SYM(ab, g_ab);
    SYM(xh, g_xh); SYM(ih, g_ih); SYM(sh, g_sh); SYM(vsh, g_vsh); SYM(oh, g_oh);
    SYM(knTh, g_knTh); SYM(knTl, g_knTl); SYM(qnTh, g_qnTh); SYM(qnTl, g_qnTl);
    SYM(abh, g_abh); SYM(abl, g_abl);
    SYM(w3h, g_w3h); SYM(w3l, g_w3l); SYM(w2h, g_w2h); SYM(w2l, g_w2l);
    SYM(wqh, g_wqh); SYM(wql, g_wql); SYM(wph, g_wph); SYM(wpl, g_wpl);

    dim3 tb(32, 8);
    dim3 tw(16, 16, 1);
    transpose_split<<<tw, tb>>>(Wq,     C_, 0, w3h,               w3l,               C_, 0);
    transpose_split<<<tw, tb>>>(Wk,     C_, 0, w3h + C_ * C_,     w3l + C_ * C_,     C_, 0);
    transpose_split<<<tw, tb>>>(Wv,     C_, 0, w3h + 2 * C_ * C_, w3l + 2 * C_ * C_, C_, 0);
    transpose_split<<<tw, tb>>>(Wk_sif, C_, 0, w2h,               w2l,               C_, 0);
    transpose_split<<<tw, tb>>>(Wv_sif, C_, 0, w2h + C_ * C_,     w2l + C_ * C_,     C_, 0);
    transpose_split<<<tw, tb>>>(Wq_sif, C_, 0, wqh,               wql,               C_, 0);
    transpose_split<<<tw, tb>>>(proj_w, C_, 0, wph,               wpl,               C_, 0);

    long n4 = (long)MTOT * C_ / 4;
    split_hi<<<(unsigned)((n4 + 255) / 256), 256>>>(x,    xh, n4);
    split_hi<<<(unsigned)((n4 + 255) / 256), 256>>>(illu, ih, n4);
    split_hi<<<(unsigned)((n4 + 255) / 256), 256>>>(sem,  sh, n4);

    // GEMM1: qkv = x @ [Wq|Wk|Wv]
    gemm_h<2><<<dim3(12, 256, 1), 256, 2 * 3 * TILE_B>>>(xh, nullptr, w3h, w3l, qkv,
        C_, C_, C_, 1536, 0, 0, 0, nullptr, nullptr, 0, 0, 1.f, nullptr, 0, 0);
    // GEMM2: [kn|vs] = illu @ [Wk_sif|Wv_sif]; vs-hi written fused (cols>=512)
    gemm_h<2><<<dim3(8, 256, 1), 256, 2 * 3 * TILE_B>>>(ih, nullptr, w2h, w2l, knvs,
        C_, C_, C_, 1024, 0, 0, 0, nullptr, nullptr, 0, 0, 1.f, vsh, C_, 512);
    // GEMM3: qn = sem @ Wq_sif
    gemm_h<2><<<dim3(4, 256, 1), 256, 2 * 3 * TILE_B>>>(sh, nullptr, wqh, wql, qn,
        C_, C_, C_, C_, 0, 0, 0, nullptr, nullptr, 0, 0, 1.f, nullptr, 0, 0);

    ln_rows<<<MTOT, 128>>>(knvs, 1024, ln_g, ln_b);
    ln_rows<<<MTOT, 128>>>(qn, 512, ln_g, ln_b);

    transpose_split<<<dim3(16, 128, 8), tb>>>(knvs, 1024, (long)N_ * 1024,
        knTh, knTl, N_, (long)C_ * N_);
    transpose_split<<<dim3(16, 128, 8), tb>>>(qn, 512, (long)N_ * 512,
        qnTh, qnTl, N_, (long)C_ * N_);

    // GEMM4 (3-pass, precision-critical): Ab[b] = (Qn^T Kn)/sqrt(C)
    gemm_h<3><<<dim3(4, 4, 8), 256, 2 * 4 * TILE_B>>>(qnTh, qnTl, knTh, knTl, ab,
        N_, N_, N_, C_, (long)C_ * N_, (long)C_ * N_, (long)C_ * C_,
        nullptr, nullptr, 0, 0, 0.044194173824159216f, nullptr, 0, 0);

    softmax_ab<<<B_ * C_, 128>>>(ab, abh, abl);

    // GEMM5: prior = V @ Ab^T + V   (per batch M=4096, N=512, K=512)
    gemm_h<2><<<dim3(4, 32, 8), 256, 2 * 3 * TILE_B>>>(vsh, nullptr, abh, abl, prior,
        C_, C_, C_, C_, (long)N_ * C_, (long)C_ * C_, (long)N_ * C_,
        nullptr, knvs + 512, 1024, (long)N_ * 1024, 1.f, nullptr, 0, 0);

    // FG-MSA
    msa_g<<<dim3(64, NSLICE), 256>>>();
    msa_soft<<<64 * 64, 64>>>(rescale);
    msa_o<<<dim3(64, NSLICE), 256>>>();

    // GEMM6: out = o @ proj_w + proj_b
    gemm_h<2><<<dim3(4, 256, 1), 256, 2 * 3 * TILE_B>>>(oh, nullptr, wph, wpl, out,
        C_, C_, C_, C_, 0, 0, 0, proj_b, nullptr, 0, 0, 1.f, nullptr, 0, 0);

    // positional branch
    dwconv3x3<true,  false><<<MTOT / 8, 128>>>(qkv + 1024, 1536, dw1, p1);
    dwconv3x3<false, true ><<<MTOT / 8, 128>>>(p1, 512, dw2, out);
}

// round 7
// speedup vs baseline: 2.4259x; 1.0463x over previous
#include <cuda_runtime.h>
#include <cuda_fp16.h>
#include <math.h>
#include <stdint.h>

#define B_    8
#define C_    512
#define N_    4096
#define MTOT  32768
#define DH    64
#define NSLICE 16

// ---------------------------------------------------------------------------
// helpers (portable PTX only: cp.async, ldmatrix, mma.sync)
// ---------------------------------------------------------------------------
__device__ __forceinline__ uint32_t smem_u32(const void* p) {
    uint32_t a;
    asm("{ .reg .u64 t; cvta.to.shared.u64 t, %1; cvt.u32.u64 %0, t; }" : "=r"(a) : "l"(p));
    return a;
}
__device__ __forceinline__ void cp_async16(uint32_t dst, const void* src) {
    asm volatile("cp.async.cg.shared.global [%0], [%1], 16;" :: "r"(dst), "l"(src));
}
#define CP_COMMIT() asm volatile("cp.async.commit_group;" ::: "memory")
#define CP_WAIT(n)  asm volatile("cp.async.wait_group %0;" :: "n"(n) : "memory")

#define LDSM_X4(r, a)                                                          \
    asm volatile("ldmatrix.sync.aligned.m8n8.x4.shared.b16 {%0,%1,%2,%3},[%4];"\
        : "=r"((r)[0]), "=r"((r)[1]), "=r"((r)[2]), "=r"((r)[3]) : "r"(a))

__device__ __forceinline__ void mma16816(float* d, const uint32_t* a, const uint32_t* b) {
    asm volatile("mma.sync.aligned.m16n8k16.row.col.f32.f16.f16.f32 "
        "{%0,%1,%2,%3},{%4,%5,%6,%7},{%8,%9},{%0,%1,%2,%3};"
        : "+f"(d[0]), "+f"(d[1]), "+f"(d[2]), "+f"(d[3])
        : "r"(a[0]), "r"(a[1]), "r"(a[2]), "r"(a[3]), "r"(b[0]), "r"(b[1]));
}

// ---------------------------------------------------------------------------
// scratch
// ---------------------------------------------------------------------------
__device__ float g_qkv  [MTOT * 1536];
__device__ float g_knvs [MTOT * 1024];
__device__ float g_qn   [MTOT * C_];
__device__ float g_prior[MTOT * C_];
__device__ float g_p1   [MTOT * C_];
__device__ float g_ab   [B_ * C_ * C_];
__device__ __half g_xh [MTOT * C_];
__device__ __half g_ih [MTOT * C_];
__device__ __half g_sh [MTOT * C_];
__device__ __half g_vsh[MTOT * C_];
__device__ __half g_oh [MTOT * C_];
__device__ __half g_knTh[B_ * C_ * N_], g_knTl[B_ * C_ * N_];
__device__ __half g_qnTh[B_ * C_ * N_], g_qnTl[B_ * C_ * N_];
__device__ __half g_abh[B_ * C_ * C_],  g_abl[B_ * C_ * C_];
__device__ __half g_w3h[1536 * C_], g_w3l[1536 * C_];
__device__ __half g_w2h[1024 * C_], g_w2l[1024 * C_];
__device__ __half g_wqh[C_ * C_],   g_wql[C_ * C_];
__device__ __half g_wph[C_ * C_],   g_wpl[C_ * C_];
__device__ float g_Gp [NSLICE * 64 * 64 * 64];
__device__ float g_nkp[NSLICE * 64 * 64];
__device__ float g_nqp[NSLICE * 64 * 64];
__device__ float g_attn[64 * 64 * 64];

// ---------------------------------------------------------------------------
// HMMA GEMM: C[m,n] = alpha*(sum_k A*(Bh+Bl)) (+AlBh when PASSES=3)
// CTA tile 128x128, BK=32, 8 warps (2Mx4N), 3-stage cp.async pipeline,
// ONE __syncthreads per K-step. smem per stage: [Ah][Bh][Bl]([Al]); 80B rows.
// Optional fp16-hi secondary output for cols >= colOff.
// ---------------------------------------------------------------------------
#define TILE_B   10240            // 128 rows * 80 B

template <int PASSES>
__global__ __launch_bounds__(256, 1) void gemm_h(
    const __half* __restrict__ Ah, const __half* __restrict__ Al,
    const __half* __restrict__ Bh, const __half* __restrict__ Bl,
    float* __restrict__ C, int K, int ldA, int ldB, int ldC,
    long sA, long sB, long sC,
    const float* __restrict__ bias,
    const float* __restrict__ res, int ldRes, long sRes, float alpha,
    __half* __restrict__ outH, int ldH, int colOff)
{
    constexpr int NT = (PASSES == 3) ? 4 : 3;
    constexpr int STAGE_B = NT * TILE_B;
    extern __shared__ char smem[];
    const int m0 = blockIdx.y * 128, n0 = blockIdx.x * 128;
    Ah += blockIdx.z * sA;
    if (PASSES == 3) Al += blockIdx.z * sA;
    Bh += blockIdx.z * sB; Bl += blockIdx.z * sB;
    C  += blockIdx.z * sC;
    if (res) res += blockIdx.z * sRes;

    const int tid = threadIdx.x;
    const int wid = tid >> 5, lane = tid & 31;
    const int wm = (wid & 1) * 64;
    const int wn = (wid >> 1) * 32;
    const uint32_t sbase = smem_u32(smem);

    float acc[4][4][4];
#pragma unroll
    for (int i = 0; i < 4; i++)
#pragma unroll
        for (int j = 0; j < 4; j++)
#pragma unroll
            for (int p = 0; p < 4; p++) acc[i][j][p] = 0.f;

    const int KB = K >> 5;

#define STAGE_LOAD(kb, buf) do {                                               \
    int k0 = (kb) << 5;                                                        \
    uint32_t st = sbase + (buf) * STAGE_B;                                     \
    _Pragma("unroll")                                                          \
    for (int pos = 0; pos < 2; pos++) {                                        \
        int idx = tid + pos * 256;                                             \
        int r = idx >> 2, cc = idx & 3;                                        \
        uint32_t so = (uint32_t)(r * 80 + cc * 16);                            \
        long ga = (long)(m0 + r) * ldA + k0 + cc * 8;                          \
        long gb = (long)(n0 + r) * ldB + k0 + cc * 8;                          \
        cp_async16(st + so,              Ah + ga);                             \
        cp_async16(st + TILE_B + so,     Bh + gb);                             \
        cp_async16(st + 2 * TILE_B + so, Bl + gb);                             \
        if (PASSES == 3) cp_async16(st + 3 * TILE_B + so, Al + ga);            \
    }                                                                          \
    CP_COMMIT();                                                               \
} while (0)

    // 3-stage prologue
    STAGE_LOAD(0, 0);
    STAGE_LOAD(1, 1);

    const int lg = lane >> 3, lr = lane & 7;
    int cbuf = 0, lbuf = 2;

    for (int kb = 0; kb < KB; kb++) {
        if (kb + 1 < KB) CP_WAIT(1); else CP_WAIT(0);
        __syncthreads();               // warps done with buf (kb-1)%3 == lbuf
        if (kb + 2 < KB) STAGE_LOAD(kb + 2, lbuf);
        uint32_t st = sbase + cbuf * STAGE_B;

#pragma unroll
        for (int ks = 0; ks < 2; ks++) {
            const int cb = ks * 2;
            uint32_t ah[4][4], al[4][4], bh[4][2], bl[4][2];
#pragma unroll
            for (int mi = 0; mi < 4; mi++) {
                int row = wm + mi * 16 + lr + (lg & 1) * 8;
                int ch  = cb + (lg >> 1);
                uint32_t a = st + (uint32_t)(row * 80 + ch * 16);
                LDSM_X4(ah[mi], a);
                if (PASSES == 3) LDSM_X4(al[mi], a + 3 * TILE_B);
            }
#pragma unroll
            for (int np = 0; np < 2; np++) {
                int row = wn + np * 16 + lr + (lg >> 1) * 8;
                int ch  = cb + (lg & 1);
                uint32_t a = st + TILE_B + (uint32_t)(row * 80 + ch * 16);
                uint32_t t4[4];
                LDSM_X4(t4, a);
                bh[np * 2][0] = t4[0]; bh[np * 2][1] = t4[1];
                bh[np * 2 + 1][0] = t4[2]; bh[np * 2 + 1][1] = t4[3];
                LDSM_X4(t4, a + TILE_B);
                bl[np * 2][0] = t4[0]; bl[np * 2][1] = t4[1];
                bl[np * 2 + 1][0] = t4[2]; bl[np * 2 + 1][1] = t4[3];
            }
#pragma unroll
            for (int mi = 0; mi < 4; mi++)
#pragma unroll
                for (int nj = 0; nj < 4; nj++) {
                    mma16816(acc[mi][nj], ah[mi], bh[nj]);
                    mma16816(acc[mi][nj], ah[mi], bl[nj]);
                    if (PASSES == 3) mma16816(acc[mi][nj], al[mi], bh[nj]);
                }
        }
        cbuf = (cbuf == 2) ? 0 : cbuf + 1;
        lbuf = (lbuf == 2) ? 0 : lbuf + 1;
    }

    const int er = lane >> 2, ec = (lane & 3) * 2;
#pragma unroll
    for (int mi = 0; mi < 4; mi++)
#pragma unroll
        for (int nj = 0; nj < 4; nj++) {
            int col = n0 + wn + nj * 8 + ec;
#pragma unroll
            for (int p = 0; p < 2; p++) {
                int row = m0 + wm + mi * 16 + er + p * 8;
                float2 v;
                v.x = acc[mi][nj][p * 2 + 0] * alpha;
                v.y = acc[mi][nj][p * 2 + 1] * alpha;
                if (bias) { v.x += bias[col]; v.y += bias[col + 1]; }
                if (res) {
                    float2 rv = *(const float2*)(res + (long)row * ldRes + col);
                    v.x += rv.x; v.y += rv.y;
                }
                *(float2*)(C + (long)row * ldC + col) = v;
                if (outH && col >= colOff) {
                    *(__half2*)(outH + (long)row * ldH + (col - colOff)) =
                        __halves2half2(__float2half_rn(v.x), __float2half_rn(v.y));
                }
            }
        }
}

// ---------------------------------------------------------------------------
// fp32 -> fp16 hi (contiguous)
// ---------------------------------------------------------------------------
__global__ void split_hi(const float* __restrict__ in, __half* __restrict__ h, long n4)
{
    long i = ((long)blockIdx.x * blockDim.x + threadIdx.x);
    if (i >= n4) return;
    i *= 4;
    float4 v = *(const float4*)(in + i);
    *(__half2*)(h + i)     = __halves2half2(__float2half_rn(v.x), __float2half_rn(v.y));
    *(__half2*)(h + i + 2) = __halves2half2(__float2half_rn(v.z), __float2half_rn(v.w));
}

// ---------------------------------------------------------------------------
// transpose + split (weights): fp32 [R,C](ldIn) -> fp16 hi/lo [C,R](ldOut)
// ---------------------------------------------------------------------------
__global__ void transpose_split(const float* __restrict__ in, int ldIn, long sIn,
                                __half* __restrict__ oh, __half* __restrict__ ol,
                                int ldOut, long sOut)
{
    in += blockIdx.z * sIn; oh += blockIdx.z * sOut; ol += blockIdx.z * sOut;
    __shared__ float tile[32][33];
    int c0 = blockIdx.x * 32, r0 = blockIdx.y * 32;
    int tx = threadIdx.x, ty = threadIdx.y;
#pragma unroll
    for (int i = 0; i < 4; i++)
        tile[ty + 8 * i][tx] = in[(long)(r0 + ty + 8 * i) * ldIn + c0 + tx];
    __syncthreads();
#pragma unroll
    for (int i = 0; i < 4; i++) {
        float v = tile[tx][ty + 8 * i];
        __half hh = __float2half_rn(v);
        long o = (long)(c0 + ty + 8 * i) * ldOut + r0 + tx;
        oh[o] = hh;
        ol[o] = __float2half_rn(v - __half2float(hh));
    }
}

// ---------------------------------------------------------------------------
// FUSED: LayerNorm rows (512) + transpose + fp16 hi/lo split.
// in: fp32 [4096, ldIn] per batch; out: fp16 [512, 4096] hi/lo per batch.
// block 256 thr handles 32 rows; grid (128, B_).
// ---------------------------------------------------------------------------
#define LDT 516
#define LNT_SMEM (32 * LDT * 4)   // 66048 B

__global__ __launch_bounds__(256) void ln_t_split(
    const float* __restrict__ in, int ldIn, long sIn,
    const float* __restrict__ gg, const float* __restrict__ bb,
    __half* __restrict__ oh, __half* __restrict__ ol, long sOut)
{
    extern __shared__ float tile[];
    in += blockIdx.y * sIn; oh += blockIdx.y * sOut; ol += blockIdx.y * sOut;
    const int r0 = blockIdx.x * 32;
    const int t = threadIdx.x;

    // load 32x512 fp32
#pragma unroll
    for (int i = 0; i < 16; i++) {
        int lin = t + i * 256;
        int r = lin >> 7, c4 = lin & 127;
        float4 v = *(const float4*)(in + (long)(r0 + r) * ldIn + c4 * 4);
        *(float4*)&tile[r * LDT + c4 * 4] = v;
    }
    __syncthreads();

    // per-row mean/var: warp w handles rows 4w..4w+3
    __shared__ float mu_s[32], inv_s[32];
    const int w = t >> 5, lane = t & 31;
#pragma unroll
    for (int rr = 0; rr < 4; rr++) {
        int r = w * 4 + rr;
        float s = 0.f, q = 0.f;
#pragma unroll
        for (int i = 0; i < 16; i++) {
            float v = tile[r * LDT + lane + i * 32];
            s += v; q += v * v;
        }
#pragma unroll
        for (int o = 16; o; o >>= 1) {
            s += __shfl_xor_sync(0xffffffffu, s, o);
            q += __shfl_xor_sync(0xffffffffu, q, o);
        }
        if (lane == 0) {
            float mu = s * (1.f / C_);
            mu_s[r]  = mu;
            inv_s[r] = rsqrtf(q * (1.f / C_) - mu * mu + 1e-5f);
        }
    }
    __syncthreads();

    // write transposed: thread t -> row r = t&31, col group cg = t>>5
    const int r = t & 31, cg = t >> 5;
    const float mu = mu_s[r], inv = inv_s[r];
#pragma unroll 8
    for (int cc = 0; cc < 64; cc++) {
        int c = cc * 8 + cg;
        float v = (tile[r * LDT + c] - mu) * inv * gg[c] + bb[c];
        __half hh = __float2half_rn(v);
        long o = (long)c * N_ + r0 + r;
        oh[o] = hh;
        ol[o] = __float2half_rn(v - __half2float(hh));
    }
}

// ---------------------------------------------------------------------------
// SIF softmax rows -> fp16 hi/lo (row-major)
// ---------------------------------------------------------------------------
__global__ void softmax_ab(const float* __restrict__ Ab,
                           __half* __restrict__ oh, __half* __restrict__ ol)
{
    long bi = blockIdx.x;
    const float* row = Ab + bi * 512;
    int t = threadIdx.x;
    float4 v = *(const float4*)(row + t * 4);
    float m = fmaxf(fmaxf(v.x, v.y), fmaxf(v.z, v.w));
#pragma unroll
    for (int o = 16; o; o >>= 1) m = fmaxf(m, __shfl_xor_sync(0xffffffffu, m, o));
    __shared__ float rm[4], rs[4];
    if ((t & 31) == 0) rm[t >> 5] = m;
    __syncthreads();
    m = fmaxf(fmaxf(rm[0], rm[1]), fmaxf(rm[2], rm[3]));
    float4 e;
    e.x = expf(v.x - m); e.y = expf(v.y - m);
    e.z = expf(v.z - m); e.w = expf(v.w - m);
    float s = e.x + e.y + e.z + e.w;
#pragma unroll
    for (int o = 16; o; o >>= 1) s += __shfl_xor_sync(0xffffffffu, s, o);
    if ((t & 31) == 0) rs[t >> 5] = s;
    __syncthreads();
    s = rs[0] + rs[1] + rs[2] + rs[3];
    float inv = 1.f / s;
    e.x *= inv; e.y *= inv; e.z *= inv; e.w *= inv;
    long o = bi * 512 + t * 4;
    __half hx = __float2half_rn(e.x), hy = __float2half_rn(e.y);
    __half hz = __float2half_rn(e.z), hw = __float2half_rn(e.w);
    *(__half2*)(oh + o)     = __halves2half2(hx, hy);
    *(__half2*)(oh + o + 2) = __halves2half2(hz, hw);
    *(__half2*)(ol + o) = __halves2half2(
        __float2half_rn(e.x - __half2float(hx)),
        __float2half_rn(e.y - __half2float(hy)));
    *(__half2*)(ol + o + 2) = __halves2half2(
        __float2half_rn(e.z - __half2float(hz)),
        __float2half_rn(e.w - __half2float(hw)));
}

// ---------------------------------------------------------------------------
// FG-MSA (fp32 SIMT)
// ---------------------------------------------------------------------------
__global__ void msa_g()
{
    int bh = blockIdx.x, sl = blockIdx.y;
    int b = bh >> 3, h = bh & 7;
    const int NS = N_ / NSLICE;
    int n0 = sl * NS;
    __shared__ float ks[16][64];
    __shared__ float qs[16][64];
    int t = threadIdx.x;
    int ty = t >> 4, tx = t & 15;
    const float* qb = g_qkv + (long)b * N_ * 1536 + h * DH;
    const float* kb = qb + 512;
    float acc[4][4];
#pragma unroll
    for (int i = 0; i < 4; i++)
#pragma unroll
        for (int j = 0; j < 4; j++) acc[i][j] = 0.f;
    float ssk = 0.f, ssq = 0.f;
    int lkk = t >> 4, lc4 = (t & 15) << 2;
    for (int nb = 0; nb < NS; nb += 16) {
        long roff = (long)(n0 + nb + lkk) * 1536 + lc4;
        *(float4*)&ks[lkk][lc4] = *(const float4*)(kb + roff);
        *(float4*)&qs[lkk][lc4] = *(const float4*)(qb + roff);
        __syncthreads();
#pragma unroll
        for (int kk = 0; kk < 16; kk++) {
            float a[4], bv[4];
#pragma unroll
            for (int i = 0; i < 4; i++) a[i] = ks[kk][ty * 4 + i];
#pragma unroll
            for (int j = 0; j < 4; j++) bv[j] = qs[kk][tx * 4 + j];
#pragma unroll
            for (int i = 0; i < 4; i++)
#pragma unroll
                for (int j = 0; j < 4; j++) acc[i][j] += a[i] * bv[j];
        }
        if (t < 64) {
#pragma unroll
            for (int kk = 0; kk < 16; kk++) {
                float kv = ks[kk][t], qv = qs[kk][t];
                ssk += kv * kv; ssq += qv * qv;
            }
        }
        __syncthreads();
    }
    float* Gb = g_Gp + ((long)sl * 64 + bh) * 4096;
#pragma unroll
    for (int i = 0; i < 4; i++)
#pragma unroll
        for (int j = 0; j < 4; j++)
            Gb[(ty * 4 + i) * 64 + tx * 4 + j] = acc[i][j];
    if (t < 64) {
        g_nkp[((long)sl * 64 + bh) * 64 + t] = ssk;
        g_nqp[((long)sl * 64 + bh) * 64 + t] = ssq;
    }
}

__global__ void msa_soft(const float* __restrict__ rescale)
{
    int r = blockIdx.x;
    int bh = r >> 6, d = r & 63, h = bh & 7;
    int t = threadIdx.x;
    float gsum = 0.f, nks = 0.f, nqs = 0.f;
#pragma unroll
    for (int sl = 0; sl < NSLICE; sl++) {
        gsum += g_Gp[((long)sl * 64 + bh) * 4096 + d * 64 + t];
        nks  += g_nkp[((long)sl * 64 + bh) * 64 + d];
        nqs  += g_nqp[((long)sl * 64 + bh) * 64 + t];
    }
    float nk = fmaxf(sqrtf(nks), 1e-12f);
    float nq = fmaxf(sqrtf(nqs), 1e-12f);
    float val = gsum * (rescale[h] / (nk * nq));
    float m = val;
#pragma unroll
    for (int o = 16; o; o >>= 1) m = fmaxf(m, __shfl_xor_sync(0xffffffffu, m, o));
    __shared__ float rm[2], rs[2];
    if ((t & 31) == 0) rm[t >> 5] = m;
    __syncthreads();
    m = fmaxf(rm[0], rm[1]);
    float e = expf(val - m);
    float s = e;
#pragma unroll
    for (int o = 16; o; o >>= 1) s += __shfl_xor_sync(0xffffffffu, s, o);
    if ((t & 31) == 0) rs[t >> 5] = s;
    __syncthreads();
    s = rs[0] + rs[1];
    g_attn[(long)bh * 4096 + d * 64 + t] = e / s;
}

__global__ void msa_o()
{
    int bh = blockIdx.x;
    int b = bh >> 3, h = bh & 7;
    int n0 = blockIdx.y * (N_ / NSLICE);
    __shared__ float at[64][65];
    __shared__ float vg[16][64];
    int t = threadIdx.x;
#pragma unroll
    for (int l = 0; l < 16; l++) {
        int idx = l * 256 + t;
        at[idx >> 6][idx & 63] = g_attn[(long)bh * 4096 + idx];
    }
    __syncthreads();
    const float* vb = g_qkv + (long)b * N_ * 1536 + 1024 + h * DH;
    const float* pb = g_prior + (long)b * N_ * C_ + h * DH;
    long obase = (long)b * N_ * C_ + h * DH;
    int lkk = t >> 4, lc4 = (t & 15) << 2;
    int ty = t >> 4, tx = t & 15;
    for (int nb = 0; nb < 256; nb += 16) {
        {
            long rv = (long)(n0 + nb + lkk) * 1536 + lc4;
            long rp = (long)(n0 + nb + lkk) * C_ + lc4;
            float4 v4 = *(const float4*)(vb + rv);
            float4 p4 = *(const float4*)(pb + rp);
            float4 w4;
            w4.x = v4.x * p4.x; w4.y = v4.y * p4.y;
            w4.z = v4.z * p4.z; w4.w = v4.w * p4.w;
            *(float4*)&vg[lkk][lc4] = w4;
        }
        __syncthreads();
        float s0 = 0.f, s1 = 0.f, s2 = 0.f, s3 = 0.f;
#pragma unroll
        for (int e = 0; e < 64; e++) {
            float vv = vg[ty][e];
            s0 += at[tx * 4 + 0][e] * vv;
            s1 += at[tx * 4 + 1][e] * vv;
            s2 += at[tx * 4 + 2][e] * vv;
            s3 += at[tx * 4 + 3][e] * vv;
        }
        long off = obase + (long)(n0 + nb + ty) * C_ + tx * 4;
        *(__half2*)(g_oh + off)     = __halves2half2(__float2half_rn(s0), __float2half_rn(s1));
        *(__half2*)(g_oh + off + 2) = __halves2half2(__float2half_rn(s2), __float2half_rn(s3));
        __syncthreads();
    }
}

// ---------------------------------------------------------------------------
// depthwise conv
// ---------------------------------------------------------------------------
__device__ __forceinline__ float gelu_exact(float x)
{
    return 0.5f * x * (1.f + erff(x * 0.70710678118654752f));
}
template <bool GELU, bool ACCUM>
__global__ void dwconv3x3(const float* __restrict__ in, int ldIn,
                          const float* __restrict__ w, float* __restrict__ out)
{
    int t = threadIdx.x;
    int c = t * 4;
    float wr[3][3][4];
#pragma unroll
    for (int ky = 0; ky < 3; ky++)
#pragma unroll
        for (int kx = 0; kx < 3; kx++)
#pragma unroll
            for (int i = 0; i < 4; i++)
                wr[ky][kx][i] = w[(long)(c + i) * 9 + ky * 3 + kx];
    long p0 = (long)blockIdx.x * 8;
    int b = (int)(p0 >> 12);
    int yx0 = (int)(p0 & 4095);
#pragma unroll
    for (int px = 0; px < 8; px++) {
        int yx = yx0 + px;
        int y = yx >> 6, x = yx & 63;
        float ax = 0.f, ay = 0.f, az = 0.f, aw = 0.f;
#pragma unroll
        for (int ky = 0; ky < 3; ky++) {
            int yy = y + ky - 1;
            if (yy < 0 || yy > 63) continue;
#pragma unroll
            for (int kx = 0; kx < 3; kx++) {
                int xx = x + kx - 1;
                if (xx < 0 || xx > 63) continue;
                float4 v = *(const float4*)(in + ((long)(b << 12) + (yy << 6) + xx) * ldIn + c);
                ax += v.x * wr[ky][kx][0];
                ay += v.y * wr[ky][kx][1];
                az += v.z * wr[ky][kx][2];
                aw += v.w * wr[ky][kx][3];
            }
        }
        if (GELU) {
            ax = gelu_exact(ax); ay = gelu_exact(ay);
            az = gelu_exact(az); aw = gelu_exact(aw);
        }
        long off = ((long)(b << 12) + yx) * C_ + c;
        if (ACCUM) {
            float4 o = *(float4*)(out + off);
            o.x += ax; o.y += ay; o.z += az; o.w += aw;
            *(float4*)(out + off) = o;
        } else {
            float4 o; o.x = ax; o.y = ay; o.z = az; o.w = aw;
            *(float4*)(out + off) = o;
        }
    }
}

// ---------------------------------------------------------------------------
// host
// ---------------------------------------------------------------------------
extern "C" void kernel_launch(void* const* d_in, const int* in_sizes, int n_in,
                              void* d_out, int out_size)
{
    const float* x       = (const float*)d_in[0];
    const float* illu    = (const float*)d_in[1];
    const float* sem     = (const float*)d_in[2];
    const float* Wk_sif  = (const float*)d_in[3];
    const float* Wq_sif  = (const float*)d_in[4];
    const float* Wv_sif  = (const float*)d_in[5];
    const float* ln_g    = (const float*)d_in[6];
    const float* ln_b    = (const float*)d_in[7];
    const float* Wq      = (const float*)d_in[8];
    const float* Wk      = (const float*)d_in[9];
    const float* Wv      = (const float*)d_in[10];
    const float* rescale = (const float*)d_in[11];
    const float* proj_w  = (const float*)d_in[12];
    const float* proj_b  = (const float*)d_in[13];
    const float* dw1     = (const float*)d_in[14];
    const float* dw2     = (const float*)d_in[15];
    float* out = (float*)d_out;

    cudaFuncSetAttribute(gemm_h<2>, cudaFuncAttributeMaxDynamicSharedMemorySize, 3 * 3 * TILE_B);
    cudaFuncSetAttribute(gemm_h<3>, cudaFuncAttributeMaxDynamicSharedMemorySize, 3 * 4 * TILE_B);
    cudaFuncSetAttribute(ln_t_split, cudaFuncAttributeMaxDynamicSharedMemorySize, LNT_SMEM);

#define SYM(p, s) do { void* _t; cudaGetSymbolAddress(&_t, s); p = (decltype(p))_t; } while (0)
    float *qkv, *knvs, *qn, *prior, *p1, *ab;
    __half *xh, *ih, *sh, *vsh, *oh;
    __half *knTh, *knTl, *qnTh, *qnTl, *abh, *abl;
    __half *w3h, *w3l, *w2h, *w2l, *wqh, *wql, *wph, *wpl;
    SYM(qkv, g_qkv);   SYM(knvs, g_knvs); SYM(qn, g_qn); SYM(prior, g_prior);
    SYM(p1, g_p1);     SYM(ab, g_ab);
    SYM(xh, g_xh); SYM(ih, g_ih); SYM(sh, g_sh); SYM(vsh, g_vsh); SYM(oh, g_oh);
    SYM(knTh, g_knTh); SYM(knTl, g_knTl); SYM(qnTh, g_qnTh); SYM(qnTl, g_qnTl);
    SYM(abh, g_abh); SYM(abl, g_abl);
    SYM(w3h, g_w3h); SYM(w3l, g_w3l); SYM(w2h, g_w2h); SYM(w2l, g_w2l);
    SYM(wqh, g_wqh); SYM(wql, g_wql); SYM(wph, g_wph); SYM(wpl, g_wpl);

    dim3 tb(32, 8);
    dim3 tw(16, 16, 1);
    transpose_split<<<tw, tb>>>(Wq,     C_, 0, w3h,               w3l,               C_, 0);
    transpose_split<<<tw, tb>>>(Wk,     C_, 0, w3h + C_ * C_,     w3l + C_ * C_,     C_, 0);
    transpose_split<<<tw, tb>>>(Wv,     C_, 0, w3h + 2 * C_ * C_, w3l + 2 * C_ * C_, C_, 0);
    transpose_split<<<tw, tb>>>(Wk_sif, C_, 0, w2h,               w2l,               C_, 0);
    transpose_split<<<tw, tb>>>(Wv_sif, C_, 0, w2h + C_ * C_,     w2l + C_ * C_,     C_, 0);
    transpose_split<<<tw, tb>>>(Wq_sif, C_, 0, wqh,               wql,               C_, 0);
    transpose_split<<<tw, tb>>>(proj_w, C_, 0, wph,               wpl,               C_, 0);

    long n4 = (long)MTOT * C_ / 4;
    split_hi<<<(unsigned)((n4 + 255) / 256), 256>>>(x,    xh, n4);
    split_hi<<<(unsigned)((n4 + 255) / 256), 256>>>(illu, ih, n4);
    split_hi<<<(unsigned)((n4 + 255) / 256), 256>>>(sem,  sh, n4);

    // GEMM1: qkv = x @ [Wq|Wk|Wv]
    gemm_h<2><<<dim3(12, 256, 1), 256, 3 * 3 * TILE_B>>>(xh, nullptr, w3h, w3l, qkv,
        C_, C_, C_, 1536, 0, 0, 0, nullptr, nullptr, 0, 0, 1.f, nullptr, 0, 0);
    // GEMM2: [kn|vs] = illu @ [Wk_sif|Wv_sif]; vs-hi written fused (cols>=512)
    gemm_h<2><<<dim3(8, 256, 1), 256, 3 * 3 * TILE_B>>>(ih, nullptr, w2h, w2l, knvs,
        C_, C_, C_, 1024, 0, 0, 0, nullptr, nullptr, 0, 0, 1.f, vsh, C_, 512);
    // GEMM3: qn = sem @ Wq_sif
    gemm_h<2><<<dim3(4, 256, 1), 256, 3 * 3 * TILE_B>>>(sh, nullptr, wqh, wql, qn,
        C_, C_, C_, C_, 0, 0, 0, nullptr, nullptr, 0, 0, 1.f, nullptr, 0, 0);

    // fused LN + transpose + split (kn from knvs cols 0..511; qn)
    ln_t_split<<<dim3(128, 8), 256, LNT_SMEM>>>(knvs, 1024, (long)N_ * 1024,
        ln_g, ln_b, knTh, knTl, (long)C_ * N_);
    ln_t_split<<<dim3(128, 8), 256, LNT_SMEM>>>(qn, 512, (long)N_ * 512,
        ln_g, ln_b, qnTh, qnTl, (long)C_ * N_);

    // GEMM4 (3-pass, precision-critical): Ab[b] = (Qn^T Kn)/sqrt(C)
    gemm_h<3><<<dim3(4, 4, 8), 256, 3 * 4 * TILE_B>>>(qnTh, qnTl, knTh, knTl, ab,
        N_, N_, N_, C_, (long)C_ * N_, (long)C_ * N_, (long)C_ * C_,
        nullptr, nullptr, 0, 0, 0.044194173824159216f, nullptr, 0, 0);

    softmax_ab<<<B_ * C_, 128>>>(ab, abh, abl);

    // GEMM5: prior = V @ Ab^T + V   (per batch M=4096, N=512, K=512)
    gemm_h<2><<<dim3(4, 32, 8), 256, 3 * 3 * TILE_B>>>(vsh, nullptr, abh, abl, prior,
        C_, C_, C_, C_, (long)N_ * C_, (long)C_ * C_, (long)N_ * C_,
        nullptr, knvs + 512, 1024, (long)N_ * 1024, 1.f, nullptr, 0, 0);

    // FG-MSA
    msa_g<<<dim3(64, NSLICE), 256>>>();
    msa_soft<<<64 * 64, 64>>>(rescale);
    msa_o<<<dim3(64, NSLICE), 256>>>();

    // GEMM6: out = o @ proj_w + proj_b
    gemm_h<2><<<dim3(4, 256, 1), 256, 3 * 3 * TILE_B>>>(oh, nullptr, wph, wpl, out,
        C_, C_, C_, C_, 0, 0, 0, proj_b, nullptr, 0, 0, 1.f, nullptr, 0, 0);

    // positional branch
    dwconv3x3<true,  false><<<MTOT / 8, 128>>>(qkv + 1024, 1536, dw1, p1);
    dwconv3x3<false, true ><<<MTOT / 8, 128>>>(p1, 512, dw2, out);
}

// round 8
// speedup vs baseline: 2.4627x; 1.0152x over previous
#include <cuda_runtime.h>
#include <cuda_fp16.h>
#include <math.h>
#include <stdint.h>

#define B_    8
#define C_    512
#define N_    4096
#define MTOT  32768
#define DH    64
#define NSLICE 16

// ---------------------------------------------------------------------------
// helpers (portable PTX only: cp.async, ldmatrix, mma.sync)
// ---------------------------------------------------------------------------
__device__ __forceinline__ uint32_t smem_u32(const void* p) {
    uint32_t a;
    asm("{ .reg .u64 t; cvta.to.shared.u64 t, %1; cvt.u32.u64 %0, t; }" : "=r"(a) : "l"(p));
    return a;
}
__device__ __forceinline__ void cp_async16(uint32_t dst, const void* src) {
    asm volatile("cp.async.cg.shared.global [%0], [%1], 16;" :: "r"(dst), "l"(src));
}
#define CP_COMMIT() asm volatile("cp.async.commit_group;" ::: "memory")
#define CP_WAIT(n)  asm volatile("cp.async.wait_group %0;" :: "n"(n) : "memory")

#define LDSM_X4(r, a)                                                          \
    asm volatile("ldmatrix.sync.aligned.m8n8.x4.shared.b16 {%0,%1,%2,%3},[%4];"\
        : "=r"((r)[0]), "=r"((r)[1]), "=r"((r)[2]), "=r"((r)[3]) : "r"(a))

__device__ __forceinline__ void mma16816(float* d, const uint32_t* a, const uint32_t* b) {
    asm volatile("mma.sync.aligned.m16n8k16.row.col.f32.f16.f16.f32 "
        "{%0,%1,%2,%3},{%4,%5,%6,%7},{%8,%9},{%0,%1,%2,%3};"
        : "+f"(d[0]), "+f"(d[1]), "+f"(d[2]), "+f"(d[3])
        : "r"(a[0]), "r"(a[1]), "r"(a[2]), "r"(a[3]), "r"(b[0]), "r"(b[1]));
}

// ---------------------------------------------------------------------------
// scratch (all big intermediates fp16)
// ---------------------------------------------------------------------------
__device__ __half g_qkvh [MTOT * 1536];   // q|k|v
__device__ __half g_knvsh[MTOT * 1024];   // kn|vs
__device__ __half g_qnh  [MTOT * C_];
__device__ __half g_wh   [MTOT * C_];     // v * prior
__device__ __half g_oh   [MTOT * C_];
__device__ __half g_p1h  [MTOT * C_];
__device__ float  g_ab   [B_ * C_ * C_];
__device__ __half g_xh [MTOT * C_];
__device__ __half g_ih [MTOT * C_];
__device__ __half g_sh [MTOT * C_];
__device__ __half g_knTh[B_ * C_ * N_], g_knTl[B_ * C_ * N_];
__device__ __half g_qnTh[B_ * C_ * N_], g_qnTl[B_ * C_ * N_];
__device__ __half g_abh[B_ * C_ * C_],  g_abl[B_ * C_ * C_];
__device__ __half g_w3h[1536 * C_], g_w3l[1536 * C_];
__device__ __half g_w2h[1024 * C_], g_w2l[1024 * C_];
__device__ __half g_wqh[C_ * C_],   g_wql[C_ * C_];
__device__ __half g_wph[C_ * C_],   g_wpl[C_ * C_];
__device__ float g_Gp [NSLICE * 64 * 64 * 64];
__device__ float g_nkp[NSLICE * 64 * 64];
__device__ float g_nqp[NSLICE * 64 * 64];
__device__ float g_attn[64 * 64 * 64];

// ---------------------------------------------------------------------------
// HMMA GEMM: acc = sum_k A*(Bh+Bl) (+AlBh if PASSES=3); epilogue:
// v = acc*alpha (+bias) (+resH) (*vmulH); optional fp32 C and/or fp16 outH.
// CTA 128x128, BK=32, 8 warps, 3-stage cp.async, 80B-padded smem rows.
// ---------------------------------------------------------------------------
#define TILE_B   10240            // 128 rows * 80 B

template <int PASSES>
__global__ __launch_bounds__(256, 1) void gemm_h(
    const __half* __restrict__ Ah, const __half* __restrict__ Al,
    const __half* __restrict__ Bh, const __half* __restrict__ Bl,
    float* __restrict__ C, int K, int ldA, int ldB, int ldC,
    long sA, long sB, long sC,
    const float* __restrict__ bias,
    const __half* __restrict__ resH, int ldRes, long sRes,
    float alpha,
    __half* __restrict__ outH, int ldH, long sH,
    const __half* __restrict__ vmulH, int ldV, long sV)
{
    constexpr int NT = (PASSES == 3) ? 4 : 3;
    constexpr int STAGE_B = NT * TILE_B;
    extern __shared__ char smem[];
    const int m0 = blockIdx.y * 128, n0 = blockIdx.x * 128;
    Ah += blockIdx.z * sA;
    if (PASSES == 3) Al += blockIdx.z * sA;
    Bh += blockIdx.z * sB; Bl += blockIdx.z * sB;
    if (C)     C     += blockIdx.z * sC;
    if (resH)  resH  += blockIdx.z * sRes;
    if (outH)  outH  += blockIdx.z * sH;
    if (vmulH) vmulH += blockIdx.z * sV;

    const int tid = threadIdx.x;
    const int wid = tid >> 5, lane = tid & 31;
    const int wm = (wid & 1) * 64;
    const int wn = (wid >> 1) * 32;
    const uint32_t sbase = smem_u32(smem);

    float acc[4][4][4];
#pragma unroll
    for (int i = 0; i < 4; i++)
#pragma unroll
        for (int j = 0; j < 4; j++)
#pragma unroll
            for (int p = 0; p < 4; p++) acc[i][j][p] = 0.f;

    const int KB = K >> 5;

#define STAGE_LOAD(kb, buf) do {                                               \
    int k0 = (kb) << 5;                                                        \
    uint32_t st = sbase + (buf) * STAGE_B;                                     \
    _Pragma("unroll")                                                          \
    for (int pos = 0; pos < 2; pos++) {                                        \
        int idx = tid + pos * 256;                                             \
        int r = idx >> 2, cc = idx & 3;                                        \
        uint32_t so = (uint32_t)(r * 80 + cc * 16);                            \
        long ga = (long)(m0 + r) * ldA + k0 + cc * 8;                          \
        long gb = (long)(n0 + r) * ldB + k0 + cc * 8;                          \
        cp_async16(st + so,              Ah + ga);                             \
        cp_async16(st + TILE_B + so,     Bh + gb);                             \
        cp_async16(st + 2 * TILE_B + so, Bl + gb);                             \
        if (PASSES == 3) cp_async16(st + 3 * TILE_B + so, Al + ga);            \
    }                                                                          \
    CP_COMMIT();                                                               \
} while (0)

    STAGE_LOAD(0, 0);
    STAGE_LOAD(1, 1);

    const int lg = lane >> 3, lr = lane & 7;
    int cbuf = 0, lbuf = 2;

    for (int kb = 0; kb < KB; kb++) {
        if (kb + 1 < KB) CP_WAIT(1); else CP_WAIT(0);
        __syncthreads();
        if (kb + 2 < KB) STAGE_LOAD(kb + 2, lbuf);
        uint32_t st = sbase + cbuf * STAGE_B;

#pragma unroll
        for (int ks = 0; ks < 2; ks++) {
            const int cb = ks * 2;
            uint32_t ah[4][4], al[4][4], bh[4][2], bl[4][2];
#pragma unroll
            for (int mi = 0; mi < 4; mi++) {
                int row = wm + mi * 16 + lr + (lg & 1) * 8;
                int ch  = cb + (lg >> 1);
                uint32_t a = st + (uint32_t)(row * 80 + ch * 16);
                LDSM_X4(ah[mi], a);
                if (PASSES == 3) LDSM_X4(al[mi], a + 3 * TILE_B);
            }
#pragma unroll
            for (int np = 0; np < 2; np++) {
                int row = wn + np * 16 + lr + (lg >> 1) * 8;
                int ch  = cb + (lg & 1);
                uint32_t a = st + TILE_B + (uint32_t)(row * 80 + ch * 16);
                uint32_t t4[4];
                LDSM_X4(t4, a);
                bh[np * 2][0] = t4[0]; bh[np * 2][1] = t4[1];
                bh[np * 2 + 1][0] = t4[2]; bh[np * 2 + 1][1] = t4[3];
                LDSM_X4(t4, a + TILE_B);
                bl[np * 2][0] = t4[0]; bl[np * 2][1] = t4[1];
                bl[np * 2 + 1][0] = t4[2]; bl[np * 2 + 1][1] = t4[3];
            }
#pragma unroll
            for (int mi = 0; mi < 4; mi++)
#pragma unroll
                for (int nj = 0; nj < 4; nj++) {
                    mma16816(acc[mi][nj], ah[mi], bh[nj]);
                    mma16816(acc[mi][nj], ah[mi], bl[nj]);
                    if (PASSES == 3) mma16816(acc[mi][nj], al[mi], bh[nj]);
                }
        }
        cbuf = (cbuf == 2) ? 0 : cbuf + 1;
        lbuf = (lbuf == 2) ? 0 : lbuf + 1;
    }

    const int er = lane >> 2, ec = (lane & 3) * 2;
#pragma unroll
    for (int mi = 0; mi < 4; mi++)
#pragma unroll
        for (int nj = 0; nj < 4; nj++) {
            int col = n0 + wn + nj * 8 + ec;
#pragma unroll
            for (int p = 0; p < 2; p++) {
                int row = m0 + wm + mi * 16 + er + p * 8;
                float2 v;
                v.x = acc[mi][nj][p * 2 + 0] * alpha;
                v.y = acc[mi][nj][p * 2 + 1] * alpha;
                if (bias) { v.x += bias[col]; v.y += bias[col + 1]; }
                if (resH) {
                    __half2 r2 = *(const __half2*)(resH + (long)row * ldRes + col);
                    v.x += __half2float(__low2half(r2));
                    v.y += __half2float(__high2half(r2));
                }
                if (vmulH) {
                    __half2 m2 = *(const __half2*)(vmulH + (long)row * ldV + col);
                    v.x *= __half2float(__low2half(m2));
                    v.y *= __half2float(__high2half(m2));
                }
                if (C) *(float2*)(C + (long)row * ldC + col) = v;
                if (outH)
                    *(__half2*)(outH + (long)row * ldH + col) =
                        __halves2half2(__float2half_rn(v.x), __float2half_rn(v.y));
            }
        }
}

// ---------------------------------------------------------------------------
// fp32 -> fp16 hi (contiguous)
// ---------------------------------------------------------------------------
__global__ void split_hi(const float* __restrict__ in, __half* __restrict__ h, long n4)
{
    long i = ((long)blockIdx.x * blockDim.x + threadIdx.x);
    if (i >= n4) return;
    i *= 4;
    float4 v = *(const float4*)(in + i);
    *(__half2*)(h + i)     = __halves2half2(__float2half_rn(v.x), __float2half_rn(v.y));
    *(__half2*)(h + i + 2) = __halves2half2(__float2half_rn(v.z), __float2half_rn(v.w));
}

// ---------------------------------------------------------------------------
// transpose + split (weights): fp32 [R,C](ldIn) -> fp16 hi/lo [C,R](ldOut)
// ---------------------------------------------------------------------------
__global__ void transpose_split(const float* __restrict__ in, int ldIn, long sIn,
                                __half* __restrict__ oh, __half* __restrict__ ol,
                                int ldOut, long sOut)
{
    in += blockIdx.z * sIn; oh += blockIdx.z * sOut; ol += blockIdx.z * sOut;
    __shared__ float tile[32][33];
    int c0 = blockIdx.x * 32, r0 = blockIdx.y * 32;
    int tx = threadIdx.x, ty = threadIdx.y;
#pragma unroll
    for (int i = 0; i < 4; i++)
        tile[ty + 8 * i][tx] = in[(long)(r0 + ty + 8 * i) * ldIn + c0 + tx];
    __syncthreads();
#pragma unroll
    for (int i = 0; i < 4; i++) {
        float v = tile[tx][ty + 8 * i];
        __half hh = __float2half_rn(v);
        long o = (long)(c0 + ty + 8 * i) * ldOut + r0 + tx;
        oh[o] = hh;
        ol[o] = __float2half_rn(v - __half2float(hh));
    }
}

// ---------------------------------------------------------------------------
// FUSED: LayerNorm rows (512, fp16 in) + transpose + fp16 hi/lo split.
// ---------------------------------------------------------------------------
#define LDT 516
#define LNT_SMEM (32 * LDT * 4)   // 66048 B

__global__ __launch_bounds__(256) void ln_t_split(
    const __half* __restrict__ in, int ldIn, long sIn,
    const float* __restrict__ gg, const float* __restrict__ bb,
    __half* __restrict__ oh, __half* __restrict__ ol, long sOut)
{
    extern __shared__ float tile[];
    in += blockIdx.y * sIn; oh += blockIdx.y * sOut; ol += blockIdx.y * sOut;
    const int r0 = blockIdx.x * 32;
    const int t = threadIdx.x;

    // load 32x512 fp16 -> fp32 smem
#pragma unroll
    for (int i = 0; i < 8; i++) {
        int lin = t + i * 256;
        int r = lin >> 6, c8 = (lin & 63) * 8;
        uint4 raw = *(const uint4*)(in + (long)(r0 + r) * ldIn + c8);
        const __half2* hp = (const __half2*)&raw;
        float* dst = &tile[r * LDT + c8];
#pragma unroll
        for (int j = 0; j < 4; j++) {
            dst[j * 2 + 0] = __half2float(__low2half(hp[j]));
            dst[j * 2 + 1] = __half2float(__high2half(hp[j]));
        }
    }
    __syncthreads();

    __shared__ float mu_s[32], inv_s[32];
    const int w = t >> 5, lane = t & 31;
#pragma unroll
    for (int rr = 0; rr < 4; rr++) {
        int r = w * 4 + rr;
        float s = 0.f, q = 0.f;
#pragma unroll
        for (int i = 0; i < 16; i++) {
            float v = tile[r * LDT + lane + i * 32];
            s += v; q += v * v;
        }
#pragma unroll
        for (int o = 16; o; o >>= 1) {
            s += __shfl_xor_sync(0xffffffffu, s, o);
            q += __shfl_xor_sync(0xffffffffu, q, o);
        }
        if (lane == 0) {
            float mu = s * (1.f / C_);
            mu_s[r]  = mu;
            inv_s[r] = rsqrtf(q * (1.f / C_) - mu * mu + 1e-5f);
        }
    }
    __syncthreads();

    const int r = t & 31, cg = t >> 5;
    const float mu = mu_s[r], inv = inv_s[r];
#pragma unroll 8
    for (int cc = 0; cc < 64; cc++) {
        int c = cc * 8 + cg;
        float v = (tile[r * LDT + c] - mu) * inv * gg[c] + bb[c];
        __half hh = __float2half_rn(v);
        long o = (long)c * N_ + r0 + r;
        oh[o] = hh;
        ol[o] = __float2half_rn(v - __half2float(hh));
    }
}

// ---------------------------------------------------------------------------
// SIF softmax rows -> fp16 hi/lo (row-major)
// ---------------------------------------------------------------------------
__global__ void softmax_ab(const float* __restrict__ Ab,
                           __half* __restrict__ oh, __half* __restrict__ ol)
{
    long bi = blockIdx.x;
    const float* row = Ab + bi * 512;
    int t = threadIdx.x;
    float4 v = *(const float4*)(row + t * 4);
    float m = fmaxf(fmaxf(v.x, v.y), fmaxf(v.z, v.w));
#pragma unroll
    for (int o = 16; o; o >>= 1) m = fmaxf(m, __shfl_xor_sync(0xffffffffu, m, o));
    __shared__ float rm[4], rs[4];
    if ((t & 31) == 0) rm[t >> 5] = m;
    __syncthreads();
    m = fmaxf(fmaxf(rm[0], rm[1]), fmaxf(rm[2], rm[3]));
    float4 e;
    e.x = expf(v.x - m); e.y = expf(v.y - m);
    e.z = expf(v.z - m); e.w = expf(v.w - m);
    float s = e.x + e.y + e.z + e.w;
#pragma unroll
    for (int o = 16; o; o >>= 1) s += __shfl_xor_sync(0xffffffffu, s, o);
    if ((t & 31) == 0) rs[t >> 5] = s;
    __syncthreads();
    s = rs[0] + rs[1] + rs[2] + rs[3];
    float inv = 1.f / s;
    e.x *= inv; e.y *= inv; e.z *= inv; e.w *= inv;
    long o = bi * 512 + t * 4;
    __half hx = __float2half_rn(e.x), hy = __float2half_rn(e.y);
    __half hz = __float2half_rn(e.z), hw = __float2half_rn(e.w);
    *(__half2*)(oh + o)     = __halves2half2(hx, hy);
    *(__half2*)(oh + o + 2) = __halves2half2(hz, hw);
    *(__half2*)(ol + o) = __halves2half2(
        __float2half_rn(e.x - __half2float(hx)),
        __float2half_rn(e.y - __half2float(hy)));
    *(__half2*)(ol + o + 2) = __halves2half2(
        __float2half_rn(e.z - __half2float(hz)),
        __float2half_rn(e.w - __half2float(hw)));
}

// ---------------------------------------------------------------------------
// FG-MSA (reads fp16 q,k from g_qkvh)
// ---------------------------------------------------------------------------
__global__ void msa_g()
{
    int bh = blockIdx.x, sl = blockIdx.y;
    int b = bh >> 3, h = bh & 7;
    const int NS = N_ / NSLICE;
    int n0 = sl * NS;
    __shared__ float ks[16][64];
    __shared__ float qs[16][64];
    int t = threadIdx.x;
    int ty = t >> 4, tx = t & 15;
    const __half* qb = g_qkvh + (long)b * N_ * 1536 + h * DH;
    const __half* kb = qb + 512;
    float acc[4][4];
#pragma unroll
    for (int i = 0; i < 4; i++)
#pragma unroll
        for (int j = 0; j < 4; j++) acc[i][j] = 0.f;
    float ssk = 0.f, ssq = 0.f;
    int lkk = t >> 4, lc4 = (t & 15) << 2;
    for (int nb = 0; nb < NS; nb += 16) {
        long roff = (long)(n0 + nb + lkk) * 1536 + lc4;
        {
            float2 rk = *(const float2*)(kb + roff);
            float2 rq = *(const float2*)(qb + roff);
            const __half2* pk = (const __half2*)&rk;
            const __half2* pq = (const __half2*)&rq;
            ks[lkk][lc4 + 0] = __half2float(__low2half(pk[0]));
            ks[lkk][lc4 + 1] = __half2float(__high2half(pk[0]));
            ks[lkk][lc4 + 2] = __half2float(__low2half(pk[1]));
            ks[lkk][lc4 + 3] = __half2float(__high2half(pk[1]));
            qs[lkk][lc4 + 0] = __half2float(__low2half(pq[0]));
            qs[lkk][lc4 + 1] = __half2float(__high2half(pq[0]));
            qs[lkk][lc4 + 2] = __half2float(__low2half(pq[1]));
            qs[lkk][lc4 + 3] = __half2float(__high2half(pq[1]));
        }
        __syncthreads();
#pragma unroll
        for (int kk = 0; kk < 16; kk++) {
            float a[4], bv[4];
#pragma unroll
            for (int i = 0; i < 4; i++) a[i] = ks[kk][ty * 4 + i];
#pragma unroll
            for (int j = 0; j < 4; j++) bv[j] = qs[kk][tx * 4 + j];
#pragma unroll
            for (int i = 0; i < 4; i++)
#pragma unroll
                for (int j = 0; j < 4; j++) acc[i][j] += a[i] * bv[j];
        }
        if (t < 64) {
#pragma unroll
            for (int kk = 0; kk < 16; kk++) {
                float kv = ks[kk][t], qv = qs[kk][t];
                ssk += kv * kv; ssq += qv * qv;
            }
        }
        __syncthreads();
    }
    float* Gb = g_Gp + ((long)sl * 64 + bh) * 4096;
#pragma unroll
    for (int i = 0; i < 4; i++)
#pragma unroll
        for (int j = 0; j < 4; j++)
            Gb[(ty * 4 + i) * 64 + tx * 4 + j] = acc[i][j];
    if (t < 64) {
        g_nkp[((long)sl * 64 + bh) * 64 + t] = ssk;
        g_nqp[((long)sl * 64 + bh) * 64 + t] = ssq;
    }
}

__global__ void msa_soft(const float* __restrict__ rescale)
{
    int r = blockIdx.x;
    int bh = r >> 6, d = r & 63, h = bh & 7;
    int t = threadIdx.x;
    float gsum = 0.f, nks = 0.f, nqs = 0.f;
#pragma unroll
    for (int sl = 0; sl < NSLICE; sl++) {
        gsum += g_Gp[((long)sl * 64 + bh) * 4096 + d * 64 + t];
        nks  += g_nkp[((long)sl * 64 + bh) * 64 + d];
        nqs  += g_nqp[((long)sl * 64 + bh) * 64 + t];
    }
    float nk = fmaxf(sqrtf(nks), 1e-12f);
    float nq = fmaxf(sqrtf(nqs), 1e-12f);
    float val = gsum * (rescale[h] / (nk * nq));
    float m = val;
#pragma unroll
    for (int o = 16; o; o >>= 1) m = fmaxf(m, __shfl_xor_sync(0xffffffffu, m, o));
    __shared__ float rm[2], rs[2];
    if ((t & 31) == 0) rm[t >> 5] = m;
    __syncthreads();
    m = fmaxf(rm[0], rm[1]);
    float e = expf(val - m);
    float s = e;
#pragma unroll
    for (int o = 16; o; o >>= 1) s += __shfl_xor_sync(0xffffffffu, s, o);
    if ((t & 31) == 0) rs[t >> 5] = s;
    __syncthreads();
    s = rs[0] + rs[1];
    g_attn[(long)bh * 4096 + d * 64 + t] = e / s;
}

// o[n, h*64+d] = sum_e attn[d,e] * w[n,e];  w = fp16 g_wh
__global__ void msa_o()
{
    int bh = blockIdx.x;
    int b = bh >> 3, h = bh & 7;
    int n0 = blockIdx.y * (N_ / NSLICE);
    __shared__ float at[64][65];
    __shared__ float vg[16][64];
    int t = threadIdx.x;
#pragma unroll
    for (int l = 0; l < 16; l++) {
        int idx = l * 256 + t;
        at[idx >> 6][idx & 63] = g_attn[(long)bh * 4096 + idx];
    }
    __syncthreads();
    const __half* wb = g_wh + (long)b * N_ * C_ + h * DH;
    long obase = (long)b * N_ * C_ + h * DH;
    int lkk = t >> 4, lc4 = (t & 15) << 2;
    int ty = t >> 4, tx = t & 15;
    for (int nb = 0; nb < 256; nb += 16) {
        {
            long rv = (long)(n0 + nb + lkk) * C_ + lc4;
            float2 raw = *(const float2*)(wb + rv);
            const __half2* hp = (const __half2*)&raw;
            vg[lkk][lc4 + 0] = __half2float(__low2half(hp[0]));
            vg[lkk][lc4 + 1] = __half2float(__high2half(hp[0]));
            vg[lkk][lc4 + 2] = __half2float(__low2half(hp[1]));
            vg[lkk][lc4 + 3] = __half2float(__high2half(hp[1]));
        }
        __syncthreads();
        float s0 = 0.f, s1 = 0.f, s2 = 0.f, s3 = 0.f;
#pragma unroll
        for (int e = 0; e < 64; e++) {
            float vv = vg[ty][e];
            s0 += at[tx * 4 + 0][e] * vv;
            s1 += at[tx * 4 + 1][e] * vv;
            s2 += at[tx * 4 + 2][e] * vv;
            s3 += at[tx * 4 + 3][e] * vv;
        }
        long off = obase + (long)(n0 + nb + ty) * C_ + tx * 4;
        *(__half2*)(g_oh + off)     = __halves2half2(__float2half_rn(s0), __float2half_rn(s1));
        *(__half2*)(g_oh + off + 2) = __halves2half2(__float2half_rn(s2), __float2half_rn(s3));
        __syncthreads();
    }
}

// ---------------------------------------------------------------------------
// depthwise conv (fp16 input)
// ---------------------------------------------------------------------------
__device__ __forceinline__ float gelu_exact(float x)
{
    return 0.5f * x * (1.f + erff(x * 0.70710678118654752f));
}

template <bool GELU, bool ACCUM>
__global__ void dwconv3x3_h(const __half* __restrict__ in, int ldIn,
                            const float* __restrict__ w,
                            float* __restrict__ outF, __half* __restrict__ outHn)
{
    int t = threadIdx.x;
    int c = t * 4;
    float wr[3][3][4];
#pragma unroll
    for (int ky = 0; ky < 3; ky++)
#pragma unroll
        for (int kx = 0; kx < 3; kx++)
#pragma unroll
            for (int i = 0; i < 4; i++)
                wr[ky][kx][i] = w[(long)(c + i) * 9 + ky * 3 + kx];
    long p0 = (long)blockIdx.x * 8;
    int b = (int)(p0 >> 12);
    int yx0 = (int)(p0 & 4095);
#pragma unroll
    for (int px = 0; px < 8; px++) {
        int yx = yx0 + px;
        int y = yx >> 6, x = yx & 63;
        float ax = 0.f, ay = 0.f, az = 0.f, aw = 0.f;
#pragma unroll
        for (int ky = 0; ky < 3; ky++) {
            int yy = y + ky - 1;
            if (yy < 0 || yy > 63) continue;
#pragma unroll
            for (int kx = 0; kx < 3; kx++) {
                int xx = x + kx - 1;
                if (xx < 0 || xx > 63) continue;
                float2 raw = *(const float2*)(in + ((long)(b << 12) + (yy << 6) + xx) * ldIn + c);
                const __half2* hp = (const __half2*)&raw;
                ax += __half2float(__low2half(hp[0]))  * wr[ky][kx][0];
                ay += __half2float(__high2half(hp[0])) * wr[ky][kx][1];
                az += __half2float(__low2half(hp[1]))  * wr[ky][kx][2];
                aw += __half2float(__high2half(hp[1])) * wr[ky][kx][3];
            }
        }
        if (GELU) {
            ax = gelu_exact(ax); ay = gelu_exact(ay);
            az = gelu_exact(az); aw = gelu_exact(aw);
        }
        long off = ((long)(b << 12) + yx) * C_ + c;
        if (ACCUM) {
            float4 o = *(float4*)(outF + off);
            o.x += ax; o.y += ay; o.z += az; o.w += aw;
            *(float4*)(outF + off) = o;
        } else {
            *(__half2*)(outHn + off)     = __halves2half2(__float2half_rn(ax), __float2half_rn(ay));
            *(__half2*)(outHn + off + 2) = __halves2half2(__float2half_rn(az), __float2half_rn(aw));
        }
    }
}

// ---------------------------------------------------------------------------
// host
// ---------------------------------------------------------------------------
extern "C" void kernel_launch(void* const* d_in, const int* in_sizes, int n_in,
                              void* d_out, int out_size)
{
    const float* x       = (const float*)d_in[0];
    const float* illu    = (const float*)d_in[1];
    const float* sem     = (const float*)d_in[2];
    const float* Wk_sif  = (const float*)d_in[3];
    const float* Wq_sif  = (const float*)d_in[4];
    const float* Wv_sif  = (const float*)d_in[5];
    const float* ln_g    = (const float*)d_in[6];
    const float* ln_b    = (const float*)d_in[7];
    const float* Wq      = (const float*)d_in[8];
    const float* Wk      = (const float*)d_in[9];
    const float* Wv      = (const float*)d_in[10];
    const float* rescale = (const float*)d_in[11];
    const float* proj_w  = (const float*)d_in[12];
    const float* proj_b  = (const float*)d_in[13];
    const float* dw1     = (const float*)d_in[14];
    const float* dw2     = (const float*)d_in[15];
    float* out = (float*)d_out;

    cudaFuncSetAttribute(gemm_h<2>, cudaFuncAttributeMaxDynamicSharedMemorySize, 3 * 3 * TILE_B);
    cudaFuncSetAttribute(gemm_h<3>, cudaFuncAttributeMaxDynamicSharedMemorySize, 3 * 4 * TILE_B);
    cudaFuncSetAttribute(ln_t_split, cudaFuncAttributeMaxDynamicSharedMemorySize, LNT_SMEM);

#define SYM(p, s) do { void* _t; cudaGetSymbolAddress(&_t, s); p = (decltype(p))_t; } while (0)
    float *ab;
    __half *qkvh, *knvsh, *qnh, *wh, *oh, *p1h;
    __half *xh, *ih, *sh;
    __half *knTh, *knTl, *qnTh, *qnTl, *abh, *abl;
    __half *w3h, *w3l, *w2h, *w2l, *wqh, *wql, *wph, *wpl;
    SYM(ab, g_ab);
    SYM(qkvh, g_qkvh); SYM(knvsh, g_knvsh); SYM(qnh, g_qnh);
    SYM(wh, g_wh); SYM(oh, g_oh); SYM(p1h, g_p1h);
    SYM(xh, g_xh); SYM(ih, g_ih); SYM(sh, g_sh);
    SYM(knTh, g_knTh); SYM(knTl, g_knTl); SYM(qnTh, g_qnTh); SYM(qnTl, g_qnTl);
    SYM(abh, g_abh); SYM(abl, g_abl);
    SYM(w3h, g_w3h); SYM(w3l, g_w3l); SYM(w2h, g_w2h); SYM(w2l, g_w2l);
    SYM(wqh, g_wqh); SYM(wql, g_wql); SYM(wph, g_wpl == nullptr ? g_wph : g_wph); SYM(wpl, g_wpl);

    dim3 tb(32, 8);
    dim3 tw(16, 16, 1);
    transpose_split<<<tw, tb>>>(Wq,     C_, 0, w3h,               w3l,               C_, 0);
    transpose_split<<<tw, tb>>>(Wk,     C_, 0, w3h + C_ * C_,     w3l + C_ * C_,     C_, 0);
    transpose_split<<<tw, tb>>>(Wv,     C_, 0, w3h + 2 * C_ * C_, w3l + 2 * C_ * C_, C_, 0);
    transpose_split<<<tw, tb>>>(Wk_sif, C_, 0, w2h,               w2l,               C_, 0);
    transpose_split<<<tw, tb>>>(Wv_sif, C_, 0, w2h + C_ * C_,     w2l + C_ * C_,     C_, 0);
    transpose_split<<<tw, tb>>>(Wq_sif, C_, 0, wqh,               wql,               C_, 0);
    transpose_split<<<tw, tb>>>(proj_w, C_, 0, wph,               wpl,               C_, 0);

    long n4 = (long)MTOT * C_ / 4;
    split_hi<<<(unsigned)((n4 + 255) / 256), 256>>>(x,    xh, n4);
    split_hi<<<(unsigned)((n4 + 255) / 256), 256>>>(illu, ih, n4);
    split_hi<<<(unsigned)((n4 + 255) / 256), 256>>>(sem,  sh, n4);

    // GEMM1: qkv(fp16) = x @ [Wq|Wk|Wv]
    gemm_h<2><<<dim3(12, 256, 1), 256, 3 * 3 * TILE_B>>>(xh, nullptr, w3h, w3l,
        nullptr, C_, C_, C_, 0, 0, 0, 0, nullptr, nullptr, 0, 0, 1.f,
        qkvh, 1536, 0, nullptr, 0, 0);
    // GEMM2: [kn|vs](fp16) = illu @ [Wk_sif|Wv_sif]
    gemm_h<2><<<dim3(8, 256, 1), 256, 3 * 3 * TILE_B>>>(ih, nullptr, w2h, w2l,
        nullptr, C_, C_, C_, 0, 0, 0, 0, nullptr, nullptr, 0, 0, 1.f,
        knvsh, 1024, 0, nullptr, 0, 0);
    // GEMM3: qn(fp16) = sem @ Wq_sif
    gemm_h<2><<<dim3(4, 256, 1), 256, 3 * 3 * TILE_B>>>(sh, nullptr, wqh, wql,
        nullptr, C_, C_, C_, 0, 0, 0, 0, nullptr, nullptr, 0, 0, 1.f,
        qnh, 512, 0, nullptr, 0, 0);

    // fused LN + transpose + split
    ln_t_split<<<dim3(128, 8), 256, LNT_SMEM>>>(knvsh, 1024, (long)N_ * 1024,
        ln_g, ln_b, knTh, knTl, (long)C_ * N_);
    ln_t_split<<<dim3(128, 8), 256, LNT_SMEM>>>(qnh, 512, (long)N_ * 512,
        ln_g, ln_b, qnTh, qnTl, (long)C_ * N_);

    // GEMM4 (3-pass): Ab[b] = (Qn^T Kn)/sqrt(C)
    gemm_h<3><<<dim3(4, 4, 8), 256, 3 * 4 * TILE_B>>>(qnTh, qnTl, knTh, knTl,
        ab, N_, N_, N_, C_, (long)C_ * N_, (long)C_ * N_, (long)C_ * C_,
        nullptr, nullptr, 0, 0, 0.044194173824159216f, nullptr, 0, 0, nullptr, 0, 0);

    softmax_ab<<<B_ * C_, 128>>>(ab, abh, abl);

    // GEMM5: w(fp16) = (V@Ab^T + V) * v   (fused v*prior)
    gemm_h<2><<<dim3(4, 32, 8), 256, 3 * 3 * TILE_B>>>(knvsh + 512, nullptr, abh, abl,
        nullptr, C_, 1024, C_, 0, (long)N_ * 1024, (long)C_ * C_, 0,
        nullptr, knvsh + 512, 1024, (long)N_ * 1024, 1.f,
        wh, 512, (long)N_ * C_, qkvh + 1024, 1536, (long)N_ * 1536);

    // FG-MSA
    msa_g<<<dim3(64, NSLICE), 256>>>();
    msa_soft<<<64 * 64, 64>>>(rescale);
    msa_o<<<dim3(64, NSLICE), 256>>>();

    // GEMM6: out = o @ proj_w + proj_b
    gemm_h<2><<<dim3(4, 256, 1), 256, 3 * 3 * TILE_B>>>(oh, nullptr, wph, wpl,
        out, C_, C_, C_, C_, 0, 0, 0, proj_b, nullptr, 0, 0, 1.f,
        nullptr, 0, 0, nullptr, 0, 0);

    // positional branch (fp16)
    dwconv3x3_h<true,  false><<<MTOT / 8, 128>>>(qkvh + 1024, 1536, dw1, nullptr, p1h);
    dwconv3x3_h<false, true ><<<MTOT / 8, 128>>>(p1h, 512, dw2, out, nullptr);
}

// round 10
// speedup vs baseline: 2.9865x; 1.2127x over previous
#include <cuda_runtime.h>
#include <cuda_fp16.h>
#include <math.h>
#include <stdint.h>

#define B_    8
#define C_    512
#define N_    4096
#define MTOT  32768
#define DH    64
#define NSLICE 16

// ---------------------------------------------------------------------------
// helpers (portable PTX only: cp.async, ldmatrix, mma.sync)
// ---------------------------------------------------------------------------
__device__ __forceinline__ uint32_t smem_u32(const void* p) {
    uint32_t a;
    asm("{ .reg .u64 t; cvta.to.shared.u64 t, %1; cvt.u32.u64 %0, t; }" : "=r"(a) : "l"(p));
    return a;
}
__device__ __forceinline__ void cp_async16(uint32_t dst, const void* src) {
    asm volatile("cp.async.cg.shared.global [%0], [%1], 16;" :: "r"(dst), "l"(src));
}
#define CP_COMMIT() asm volatile("cp.async.commit_group;" ::: "memory")
#define CP_WAIT(n)  asm volatile("cp.async.wait_group %0;" :: "n"(n) : "memory")

#define LDSM_X4(r, a)                                                          \
    asm volatile("ldmatrix.sync.aligned.m8n8.x4.shared.b16 {%0,%1,%2,%3},[%4];"\
        : "=r"((r)[0]), "=r"((r)[1]), "=r"((r)[2]), "=r"((r)[3]) : "r"(a))

__device__ __forceinline__ void mma16816(float* d, const uint32_t* a, const uint32_t* b) {
    asm volatile("mma.sync.aligned.m16n8k16.row.col.f32.f16.f16.f32 "
        "{%0,%1,%2,%3},{%4,%5,%6,%7},{%8,%9},{%0,%1,%2,%3};"
        : "+f"(d[0]), "+f"(d[1]), "+f"(d[2]), "+f"(d[3])
        : "r"(a[0]), "r"(a[1]), "r"(a[2]), "r"(a[3]), "r"(b[0]), "r"(b[1]));
}

// ---------------------------------------------------------------------------
// scratch
// ---------------------------------------------------------------------------
__device__ __half g_qkvh [MTOT * 1536];   // q|k|v
__device__ __half g_knvsh[MTOT * 1024];   // kn|vs
__device__ __half g_qnh  [MTOT * C_];
__device__ __half g_wh   [MTOT * C_];     // v * prior
__device__ __half g_oh   [MTOT * C_];
__device__ __half g_p1h  [MTOT * C_];
__device__ float  g_ab   [B_ * C_ * C_];
__device__ __half g_xh [MTOT * C_];
__device__ __half g_ih [MTOT * C_];
__device__ __half g_sh [MTOT * C_];
__device__ __half g_knTh[B_ * C_ * N_], g_knTl[B_ * C_ * N_];
__device__ __half g_qnTh[B_ * C_ * N_], g_qnTl[B_ * C_ * N_];
__device__ __half g_abh[B_ * C_ * C_],  g_abl[B_ * C_ * C_];
__device__ __half g_w3h[1536 * C_], g_w3l[1536 * C_];
__device__ __half g_w2h[1024 * C_], g_w2l[1024 * C_];
__device__ __half g_wqh[C_ * C_],   g_wql[C_ * C_];
__device__ __half g_wph[C_ * C_],   g_wpl[C_ * C_];
__device__ float g_Gp [NSLICE * 64 * 64 * 64];
__device__ float g_nkp[NSLICE * 64 * 64];
__device__ float g_nqp[NSLICE * 64 * 64];
__device__ float g_attn[64 * 64 * 64];

// ---------------------------------------------------------------------------
// HMMA GEMM, PASSES = 1 (AhBh), 2 (+AhBl), 3 (+AlBh). fp32 TMEM-free acc.
// CTA 128x128, BK=32, 8 warps, 3-stage cp.async, 80B-padded smem rows.
// epilogue: v = acc*alpha (+bias)(+resH)(*vmulH) -> fp32 C and/or fp16 outH.
// ---------------------------------------------------------------------------
#define TILE_B   10240            // 128 rows * 80 B

template <int PASSES>
__global__ __launch_bounds__(256, 1) void gemm_h(
    const __half* __restrict__ Ah, const __half* __restrict__ Al,
    const __half* __restrict__ Bh, const __half* __restrict__ Bl,
    float* __restrict__ C, int K, int ldA, int ldB, int ldC,
    long sA, long sB, long sC,
    const float* __restrict__ bias,
    const __half* __restrict__ resH, int ldRes, long sRes,
    float alpha,
    __half* __restrict__ outH, int ldH, long sH,
    const __half* __restrict__ vmulH, int ldV, long sV)
{
    constexpr int NT = PASSES + 1;        // tiles per stage
    constexpr int STAGE_B = NT * TILE_B;
    extern __shared__ char smem[];
    const int m0 = blockIdx.y * 128, n0 = blockIdx.x * 128;
    Ah += blockIdx.z * sA;
    if (PASSES == 3) Al += blockIdx.z * sA;
    Bh += blockIdx.z * sB;
    if (PASSES >= 2) Bl += blockIdx.z * sB;
    if (C)     C     += blockIdx.z * sC;
    if (resH)  resH  += blockIdx.z * sRes;
    if (outH)  outH  += blockIdx.z * sH;
    if (vmulH) vmulH += blockIdx.z * sV;

    const int tid = threadIdx.x;
    const int wid = tid >> 5, lane = tid & 31;
    const int wm = (wid & 1) * 64;
    const int wn = (wid >> 1) * 32;
    const uint32_t sbase = smem_u32(smem);

    float acc[4][4][4];
#pragma unroll
    for (int i = 0; i < 4; i++)
#pragma unroll
        for (int j = 0; j < 4; j++)
#pragma unroll
            for (int p = 0; p < 4; p++) acc[i][j][p] = 0.f;

    const int KB = K >> 5;

#define STAGE_LOAD(kb, buf) do {                                               \
    int k0 = (kb) << 5;                                                        \
    uint32_t st = sbase + (buf) * STAGE_B;                                     \
    _Pragma("unroll")                                                          \
    for (int pos = 0; pos < 2; pos++) {                                        \
        int idx = tid + pos * 256;                                             \
        int r = idx >> 2, cc = idx & 3;                                        \
        uint32_t so = (uint32_t)(r * 80 + cc * 16);                            \
        long ga = (long)(m0 + r) * ldA + k0 + cc * 8;                          \
        long gb = (long)(n0 + r) * ldB + k0 + cc * 8;                          \
        cp_async16(st + so,          Ah + ga);                                 \
        cp_async16(st + TILE_B + so, Bh + gb);                                 \
        if (PASSES >= 2) cp_async16(st + 2 * TILE_B + so, Bl + gb);            \
        if (PASSES == 3) cp_async16(st + 3 * TILE_B + so, Al + ga);            \
    }                                                                          \
    CP_COMMIT();                                                               \
} while (0)

    STAGE_LOAD(0, 0);
    STAGE_LOAD(1, 1);

    const int lg = lane >> 3, lr = lane & 7;
    int cbuf = 0, lbuf = 2;

    for (int kb = 0; kb < KB; kb++) {
        if (kb + 1 < KB) CP_WAIT(1); else CP_WAIT(0);
        __syncthreads();
        if (kb + 2 < KB) STAGE_LOAD(kb + 2, lbuf);
        uint32_t st = sbase + cbuf * STAGE_B;

#pragma unroll
        for (int ks = 0; ks < 2; ks++) {
            const int cb = ks * 2;
            uint32_t ah[4][4], al[4][4], bh[4][2], bl[4][2];
#pragma unroll
            for (int mi = 0; mi < 4; mi++) {
                int row = wm + mi * 16 + lr + (lg & 1) * 8;
                int ch  = cb + (lg >> 1);
                uint32_t a = st + (uint32_t)(row * 80 + ch * 16);
                LDSM_X4(ah[mi], a);
                if (PASSES == 3) LDSM_X4(al[mi], a + 3 * TILE_B);
            }
#pragma unroll
            for (int np = 0; np < 2; np++) {
                int row = wn + np * 16 + lr + (lg >> 1) * 8;
                int ch  = cb + (lg & 1);
                uint32_t a = st + TILE_B + (uint32_t)(row * 80 + ch * 16);
                uint32_t t4[4];
                LDSM_X4(t4, a);
                bh[np * 2][0] = t4[0]; bh[np * 2][1] = t4[1];
                bh[np * 2 + 1][0] = t4[2]; bh[np * 2 + 1][1] = t4[3];
                if (PASSES >= 2) {
                    LDSM_X4(t4, a + TILE_B);
                    bl[np * 2][0] = t4[0]; bl[np * 2][1] = t4[1];
                    bl[np * 2 + 1][0] = t4[2]; bl[np * 2 + 1][1] = t4[3];
                }
            }
#pragma unroll
            for (int mi = 0; mi < 4; mi++)
#pragma unroll
                for (int nj = 0; nj < 4; nj++) {
                    mma16816(acc[mi][nj], ah[mi], bh[nj]);
                    if (PASSES >= 2) mma16816(acc[mi][nj], ah[mi], bl[nj]);
                    if (PASSES == 3) mma16816(acc[mi][nj], al[mi], bh[nj]);
                }
        }
        cbuf = (cbuf == 2) ? 0 : cbuf + 1;
        lbuf = (lbuf == 2) ? 0 : lbuf + 1;
    }

    const int er = lane >> 2, ec = (lane & 3) * 2;
#pragma unroll
    for (int mi = 0; mi < 4; mi++)
#pragma unroll
        for (int nj = 0; nj < 4; nj++) {
            int col = n0 + wn + nj * 8 + ec;
#pragma unroll
            for (int p = 0; p < 2; p++) {
                int row = m0 + wm + mi * 16 + er + p * 8;
                float2 v;
                v.x = acc[mi][nj][p * 2 + 0] * alpha;
                v.y = acc[mi][nj][p * 2 + 1] * alpha;
                if (bias) { v.x += bias[col]; v.y += bias[col + 1]; }
                if (resH) {
                    __half2 r2 = *(const __half2*)(resH + (long)row * ldRes + col);
                    v.x += __half2float(__low2half(r2));
                    v.y += __half2float(__high2half(r2));
                }
                if (vmulH) {
                    __half2 m2 = *(const __half2*)(vmulH + (long)row * ldV + col);
                    v.x *= __half2float(__low2half(m2));
                    v.y *= __half2float(__high2half(m2));
                }
                if (C) *(float2*)(C + (long)row * ldC + col) = v;
                if (outH)
                    *(__half2*)(outH + (long)row * ldH + col) =
                        __halves2half2(__float2half_rn(v.x), __float2half_rn(v.y));
            }
        }
}

// ---------------------------------------------------------------------------
// fused fp32 -> fp16 for x, illu, sem (3-way ILP per thread)
// ---------------------------------------------------------------------------
__global__ void split_hi3(const float* __restrict__ a, const float* __restrict__ b,
                          const float* __restrict__ c,
                          __half* __restrict__ ha, __half* __restrict__ hb,
                          __half* __restrict__ hc, long n4)
{
    long i = ((long)blockIdx.x * blockDim.x + threadIdx.x);
    if (i >= n4) return;
    i *= 4;
    float4 va = *(const float4*)(a + i);
    float4 vb = *(const float4*)(b + i);
    float4 vc = *(const float4*)(c + i);
    *(__half2*)(ha + i)     = __halves2half2(__float2half_rn(va.x), __float2half_rn(va.y));
    *(__half2*)(ha + i + 2) = __halves2half2(__float2half_rn(va.z), __float2half_rn(va.w));
    *(__half2*)(hb + i)     = __halves2half2(__float2half_rn(vb.x), __float2half_rn(vb.y));
    *(__half2*)(hb + i + 2) = __halves2half2(__float2half_rn(vb.z), __float2half_rn(vb.w));
    *(__half2*)(hc + i)     = __halves2half2(__float2half_rn(vc.x), __float2half_rn(vc.y));
    *(__half2*)(hc + i + 2) = __halves2half2(__float2half_rn(vc.z), __float2half_rn(vc.w));
}

// ---------------------------------------------------------------------------
// transpose + split (weights): fp32 [R,C](ldIn) -> fp16 hi/lo [C,R](ldOut)
// ---------------------------------------------------------------------------
__global__ void transpose_split(const float* __restrict__ in, int ldIn, long sIn,
                                __half* __restrict__ oh, __half* __restrict__ ol,
                                int ldOut, long sOut)
{
    in += blockIdx.z * sIn; oh += blockIdx.z * sOut; ol += blockIdx.z * sOut;
    __shared__ float tile[32][33];
    int c0 = blockIdx.x * 32, r0 = blockIdx.y * 32;
    int tx = threadIdx.x, ty = threadIdx.y;
#pragma unroll
    for (int i = 0; i < 4; i++)
        tile[ty + 8 * i][tx] = in[(long)(r0 + ty + 8 * i) * ldIn + c0 + tx];
    __syncthreads();
#pragma unroll
    for (int i = 0; i < 4; i++) {
        float v = tile[tx][ty + 8 * i];
        __half hh = __float2half_rn(v);
        long o = (long)(c0 + ty + 8 * i) * ldOut + r0 + tx;
        oh[o] = hh;
        ol[o] = __float2half_rn(v - __half2float(hh));
    }
}

// ---------------------------------------------------------------------------
// FUSED: LayerNorm rows (512, fp16 in) + transpose + fp16 hi/lo split.
// ---------------------------------------------------------------------------
#define LDT 516
#define LNT_SMEM (32 * LDT * 4)   // 66048 B

__global__ __launch_bounds__(256) void ln_t_split(
    const __half* __restrict__ in, int ldIn, long sIn,
    const float* __restrict__ gg, const float* __restrict__ bb,
    __half* __restrict__ oh, __half* __restrict__ ol, long sOut)
{
    extern __shared__ float tile[];
    in += blockIdx.y * sIn; oh += blockIdx.y * sOut; ol += blockIdx.y * sOut;
    const int r0 = blockIdx.x * 32;
    const int t = threadIdx.x;

#pragma unroll
    for (int i = 0; i < 8; i++) {
        int lin = t + i * 256;
        int r = lin >> 6, c8 = (lin & 63) * 8;
        uint4 raw = *(const uint4*)(in + (long)(r0 + r) * ldIn + c8);
        const __half2* hp = (const __half2*)&raw;
        float* dst = &tile[r * LDT + c8];
#pragma unroll
        for (int j = 0; j < 4; j++) {
            dst[j * 2 + 0] = __half2float(__low2half(hp[j]));
            dst[j * 2 + 1] = __half2float(__high2half(hp[j]));
        }
    }
    __syncthreads();

    __shared__ float mu_s[32], inv_s[32];
    const int w = t >> 5, lane = t & 31;
#pragma unroll
    for (int rr = 0; rr < 4; rr++) {
        int r = w * 4 + rr;
        float s = 0.f, q = 0.f;
#pragma unroll
        for (int i = 0; i < 16; i++) {
            float v = tile[r * LDT + lane + i * 32];
            s += v; q += v * v;
        }
#pragma unroll
        for (int o = 16; o; o >>= 1) {
            s += __shfl_xor_sync(0xffffffffu, s, o);
            q += __shfl_xor_sync(0xffffffffu, q, o);
        }
        if (lane == 0) {
            float mu = s * (1.f / C_);
            mu_s[r]  = mu;
            inv_s[r] = rsqrtf(q * (1.f / C_) - mu * mu + 1e-5f);
        }
    }
    __syncthreads();

    const int r = t & 31, cg = t >> 5;
    const float mu = mu_s[r], inv = inv_s[r];
#pragma unroll 8
    for (int cc = 0; cc < 64; cc++) {
        int c = cc * 8 + cg;
        float v = (tile[r * LDT + c] - mu) * inv * gg[c] + bb[c];
        __half hh = __float2half_rn(v);
        long o = (long)c * N_ + r0 + r;
        oh[o] = hh;
        ol[o] = __float2half_rn(v - __half2float(hh));
    }
}

// ---------------------------------------------------------------------------
// SIF softmax rows -> fp16 hi/lo (row-major)
// ---------------------------------------------------------------------------
__global__ void softmax_ab(const float* __restrict__ Ab,
                           __half* __restrict__ oh, __half* __restrict__ ol)
{
    long bi = blockIdx.x;
    const float* row = Ab + bi * 512;
    int t = threadIdx.x;
    float4 v = *(const float4*)(row + t * 4);
    float m = fmaxf(fmaxf(v.x, v.y), fmaxf(v.z, v.w));
#pragma unroll
    for (int o = 16; o; o >>= 1) m = fmaxf(m, __shfl_xor_sync(0xffffffffu, m, o));
    __shared__ float rm[4], rs[4];
    if ((t & 31) == 0) rm[t >> 5] = m;
    __syncthreads();
    m = fmaxf(fmaxf(rm[0], rm[1]), fmaxf(rm[2], rm[3]));
    float4 e;
    e.x = expf(v.x - m); e.y = expf(v.y - m);
    e.z = expf(v.z - m); e.w = expf(v.w - m);
    float s = e.x + e.y + e.z + e.w;
#pragma unroll
    for (int o = 16; o; o >>= 1) s += __shfl_xor_sync(0xffffffffu, s, o);
    if ((t & 31) == 0) rs[t >> 5] = s;
    __syncthreads();
    s = rs[0] + rs[1] + rs[2] + rs[3];
    float inv = 1.f / s;
    e.x *= inv; e.y *= inv; e.z *= inv; e.w *= inv;
    long o = bi * 512 + t * 4;
    __half hx = __float2half_rn(e.x), hy = __float2half_rn(e.y);
    __half hz = __float2half_rn(e.z), hw = __float2half_rn(e.w);
    *(__half2*)(oh + o)     = __halves2half2(hx, hy);
    *(__half2*)(oh + o + 2) = __halves2half2(hz, hw);
    *(__half2*)(ol + o) = __halves2half2(
        __float2half_rn(e.x - __half2float(hx)),
        __float2half_rn(e.y - __half2float(hy)));
    *(__half2*)(ol + o + 2) = __halves2half2(
        __float2half_rn(e.z - __half2float(hz)),
        __float2half_rn(e.w - __half2float(hw)));
}

// ---------------------------------------------------------------------------
// FG-MSA (reads fp16 q,k from g_qkvh)
// ---------------------------------------------------------------------------
__global__ void msa_g()
{
    int bh = blockIdx.x, sl = blockIdx.y;
    int b = bh >> 3, h = bh & 7;
    const int NS = N_ / NSLICE;
    int n0 = sl * NS;
    __shared__ float ks[16][64];
    __shared__ float qs[16][64];
    int t = threadIdx.x;
    int ty = t >> 4, tx = t & 15;
    const __half* qb = g_qkvh + (long)b * N_ * 1536 + h * DH;
    const __half* kb = qb + 512;
    float acc[4][4];
#pragma unroll
    for (int i = 0; i < 4; i++)
#pragma unroll
        for (int j = 0; j < 4; j++) acc[i][j] = 0.f;
    float ssk = 0.f, ssq = 0.f;
    int lkk = t >> 4, lc4 = (t & 15) << 2;
    for (int nb = 0; nb < NS; nb += 16) {
        long roff = (long)(n0 + nb + lkk) * 1536 + lc4;
        {
            float2 rk = *(const float2*)(kb + roff);
            float2 rq = *(const float2*)(qb + roff);
            const __half2* pk = (const __half2*)&rk;
            const __half2* pq = (const __half2*)&rq;
            ks[lkk][lc4 + 0] = __half2float(__low2half(pk[0]));
            ks[lkk][lc4 + 1] = __half2float(__high2half(pk[0]));
            ks[lkk][lc4 + 2] = __half2float(__low2half(pk[1]));
            ks[lkk][lc4 + 3] = __half2float(__high2half(pk[1]));
            qs[lkk][lc4 + 0] = __half2float(__low2half(pq[0]));
            qs[lkk][lc4 + 1] = __half2float(__high2half(pq[0]));
            qs[lkk][lc4 + 2] = __half2float(__low2half(pq[1]));
            qs[lkk][lc4 + 3] = __half2float(__high2half(pq[1]));
        }
        __syncthreads();
#pragma unroll
        for (int kk = 0; kk < 16; kk++) {
            float a[4], bv[4];
#pragma unroll
            for (int i = 0; i < 4; i++) a[i] = ks[kk][ty * 4 + i];
#pragma unroll
            for (int j = 0; j < 4; j++) bv[j] = qs[kk][tx * 4 + j];
#pragma unroll
            for (int i = 0; i < 4; i++)
#pragma unroll
                for (int j = 0; j < 4; j++) acc[i][j] += a[i] * bv[j];
        }
        if (t < 64) {
#pragma unroll
            for (int kk = 0; kk < 16; kk++) {
                float kv = ks[kk][t], qv = qs[kk][t];
                ssk += kv * kv; ssq += qv * qv;
            }
        }
        __syncthreads();
    }
    float* Gb = g_Gp + ((long)sl * 64 + bh) * 4096;
#pragma unroll
    for (int i = 0; i < 4; i++)
#pragma unroll
        for (int j = 0; j < 4; j++)
            Gb[(ty * 4 + i) * 64 + tx * 4 + j] = acc[i][j];
    if (t < 64) {
        g_nkp[((long)sl * 64 + bh) * 64 + t] = ssk;
        g_nqp[((long)sl * 64 + bh) * 64 + t] = ssq;
    }
}

__global__ void msa_soft(const float* __restrict__ rescale)
{
    int r = blockIdx.x;
    int bh = r >> 6, d = r & 63, h = bh & 7;
    int t = threadIdx.x;
    float gsum = 0.f, nks = 0.f, nqs = 0.f;
#pragma unroll
    for (int sl = 0; sl < NSLICE; sl++) {
        gsum += g_Gp[((long)sl * 64 + bh) * 4096 + d * 64 + t];
        nks  += g_nkp[((long)sl * 64 + bh) * 64 + d];
        nqs  += g_nqp[((long)sl * 64 + bh) * 64 + t];
    }
    float nk = fmaxf(sqrtf(nks), 1e-12f);
    float nq = fmaxf(sqrtf(nqs), 1e-12f);
    float val = gsum * (rescale[h] / (nk * nq));
    float m = val;
#pragma unroll
    for (int o = 16; o; o >>= 1) m = fmaxf(m, __shfl_xor_sync(0xffffffffu, m, o));
    __shared__ float rm[2], rs[2];
    if ((t & 31) == 0) rm[t >> 5] = m;
    __syncthreads();
    m = fmaxf(rm[0], rm[1]);
    float e = expf(val - m);
    float s = e;
#pragma unroll
    for (int o = 16; o; o >>= 1) s += __shfl_xor_sync(0xffffffffu, s, o);
    if ((t & 31) == 0) rs[t >> 5] = s;
    __syncthreads();
    s = rs[0] + rs[1];
    g_attn[(long)bh * 4096 + d * 64 + t] = e / s;
}

__global__ void msa_o()
{
    int bh = blockIdx.x;
    int b = bh >> 3, h = bh & 7;
    int n0 = blockIdx.y * (N_ / NSLICE);
    __shared__ float at[64][65];
    __shared__ float vg[16][64];
    int t = threadIdx.x;
#pragma unroll
    for (int l = 0; l < 16; l++) {
        int idx = l * 256 + t;
        at[idx >> 6][idx & 63] = g_attn[(long)bh * 4096 + idx];
    }
    __syncthreads();
    const __half* wb = g_wh + (long)b * N_ * C_ + h * DH;
    long obase = (long)b * N_ * C_ + h * DH;
    int lkk = t >> 4, lc4 = (t & 15) << 2;
    int ty = t >> 4, tx = t & 15;
    for (int nb = 0; nb < 256; nb += 16) {
        {
            long rv = (long)(n0 + nb + lkk) * C_ + lc4;
            float2 raw = *(const float2*)(wb + rv);
            const __half2* hp = (const __half2*)&raw;
            vg[lkk][lc4 + 0] = __half2float(__low2half(hp[0]));
            vg[lkk][lc4 + 1] = __half2float(__high2half(hp[0]));
            vg[lkk][lc4 + 2] = __half2float(__low2half(hp[1]));
            vg[lkk][lc4 + 3] = __half2float(__high2half(hp[1]));
        }
        __syncthreads();
        float s0 = 0.f, s1 = 0.f, s2 = 0.f, s3 = 0.f;
#pragma unroll
        for (int e = 0; e < 64; e++) {
            float vv = vg[ty][e];
            s0 += at[tx * 4 + 0][e] * vv;
            s1 += at[tx * 4 + 1][e] * vv;
            s2 += at[tx * 4 + 2][e] * vv;
            s3 += at[tx * 4 + 3][e] * vv;
        }
        long off = obase + (long)(n0 + nb + ty) * C_ + tx * 4;
        *(__half2*)(g_oh + off)     = __halves2half2(__float2half_rn(s0), __float2half_rn(s1));
        *(__half2*)(g_oh + off + 2) = __halves2half2(__float2half_rn(s2), __float2half_rn(s3));
        __syncthreads();
    }
}

// ---------------------------------------------------------------------------
// depthwise conv (fp16 input)
// ---------------------------------------------------------------------------
__device__ __forceinline__ float gelu_exact(float x)
{
    return 0.5f * x * (1.f + erff(x * 0.70710678118654752f));
}

template <bool GELU, bool ACCUM>
__global__ void dwconv3x3_h(const __half* __restrict__ in, int ldIn,
                            const float* __restrict__ w,
                            float* __restrict__ outF, __half* __restrict__ outHn)
{
    int t = threadIdx.x;
    int c = t * 4;
    float wr[3][3][4];
#pragma unroll
    for (int ky = 0; ky < 3; ky++)
#pragma unroll
        for (int kx = 0; kx < 3; kx++)
#pragma unroll
            for (int i = 0; i < 4; i++)
                wr[ky][kx][i] = w[(long)(c + i) * 9 + ky * 3 + kx];
    long p0 = (long)blockIdx.x * 8;
    int b = (int)(p0 >> 12);
    int yx0 = (int)(p0 & 4095);
#pragma unroll
    for (int px = 0; px < 8; px++) {
        int yx = yx0 + px;
        int y = yx >> 6, x = yx & 63;
        float ax = 0.f, ay = 0.f, az = 0.f, aw = 0.f;
#pragma unroll
        for (int ky = 0; ky < 3; ky++) {
            int yy = y + ky - 1;
            if (yy < 0 || yy > 63) continue;
#pragma unroll
            for (int kx = 0; kx < 3; kx++) {
                int xx = x + kx - 1;
                if (xx < 0 || xx > 63) continue;
                float2 raw = *(const float2*)(in + ((long)(b << 12) + (yy << 6) + xx) * ldIn + c);
                const __half2* hp = (const __half2*)&raw;
                ax += __half2float(__low2half(hp[0]))  * wr[ky][kx][0];
                ay += __half2float(__high2half(hp[0])) * wr[ky][kx][1];
                az += __half2float(__low2half(hp[1]))  * wr[ky][kx][2];
                aw += __half2float(__high2half(hp[1])) * wr[ky][kx][3];
            }
        }
        if (GELU) {
            ax = gelu_exact(ax); ay = gelu_exact(ay);
            az = gelu_exact(az); aw = gelu_exact(aw);
        }
        long off = ((long)(b << 12) + yx) * C_ + c;
        if (ACCUM) {
            float4 o = *(float4*)(outF + off);
            o.x += ax; o.y += ay; o.z += az; o.w += aw;
            *(float4*)(outF + off) = o;
        } else {
            *(__half2*)(outHn + off)     = __halves2half2(__float2half_rn(ax), __float2half_rn(ay));
            *(__half2*)(outHn + off + 2) = __halves2half2(__float2half_rn(az), __float2half_rn(aw));
        }
    }
}

// ---------------------------------------------------------------------------
// host
// ---------------------------------------------------------------------------
extern "C" void kernel_launch(void* const* d_in, const int* in_sizes, int n_in,
                              void* d_out, int out_size)
{
    const float* x       = (const float*)d_in[0];
    const float* illu    = (const float*)d_in[1];
    const float* sem     = (const float*)d_in[2];
    const float* Wk_sif  = (const float*)d_in[3];
    const float* Wq_sif  = (const float*)d_in[4];
    const float* Wv_sif  = (const float*)d_in[5];
    const float* ln_g    = (const float*)d_in[6];
    const float* ln_b    = (const float*)d_in[7];
    const float* Wq      = (const float*)d_in[8];
    const float* Wk      = (const float*)d_in[9];
    const float* Wv      = (const float*)d_in[10];
    const float* rescale = (const float*)d_in[11];
    const float* proj_w  = (const float*)d_in[12];
    const float* proj_b  = (const float*)d_in[13];
    const float* dw1     = (const float*)d_in[14];
    const float* dw2     = (const float*)d_in[15];
    float* out = (float*)d_out;

    cudaFuncSetAttribute(gemm_h<1>, cudaFuncAttributeMaxDynamicSharedMemorySize, 3 * 2 * TILE_B);
    cudaFuncSetAttribute(gemm_h<2>, cudaFuncAttributeMaxDynamicSharedMemorySize, 3 * 3 * TILE_B);
    cudaFuncSetAttribute(gemm_h<3>, cudaFuncAttributeMaxDynamicSharedMemorySize, 3 * 4 * TILE_B);
    cudaFuncSetAttribute(ln_t_split, cudaFuncAttributeMaxDynamicSharedMemorySize, LNT_SMEM);

#define SYM(p, s) do { void* _t; cudaGetSymbolAddress(&_t, s); p = (decltype(p))_t; } while (0)
    float *ab;
    __half *qkvh, *knvsh, *qnh, *wh, *oh, *p1h;
    __half *xh, *ih, *sh;
    __half *knTh, *knTl, *qnTh, *qnTl, *abh, *abl;
    __half *w3h, *w3l, *w2h, *w2l, *wqh, *wql, *wph, *wpl;
    SYM(ab, g_ab);
    SYM(qkvh, g_qkvh); SYM(knvsh, g_knvsh); SYM(qnh, g_qnh);
    SYM(wh, g_wh); SYM(oh, g_oh); SYM(p1h, g_p1h);
    SYM(xh, g_xh); SYM(ih, g_ih); SYM(sh, g_sh);
    SYM(knTh, g_knTh); SYM(knTl, g_knTl); SYM(qnTh, g_qnTh); SYM(qnTl, g_qnTl);
    SYM(abh, g_abh); SYM(abl, g_abl);
    SYM(w3h, g_w3h); SYM(w3l, g_w3l); SYM(w2h, g_w2h); SYM(w2l, g_w2l);
    SYM(wqh, g_wqh); SYM(wql, g_wql); SYM(wph, g_wph); SYM(wpl, g_wpl);

    dim3 tb(32, 8);
    dim3 tw(16, 16, 1);
    transpose_split<<<tw, tb>>>(Wq,     C_, 0, w3h,               w3l,               C_, 0);
    transpose_split<<<tw, tb>>>(Wk,     C_, 0, w3h + C_ * C_,     w3l + C_ * C_,     C_, 0);
    transpose_split<<<tw, tb>>>(Wv,     C_, 0, w3h + 2 * C_ * C_, w3l + 2 * C_ * C_, C_, 0);
    transpose_split<<<tw, tb>>>(Wk_sif, C_, 0, w2h,               w2l,               C_, 0);
    transpose_split<<<tw, tb>>>(Wv_sif, C_, 0, w2h + C_ * C_,     w2l + C_ * C_,     C_, 0);
    transpose_split<<<tw, tb>>>(Wq_sif, C_, 0, wqh,               wql,               C_, 0);
    transpose_split<<<tw, tb>>>(proj_w, C_, 0, wph,               wpl,               C_, 0);

    long n4 = (long)MTOT * C_ / 4;
    split_hi3<<<(unsigned)((n4 + 255) / 256), 256>>>(x, illu, sem, xh, ih, sh, n4);

    // GEMM1 (1-pass): qkv(fp16) = x @ [Wq|Wk|Wv]
    gemm_h<1><<<dim3(12, 256, 1), 256, 3 * 2 * TILE_B>>>(xh, nullptr, w3h, nullptr,
        nullptr, C_, C_, C_, 0, 0, 0, 0, nullptr, nullptr, 0, 0, 1.f,
        qkvh, 1536, 0, nullptr, 0, 0);
    // GEMM2 (1-pass): [kn|vs](fp16) = illu @ [Wk_sif|Wv_sif]
    gemm_h<1><<<dim3(8, 256, 1), 256, 3 * 2 * TILE_B>>>(ih, nullptr, w2h, nullptr,
        nullptr, C_, C_, C_, 0, 0, 0, 0, nullptr, nullptr, 0, 0, 1.f,
        knvsh, 1024, 0, nullptr, 0, 0);
    // GEMM3 (1-pass): qn(fp16) = sem @ Wq_sif
    gemm_h<1><<<dim3(4, 256, 1), 256, 3 * 2 * TILE_B>>>(sh, nullptr, wqh, nullptr,
        nullptr, C_, C_, C_, 0, 0, 0, 0, nullptr, nullptr, 0, 0, 1.f,
        qnh, 512, 0, nullptr, 0, 0);

    // fused LN + transpose + split
    ln_t_split<<<dim3(128, 8), 256, LNT_SMEM>>>(knvsh, 1024, (long)N_ * 1024,
        ln_g, ln_b, knTh, knTl, (long)C_ * N_);
    ln_t_split<<<dim3(128, 8), 256, LNT_SMEM>>>(qnh, 512, (long)N_ * 512,
        ln_g, ln_b, qnTh, qnTl, (long)C_ * N_);

    // GEMM4 (3-pass): Ab[b] = (Qn^T Kn)/sqrt(C)
    gemm_h<3><<<dim3(4, 4, 8), 256, 3 * 4 * TILE_B>>>(qnTh, qnTl, knTh, knTl,
        ab, N_, N_, N_, C_, (long)C_ * N_, (long)C_ * N_, (long)C_ * C_,
        nullptr, nullptr, 0, 0, 0.044194173824159216f, nullptr, 0, 0, nullptr, 0, 0);

    softmax_ab<<<B_ * C_, 128>>>(ab, abh, abl);

    // GEMM5 (1-pass): w(fp16) = (V@Ab^T + V) * v
    gemm_h<1><<<dim3(4, 32, 8), 256, 3 * 2 * TILE_B>>>(knvsh + 512, nullptr, abh, nullptr,
        nullptr, C_, 1024, C_, 0, (long)N_ * 1024, (long)C_ * C_, 0,
        nullptr, knvsh + 512, 1024, (long)N_ * 1024, 1.f,
        wh, 512, (long)N_ * C_, qkvh + 1024, 1536, (long)N_ * 1536);

    // FG-MSA
    msa_g<<<dim3(64, NSLICE), 256>>>();
    msa_soft<<<64 * 64, 64>>>(rescale);
    msa_o<<<dim3(64, NSLICE), 256>>>();

    // GEMM6 (2-pass): out = o @ proj_w + proj_b
    gemm_h<2><<<dim3(4, 256, 1), 256, 3 * 3 * TILE_B>>>(oh, nullptr, wph, wpl,
        out, C_, C_, C_, C_, 0, 0, 0, proj_b, nullptr, 0, 0, 1.f,
        nullptr, 0, 0, nullptr, 0, 0);

    // positional branch (fp16)
    dwconv3x3_h<true,  false><<<MTOT / 8, 128>>>(qkvh + 1024, 1536, dw1, nullptr, p1h);
    dwconv3x3_h<false, true ><<<MTOT / 8, 128>>>(p1h, 512, dw2, out, nullptr);
}

// round 11
// speedup vs baseline: 3.5127x; 1.1762x over previous
#include <cuda_runtime.h>
#include <cuda_fp16.h>
#include <math.h>
#include <stdint.h>

#define B_    8
#define C_    512
#define N_    4096
#define MTOT  32768
#define DH    64
#define NSLICE 16

// ---------------------------------------------------------------------------
// helpers (portable PTX only: cp.async, ldmatrix, mma.sync)
// ---------------------------------------------------------------------------
__device__ __forceinline__ uint32_t smem_u32(const void* p) {
    uint32_t a;
    asm("{ .reg .u64 t; cvta.to.shared.u64 t, %1; cvt.u32.u64 %0, t; }" : "=r"(a) : "l"(p));
    return a;
}
__device__ __forceinline__ void cp_async16(uint32_t dst, const void* src) {
    asm volatile("cp.async.cg.shared.global [%0], [%1], 16;" :: "r"(dst), "l"(src));
}
#define CP_COMMIT() asm volatile("cp.async.commit_group;" ::: "memory")
#define CP_WAIT(n)  asm volatile("cp.async.wait_group %0;" :: "n"(n) : "memory")

#define LDSM_X4(r, a)                                                          \
    asm volatile("ldmatrix.sync.aligned.m8n8.x4.shared.b16 {%0,%1,%2,%3},[%4];"\
        : "=r"((r)[0]), "=r"((r)[1]), "=r"((r)[2]), "=r"((r)[3]) : "r"(a))

__device__ __forceinline__ void mma16816(float* d, const uint32_t* a, const uint32_t* b) {
    asm volatile("mma.sync.aligned.m16n8k16.row.col.f32.f16.f16.f32 "
        "{%0,%1,%2,%3},{%4,%5,%6,%7},{%8,%9},{%0,%1,%2,%3};"
        : "+f"(d[0]), "+f"(d[1]), "+f"(d[2]), "+f"(d[3])
        : "r"(a[0]), "r"(a[1]), "r"(a[2]), "r"(a[3]), "r"(b[0]), "r"(b[1]));
}

// ---------------------------------------------------------------------------
// scratch
// ---------------------------------------------------------------------------
__device__ __half g_qkvh [MTOT * 1536];   // q|k|v
__device__ __half g_knvsh[MTOT * 1024];   // kn|vs
__device__ __half g_qnh  [MTOT * C_];
__device__ __half g_wh   [MTOT * C_];     // v * prior
__device__ __half g_oh   [MTOT * C_];
__device__ __half g_p1h  [MTOT * C_];
__device__ __half g_p2h  [MTOT * C_];
__device__ float  g_ab   [B_ * C_ * C_];
__device__ __half g_xh [MTOT * C_];
__device__ __half g_ih [MTOT * C_];
__device__ __half g_sh [MTOT * C_];
__device__ __half g_knTh[B_ * C_ * N_], g_knTl[B_ * C_ * N_];
__device__ __half g_qnTh[B_ * C_ * N_], g_qnTl[B_ * C_ * N_];
__device__ __half g_abh[B_ * C_ * C_],  g_abl[B_ * C_ * C_];
__device__ __half g_w3h[1536 * C_], g_w3l[1536 * C_];
__device__ __half g_w2h[1024 * C_], g_w2l[1024 * C_];
__device__ __half g_wqh[C_ * C_],   g_wql[C_ * C_];
__device__ __half g_wph[C_ * C_],   g_wpl[C_ * C_];
__device__ float g_Gp [NSLICE * 64 * 64 * 64];
__device__ float g_nkp[NSLICE * 64 * 64];
__device__ float g_nqp[NSLICE * 64 * 64];
__device__ float g_attn[64 * 64 * 64];

// ---------------------------------------------------------------------------
// HMMA GEMM, PASSES = 1 (AhBh), 2 (+AhBl), 3 (+AlBh).
// CTA 128x128, BK=32, 8 warps, 3-stage cp.async, 80B-padded smem rows.
// MINB: min blocks/SM hint (2 for small smem variants -> 2 CTAs/SM).
// epilogue: v = acc*alpha (+bias)(+resH)(*vmulH) -> fp32 C and/or fp16 outH.
// ---------------------------------------------------------------------------
#define TILE_B   10240            // 128 rows * 80 B

template <int PASSES, int MINB>
__global__ __launch_bounds__(256, MINB) void gemm_h(
    const __half* __restrict__ Ah, const __half* __restrict__ Al,
    const __half* __restrict__ Bh, const __half* __restrict__ Bl,
    float* __restrict__ C, int K, int ldA, int ldB, int ldC,
    long sA, long sB, long sC,
    const float* __restrict__ bias,
    const __half* __restrict__ resH, int ldRes, long sRes,
    float alpha,
    __half* __restrict__ outH, int ldH, long sH,
    const __half* __restrict__ vmulH, int ldV, long sV)
{
    constexpr int NT = PASSES + 1;        // tiles per stage
    constexpr int STAGE_B = NT * TILE_B;
    extern __shared__ char smem[];
    const int m0 = blockIdx.y * 128, n0 = blockIdx.x * 128;
    Ah += blockIdx.z * sA;
    if (PASSES == 3) Al += blockIdx.z * sA;
    Bh += blockIdx.z * sB;
    if (PASSES >= 2) Bl += blockIdx.z * sB;
    if (C)     C     += blockIdx.z * sC;
    if (resH)  resH  += blockIdx.z * sRes;
    if (outH)  outH  += blockIdx.z * sH;
    if (vmulH) vmulH += blockIdx.z * sV;

    const int tid = threadIdx.x;
    const int wid = tid >> 5, lane = tid & 31;
    const int wm = (wid & 1) * 64;
    const int wn = (wid >> 1) * 32;
    const uint32_t sbase = smem_u32(smem);

    float acc[4][4][4];
#pragma unroll
    for (int i = 0; i < 4; i++)
#pragma unroll
        for (int j = 0; j < 4; j++)
#pragma unroll
            for (int p = 0; p < 4; p++) acc[i][j][p] = 0.f;

    const int KB = K >> 5;

#define STAGE_LOAD(kb, buf) do {                                               \
    int k0 = (kb) << 5;                                                        \
    uint32_t st = sbase + (buf) * STAGE_B;                                     \
    _Pragma("unroll")                                                          \
    for (int pos = 0; pos < 2; pos++) {                                        \
        int idx = tid + pos * 256;                                             \
        int r = idx >> 2, cc = idx & 3;                                        \
        uint32_t so = (uint32_t)(r * 80 + cc * 16);                            \
        long ga = (long)(m0 + r) * ldA + k0 + cc * 8;                          \
        long gb = (long)(n0 + r) * ldB + k0 + cc * 8;                          \
        cp_async16(st + so,          Ah + ga);                                 \
        cp_async16(st + TILE_B + so, Bh + gb);                                 \
        if (PASSES >= 2) cp_async16(st + 2 * TILE_B + so, Bl + gb);            \
        if (PASSES == 3) cp_async16(st + 3 * TILE_B + so, Al + ga);            \
    }                                                                          \
    CP_COMMIT();                                                               \
} while (0)

    STAGE_LOAD(0, 0);
    STAGE_LOAD(1, 1);

    const int lg = lane >> 3, lr = lane & 7;
    int cbuf = 0, lbuf = 2;

    for (int kb = 0; kb < KB; kb++) {
        if (kb + 1 < KB) CP_WAIT(1); else CP_WAIT(0);
        __syncthreads();
        if (kb + 2 < KB) STAGE_LOAD(kb + 2, lbuf);
        uint32_t st = sbase + cbuf * STAGE_B;

#pragma unroll
        for (int ks = 0; ks < 2; ks++) {
            const int cb = ks * 2;
            uint32_t ah[4][4], al[4][4], bh[4][2], bl[4][2];
#pragma unroll
            for (int mi = 0; mi < 4; mi++) {
                int row = wm + mi * 16 + lr + (lg & 1) * 8;
                int ch  = cb + (lg >> 1);
                uint32_t a = st + (uint32_t)(row * 80 + ch * 16);
                LDSM_X4(ah[mi], a);
                if (PASSES == 3) LDSM_X4(al[mi], a + 3 * TILE_B);
            }
#pragma unroll
            for (int np = 0; np < 2; np++) {
                int row = wn + np * 16 + lr + (lg >> 1) * 8;
                int ch  = cb + (lg & 1);
                uint32_t a = st + TILE_B + (uint32_t)(row * 80 + ch * 16);
                uint32_t t4[4];
                LDSM_X4(t4, a);
                bh[np * 2][0] = t4[0]; bh[np * 2][1] = t4[1];
                bh[np * 2 + 1][0] = t4[2]; bh[np * 2 + 1][1] = t4[3];
                if (PASSES >= 2) {
                    LDSM_X4(t4, a + TILE_B);
                    bl[np * 2][0] = t4[0]; bl[np * 2][1] = t4[1];
                    bl[np * 2 + 1][0] = t4[2]; bl[np * 2 + 1][1] = t4[3];
                }
            }
#pragma unroll
            for (int mi = 0; mi < 4; mi++)
#pragma unroll
                for (int nj = 0; nj < 4; nj++) {
                    mma16816(acc[mi][nj], ah[mi], bh[nj]);
                    if (PASSES >= 2) mma16816(acc[mi][nj], ah[mi], bl[nj]);
                    if (PASSES == 3) mma16816(acc[mi][nj], al[mi], bh[nj]);
                }
        }
        cbuf = (cbuf == 2) ? 0 : cbuf + 1;
        lbuf = (lbuf == 2) ? 0 : lbuf + 1;
    }

    const int er = lane >> 2, ec = (lane & 3) * 2;
#pragma unroll
    for (int mi = 0; mi < 4; mi++)
#pragma unroll
        for (int nj = 0; nj < 4; nj++) {
            int col = n0 + wn + nj * 8 + ec;
#pragma unroll
            for (int p = 0; p < 2; p++) {
                int row = m0 + wm + mi * 16 + er + p * 8;
                float2 v;
                v.x = acc[mi][nj][p * 2 + 0] * alpha;
                v.y = acc[mi][nj][p * 2 + 1] * alpha;
                if (bias) { v.x += bias[col]; v.y += bias[col + 1]; }
                if (resH) {
                    __half2 r2 = *(const __half2*)(resH + (long)row * ldRes + col);
                    v.x += __half2float(__low2half(r2));
                    v.y += __half2float(__high2half(r2));
                }
                if (vmulH) {
                    __half2 m2 = *(const __half2*)(vmulH + (long)row * ldV + col);
                    v.x *= __half2float(__low2half(m2));
                    v.y *= __half2float(__high2half(m2));
                }
                if (C) *(float2*)(C + (long)row * ldC + col) = v;
                if (outH)
                    *(__half2*)(outH + (long)row * ldH + col) =
                        __halves2half2(__float2half_rn(v.x), __float2half_rn(v.y));
            }
        }
}

// ---------------------------------------------------------------------------
// fused fp32 -> fp16 for x, illu, sem
// ---------------------------------------------------------------------------
__global__ void split_hi3(const float* __restrict__ a, const float* __restrict__ b,
                          const float* __restrict__ c,
                          __half* __restrict__ ha, __half* __restrict__ hb,
                          __half* __restrict__ hc, long n4)
{
    long i = ((long)blockIdx.x * blockDim.x + threadIdx.x);
    if (i >= n4) return;
    i *= 4;
    float4 va = *(const float4*)(a + i);
    float4 vb = *(const float4*)(b + i);
    float4 vc = *(const float4*)(c + i);
    *(__half2*)(ha + i)     = __halves2half2(__float2half_rn(va.x), __float2half_rn(va.y));
    *(__half2*)(ha + i + 2) = __halves2half2(__float2half_rn(va.z), __float2half_rn(va.w));
    *(__half2*)(hb + i)     = __halves2half2(__float2half_rn(vb.x), __float2half_rn(vb.y));
    *(__half2*)(hb + i + 2) = __halves2half2(__float2half_rn(vb.z), __float2half_rn(vb.w));
    *(__half2*)(hc + i)     = __halves2half2(__float2half_rn(vc.x), __float2half_rn(vc.y));
    *(__half2*)(hc + i + 2) = __halves2half2(__float2half_rn(vc.z), __float2half_rn(vc.w));
}

// ---------------------------------------------------------------------------
// transpose + split (weights): fp32 [R,C](ldIn) -> fp16 hi/lo [C,R](ldOut)
// ---------------------------------------------------------------------------
__global__ void transpose_split(const float* __restrict__ in, int ldIn, long sIn,
                                __half* __restrict__ oh, __half* __restrict__ ol,
                                int ldOut, long sOut)
{
    in += blockIdx.z * sIn; oh += blockIdx.z * sOut; ol += blockIdx.z * sOut;
    __shared__ float tile[32][33];
    int c0 = blockIdx.x * 32, r0 = blockIdx.y * 32;
    int tx = threadIdx.x, ty = threadIdx.y;
#pragma unroll
    for (int i = 0; i < 4; i++)
        tile[ty + 8 * i][tx] = in[(long)(r0 + ty + 8 * i) * ldIn + c0 + tx];
    __syncthreads();
#pragma unroll
    for (int i = 0; i < 4; i++) {
        float v = tile[tx][ty + 8 * i];
        __half hh = __float2half_rn(v);
        long o = (long)(c0 + ty + 8 * i) * ldOut + r0 + tx;
        oh[o] = hh;
        ol[o] = __float2half_rn(v - __half2float(hh));
    }
}

// ---------------------------------------------------------------------------
// FUSED: LayerNorm rows (512, fp16 in) + transpose + fp16 hi/lo split.
// ---------------------------------------------------------------------------
#define LDT 516
#define LNT_SMEM (32 * LDT * 4)   // 66048 B

__global__ __launch_bounds__(256) void ln_t_split(
    const __half* __restrict__ in, int ldIn, long sIn,
    const float* __restrict__ gg, const float* __restrict__ bb,
    __half* __restrict__ oh, __half* __restrict__ ol, long sOut)
{
    extern __shared__ float tile[];
    in += blockIdx.y * sIn; oh += blockIdx.y * sOut; ol += blockIdx.y * sOut;
    const int r0 = blockIdx.x * 32;
    const int t = threadIdx.x;

#pragma unroll
    for (int i = 0; i < 8; i++) {
        int lin = t + i * 256;
        int r = lin >> 6, c8 = (lin & 63) * 8;
        uint4 raw = *(const uint4*)(in + (long)(r0 + r) * ldIn + c8);
        const __half2* hp = (const __half2*)&raw;
        float* dst = &tile[r * LDT + c8];
#pragma unroll
        for (int j = 0; j < 4; j++) {
            dst[j * 2 + 0] = __half2float(__low2half(hp[j]));
            dst[j * 2 + 1] = __half2float(__high2half(hp[j]));
        }
    }
    __syncthreads();

    __shared__ float mu_s[32], inv_s[32];
    const int w = t >> 5, lane = t & 31;
#pragma unroll
    for (int rr = 0; rr < 4; rr++) {
        int r = w * 4 + rr;
        float s = 0.f, q = 0.f;
#pragma unroll
        for (int i = 0; i < 16; i++) {
            float v = tile[r * LDT + lane + i * 32];
            s += v; q += v * v;
        }
#pragma unroll
        for (int o = 16; o; o >>= 1) {
            s += __shfl_xor_sync(0xffffffffu, s, o);
            q += __shfl_xor_sync(0xffffffffu, q, o);
        }
        if (lane == 0) {
            float mu = s * (1.f / C_);
            mu_s[r]  = mu;
            inv_s[r] = rsqrtf(q * (1.f / C_) - mu * mu + 1e-5f);
        }
    }
    __syncthreads();

    const int r = t & 31, cg = t >> 5;
    const float mu = mu_s[r], inv = inv_s[r];
#pragma unroll 8
    for (int cc = 0; cc < 64; cc++) {
        int c = cc * 8 + cg;
        float v = (tile[r * LDT + c] - mu) * inv * gg[c] + bb[c];
        __half hh = __float2half_rn(v);
        long o = (long)c * N_ + r0 + r;
        oh[o] = hh;
        ol[o] = __float2half_rn(v - __half2float(hh));
    }
}

// ---------------------------------------------------------------------------
// SIF softmax rows -> fp16 hi/lo (row-major)
// ---------------------------------------------------------------------------
__global__ void softmax_ab(const float* __restrict__ Ab,
                           __half* __restrict__ oh, __half* __restrict__ ol)
{
    long bi = blockIdx.x;
    const float* row = Ab + bi * 512;
    int t = threadIdx.x;
    float4 v = *(const float4*)(row + t * 4);
    float m = fmaxf(fmaxf(v.x, v.y), fmaxf(v.z, v.w));
#pragma unroll
    for (int o = 16; o; o >>= 1) m = fmaxf(m, __shfl_xor_sync(0xffffffffu, m, o));
    __shared__ float rm[4], rs[4];
    if ((t & 31) == 0) rm[t >> 5] = m;
    __syncthreads();
    m = fmaxf(fmaxf(rm[0], rm[1]), fmaxf(rm[2], rm[3]));
    float4 e;
    e.x = expf(v.x - m); e.y = expf(v.y - m);
    e.z = expf(v.z - m); e.w = expf(v.w - m);
    float s = e.x + e.y + e.z + e.w;
#pragma unroll
    for (int o = 16; o; o >>= 1) s += __shfl_xor_sync(0xffffffffu, s, o);
    if ((t & 31) == 0) rs[t >> 5] = s;
    __syncthreads();
    s = rs[0] + rs[1] + rs[2] + rs[3];
    float inv = 1.f / s;
    e.x *= inv; e.y *= inv; e.z *= inv; e.w *= inv;
    long o = bi * 512 + t * 4;
    __half hx = __float2half_rn(e.x), hy = __float2half_rn(e.y);
    __half hz = __float2half_rn(e.z), hw = __float2half_rn(e.w);
    *(__half2*)(oh + o)     = __halves2half2(hx, hy);
    *(__half2*)(oh + o + 2) = __halves2half2(hz, hw);
    *(__half2*)(ol + o) = __halves2half2(
        __float2half_rn(e.x - __half2float(hx)),
        __float2half_rn(e.y - __half2float(hy)));
    *(__half2*)(ol + o + 2) = __halves2half2(
        __float2half_rn(e.z - __half2float(hz)),
        __float2half_rn(e.w - __half2float(hw)));
}

// ---------------------------------------------------------------------------
// FG-MSA (reads fp16 q,k from g_qkvh)
// ---------------------------------------------------------------------------
__global__ void msa_g()
{
    int bh = blockIdx.x, sl = blockIdx.y;
    int b = bh >> 3, h = bh & 7;
    const int NS = N_ / NSLICE;
    int n0 = sl * NS;
    __shared__ float ks[16][64];
    __shared__ float qs[16][64];
    int t = threadIdx.x;
    int ty = t >> 4, tx = t & 15;
    const __half* qb = g_qkvh + (long)b * N_ * 1536 + h * DH;
    const __half* kb = qb + 512;
    float acc[4][4];
#pragma unroll
    for (int i = 0; i < 4; i++)
#pragma unroll
        for (int j = 0; j < 4; j++) acc[i][j] = 0.f;
    float ssk = 0.f, ssq = 0.f;
    int lkk = t >> 4, lc4 = (t & 15) << 2;
    for (int nb = 0; nb < NS; nb += 16) {
        long roff = (long)(n0 + nb + lkk) * 1536 + lc4;
        {
            float2 rk = *(const float2*)(kb + roff);
            float2 rq = *(const float2*)(qb + roff);
            const __half2* pk = (const __half2*)&rk;
            const __half2* pq = (const __half2*)&rq;
            ks[lkk][lc4 + 0] = __half2float(__low2half(pk[0]));
            ks[lkk][lc4 + 1] = __half2float(__high2half(pk[0]));
            ks[lkk][lc4 + 2] = __half2float(__low2half(pk[1]));
            ks[lkk][lc4 + 3] = __half2float(__high2half(pk[1]));
            qs[lkk][lc4 + 0] = __half2float(__low2half(pq[0]));
            qs[lkk][lc4 + 1] = __half2float(__high2half(pq[0]));
            qs[lkk][lc4 + 2] = __half2float(__low2half(pq[1]));
            qs[lkk][lc4 + 3] = __half2float(__high2half(pq[1]));
        }
        __syncthreads();
#pragma unroll
        for (int kk = 0; kk < 16; kk++) {
            float a[4], bv[4];
#pragma unroll
            for (int i = 0; i < 4; i++) a[i] = ks[kk][ty * 4 + i];
#pragma unroll
            for (int j = 0; j < 4; j++) bv[j] = qs[kk][tx * 4 + j];
#pragma unroll
            for (int i = 0; i < 4; i++)
#pragma unroll
                for (int j = 0; j < 4; j++) acc[i][j] += a[i] * bv[j];
        }
        if (t < 64) {
#pragma unroll
            for (int kk = 0; kk < 16; kk++) {
                float kv = ks[kk][t], qv = qs[kk][t];
                ssk += kv * kv; ssq += qv * qv;
            }
        }
        __syncthreads();
    }
    float* Gb = g_Gp + ((long)sl * 64 + bh) * 4096;
#pragma unroll
    for (int i = 0; i < 4; i++)
#pragma unroll
        for (int j = 0; j < 4; j++)
            Gb[(ty * 4 + i) * 64 + tx * 4 + j] = acc[i][j];
    if (t < 64) {
        g_nkp[((long)sl * 64 + bh) * 64 + t] = ssk;
        g_nqp[((long)sl * 64 + bh) * 64 + t] = ssq;
    }
}

__global__ void msa_soft(const float* __restrict__ rescale)
{
    int r = blockIdx.x;
    int bh = r >> 6, d = r & 63, h = bh & 7;
    int t = threadIdx.x;
    float gsum = 0.f, nks = 0.f, nqs = 0.f;
#pragma unroll
    for (int sl = 0; sl < NSLICE; sl++) {
        gsum += g_Gp[((long)sl * 64 + bh) * 4096 + d * 64 + t];
        nks  += g_nkp[((long)sl * 64 + bh) * 64 + d];
        nqs  += g_nqp[((long)sl * 64 + bh) * 64 + t];
    }
    float nk = fmaxf(sqrtf(nks), 1e-12f);
    float nq = fmaxf(sqrtf(nqs), 1e-12f);
    float val = gsum * (rescale[h] / (nk * nq));
    float m = val;
#pragma unroll
    for (int o = 16; o; o >>= 1) m = fmaxf(m, __shfl_xor_sync(0xffffffffu, m, o));
    __shared__ float rm[2], rs[2];
    if ((t & 31) == 0) rm[t >> 5] = m;
    __syncthreads();
    m = fmaxf(rm[0], rm[1]);
    float e = expf(val - m);
    float s = e;
#pragma unroll
    for (int o = 16; o; o >>= 1) s += __shfl_xor_sync(0xffffffffu, s, o);
    if ((t & 31) == 0) rs[t >> 5] = s;
    __syncthreads();
    s = rs[0] + rs[1];
    g_attn[(long)bh * 4096 + d * 64 + t] = e / s;
}

__global__ void msa_o()
{
    int bh = blockIdx.x;
    int b = bh >> 3, h = bh & 7;
    int n0 = blockIdx.y * (N_ / NSLICE);
    __shared__ float at[64][65];
    __shared__ float vg[16][64];
    int t = threadIdx.x;
#pragma unroll
    for (int l = 0; l < 16; l++) {
        int idx = l * 256 + t;
        at[idx >> 6][idx & 63] = g_attn[(long)bh * 4096 + idx];
    }
    __syncthreads();
    const __half* wb = g_wh + (long)b * N_ * C_ + h * DH;
    long obase = (long)b * N_ * C_ + h * DH;
    int lkk = t >> 4, lc4 = (t & 15) << 2;
    int ty = t >> 4, tx = t & 15;
    for (int nb = 0; nb < 256; nb += 16) {
        {
            long rv = (long)(n0 + nb + lkk) * C_ + lc4;
            float2 raw = *(const float2*)(wb + rv);
            const __half2* hp = (const __half2*)&raw;
            vg[lkk][lc4 + 0] = __half2float(__low2half(hp[0]));
            vg[lkk][lc4 + 1] = __half2float(__high2half(hp[0]));
            vg[lkk][lc4 + 2] = __half2float(__low2half(hp[1]));
            vg[lkk][lc4 + 3] = __half2float(__high2half(hp[1]));
        }
        __syncthreads();
        float s0 = 0.f, s1 = 0.f, s2 = 0.f, s3 = 0.f;
#pragma unroll
        for (int e = 0; e < 64; e++) {
            float vv = vg[ty][e];
            s0 += at[tx * 4 + 0][e] * vv;
            s1 += at[tx * 4 + 1][e] * vv;
            s2 += at[tx * 4 + 2][e] * vv;
            s3 += at[tx * 4 + 3][e] * vv;
        }
        long off = obase + (long)(n0 + nb + ty) * C_ + tx * 4;
        *(__half2*)(g_oh + off)     = __halves2half2(__float2half_rn(s0), __float2half_rn(s1));
        *(__half2*)(g_oh + off + 2) = __halves2half2(__float2half_rn(s2), __float2half_rn(s3));
        __syncthreads();
    }
}

// ---------------------------------------------------------------------------
// depthwise conv (fp16 in, fp16 out)
// ---------------------------------------------------------------------------
__device__ __forceinline__ float gelu_exact(float x)
{
    return 0.5f * x * (1.f + erff(x * 0.70710678118654752f));
}

template <bool GELU>
__global__ void dwconv3x3_h(const __half* __restrict__ in, int ldIn,
                            const float* __restrict__ w,
                            __half* __restrict__ outHn)
{
    int t = threadIdx.x;
    int c = t * 4;
    float wr[3][3][4];
#pragma unroll
    for (int ky = 0; ky < 3; ky++)
#pragma unroll
        for (int kx = 0; kx < 3; kx++)
#pragma unroll
            for (int i = 0; i < 4; i++)
                wr[ky][kx][i] = w[(long)(c + i) * 9 + ky * 3 + kx];
    long p0 = (long)blockIdx.x * 8;
    int b = (int)(p0 >> 12);
    int yx0 = (int)(p0 & 4095);
#pragma unroll
    for (int px = 0; px < 8; px++) {
        int yx = yx0 + px;
        int y = yx >> 6, x = yx & 63;
        float ax = 0.f, ay = 0.f, az = 0.f, aw = 0.f;
#pragma unroll
        for (int ky = 0; ky < 3; ky++) {
            int yy = y + ky - 1;
            if (yy < 0 || yy > 63) continue;
#pragma unroll
            for (int kx = 0; kx < 3; kx++) {
                int xx = x + kx - 1;
                if (xx < 0 || xx > 63) continue;
                float2 raw = *(const float2*)(in + ((long)(b << 12) + (yy << 6) + xx) * ldIn + c);
                const __half2* hp = (const __half2*)&raw;
                ax += __half2float(__low2half(hp[0]))  * wr[ky][kx][0];
                ay += __half2float(__high2half(hp[0])) * wr[ky][kx][1];
                az += __half2float(__low2half(hp[1]))  * wr[ky][kx][2];
                aw += __half2float(__high2half(hp[1])) * wr[ky][kx][3];
            }
        }
        if (GELU) {
            ax = gelu_exact(ax); ay = gelu_exact(ay);
            az = gelu_exact(az); aw = gelu_exact(aw);
        }
        long off = ((long)(b << 12) + yx) * C_ + c;
        *(__half2*)(outHn + off)     = __halves2half2(__float2half_rn(ax), __float2half_rn(ay));
        *(__half2*)(outHn + off + 2) = __halves2half2(__float2half_rn(az), __float2half_rn(aw));
    }
}

// ---------------------------------------------------------------------------
// host
// ---------------------------------------------------------------------------
extern "C" void kernel_launch(void* const* d_in, const int* in_sizes, int n_in,
                              void* d_out, int out_size)
{
    const float* x       = (const float*)d_in[0];
    const float* illu    = (const float*)d_in[1];
    const float* sem     = (const float*)d_in[2];
    const float* Wk_sif  = (const float*)d_in[3];
    const float* Wq_sif  = (const float*)d_in[4];
    const float* Wv_sif  = (const float*)d_in[5];
    const float* ln_g    = (const float*)d_in[6];
    const float* ln_b    = (const float*)d_in[7];
    const float* Wq      = (const float*)d_in[8];
    const float* Wk      = (const float*)d_in[9];
    const float* Wv      = (const float*)d_in[10];
    const float* rescale = (const float*)d_in[11];
    const float* proj_w  = (const float*)d_in[12];
    const float* proj_b  = (const float*)d_in[13];
    const float* dw1     = (const float*)d_in[14];
    const float* dw2     = (const float*)d_in[15];
    float* out = (float*)d_out;

    cudaFuncSetAttribute((const void*)gemm_h<1, 2>, cudaFuncAttributeMaxDynamicSharedMemorySize, 3 * 2 * TILE_B);
    cudaFuncSetAttribute((const void*)gemm_h<2, 2>, cudaFuncAttributeMaxDynamicSharedMemorySize, 3 * 3 * TILE_B);
    cudaFuncSetAttribute((const void*)gemm_h<3, 1>, cudaFuncAttributeMaxDynamicSharedMemorySize, 3 * 4 * TILE_B);
    cudaFuncSetAttribute((const void*)ln_t_split, cudaFuncAttributeMaxDynamicSharedMemorySize, LNT_SMEM);

#define SYM(p, s) do { void* _t; cudaGetSymbolAddress(&_t, s); p = (decltype(p))_t; } while (0)
    float *ab;
    __half *qkvh, *knvsh, *qnh, *wh, *oh, *p1h, *p2h;
    __half *xh, *ih, *sh;
    __half *knTh, *knTl, *qnTh, *qnTl, *abh, *abl;
    __half *w3h, *w3l, *w2h, *w2l, *wqh, *wql, *wph, *wpl;
    SYM(ab, g_ab);
    SYM(qkvh, g_qkvh); SYM(knvsh, g_knvsh); SYM(qnh, g_qnh);
    SYM(wh, g_wh); SYM(oh, g_oh); SYM(p1h, g_p1h); SYM(p2h, g_p2h);
    SYM(xh, g_xh); SYM(ih, g_ih); SYM(sh, g_sh);
    SYM(knTh, g_knTh); SYM(knTl, g_knTl); SYM(qnTh, g_qnTh); SYM(qnTl, g_qnTl);
    SYM(abh, g_abh); SYM(abl, g_abl);
    SYM(w3h, g_w3h); SYM(w3l, g_w3l); SYM(w2h, g_w2h); SYM(w2l, g_w2l);
    SYM(wqh, g_wqh); SYM(wql, g_wql); SYM(wph, g_wph); SYM(wpl, g_wpl);

    dim3 tb(32, 8);
    dim3 tw(16, 16, 1);
    transpose_split<<<tw, tb>>>(Wq,     C_, 0, w3h,               w3l,               C_, 0);
    transpose_split<<<tw, tb>>>(Wk,     C_, 0, w3h + C_ * C_,     w3l + C_ * C_,     C_, 0);
    transpose_split<<<tw, tb>>>(Wv,     C_, 0, w3h + 2 * C_ * C_, w3l + 2 * C_ * C_, C_, 0);
    transpose_split<<<tw, tb>>>(Wk_sif, C_, 0, w2h,               w2l,               C_, 0);
    transpose_split<<<tw, tb>>>(Wv_sif, C_, 0, w2h + C_ * C_,     w2l + C_ * C_,     C_, 0);
    transpose_split<<<tw, tb>>>(Wq_sif, C_, 0, wqh,               wql,               C_, 0);
    transpose_split<<<tw, tb>>>(proj_w, C_, 0, wph,               wpl,               C_, 0);

    long n4 = (long)MTOT * C_ / 4;
    split_hi3<<<(unsigned)((n4 + 255) / 256), 256>>>(x, illu, sem, xh, ih, sh, n4);

    // GEMM1 (1-pass): qkv(fp16) = x @ [Wq|Wk|Wv]
    gemm_h<1, 2><<<dim3(12, 256, 1), 256, 3 * 2 * TILE_B>>>(xh, nullptr, w3h, nullptr,
        nullptr, C_, C_, C_, 0, 0, 0, 0, nullptr, nullptr, 0, 0, 1.f,
        qkvh, 1536, 0, nullptr, 0, 0);
    // GEMM2 (1-pass): [kn|vs](fp16) = illu @ [Wk_sif|Wv_sif]
    gemm_h<1, 2><<<dim3(8, 256, 1), 256, 3 * 2 * TILE_B>>>(ih, nullptr, w2h, nullptr,
        nullptr, C_, C_, C_, 0, 0, 0, 0, nullptr, nullptr, 0, 0, 1.f,
        knvsh, 1024, 0, nullptr, 0, 0);
    // GEMM3 (1-pass): qn(fp16) = sem @ Wq_sif
    gemm_h<1, 2><<<dim3(4, 256, 1), 256, 3 * 2 * TILE_B>>>(sh, nullptr, wqh, nullptr,
        nullptr, C_, C_, C_, 0, 0, 0, 0, nullptr, nullptr, 0, 0, 1.f,
        qnh, 512, 0, nullptr, 0, 0);

    // positional branch (independent of SIF/MSA; result consumed by GEMM6 epilogue)
    dwconv3x3_h<true ><<<MTOT / 8, 128>>>(qkvh + 1024, 1536, dw1, p1h);
    dwconv3x3_h<false><<<MTOT / 8, 128>>>(p1h, 512, dw2, p2h);

    // fused LN + transpose + split
    ln_t_split<<<dim3(128, 8), 256, LNT_SMEM>>>(knvsh, 1024, (long)N_ * 1024,
        ln_g, ln_b, knTh, knTl, (long)C_ * N_);
    ln_t_split<<<dim3(128, 8), 256, LNT_SMEM>>>(qnh, 512, (long)N_ * 512,
        ln_g, ln_b, qnTh, qnTl, (long)C_ * N_);

    // GEMM4 (3-pass): Ab[b] = (Qn^T Kn)/sqrt(C)
    gemm_h<3, 1><<<dim3(4, 4, 8), 256, 3 * 4 * TILE_B>>>(qnTh, qnTl, knTh, knTl,
        ab, N_, N_, N_, C_, (long)C_ * N_, (long)C_ * N_, (long)C_ * C_,
        nullptr, nullptr, 0, 0, 0.044194173824159216f, nullptr, 0, 0, nullptr, 0, 0);

    softmax_ab<<<B_ * C_, 128>>>(ab, abh, abl);

    // GEMM5 (1-pass): w(fp16) = (V@Ab^T + V) * v
    gemm_h<1, 2><<<dim3(4, 32, 8), 256, 3 * 2 * TILE_B>>>(knvsh + 512, nullptr, abh, nullptr,
        nullptr, C_, 1024, C_, 0, (long)N_ * 1024, (long)C_ * C_, 0,
        nullptr, knvsh + 512, 1024, (long)N_ * 1024, 1.f,
        wh, 512, (long)N_ * C_, qkvh + 1024, 1536, (long)N_ * 1536);

    // FG-MSA
    msa_g<<<dim3(64, NSLICE), 256>>>();
    msa_soft<<<64 * 64, 64>>>(rescale);
    msa_o<<<dim3(64, NSLICE), 256>>>();

    // GEMM6 (2-pass): out = o @ proj_w + proj_b + p2  (positional branch fused)
    gemm_h<2, 2><<<dim3(4, 256, 1), 256, 3 * 3 * TILE_B>>>(oh, nullptr, wph, wpl,
        out, C_, C_, C_, C_, 0, 0, 0, proj_b, p2h, C_, 0, 1.f,
        nullptr, 0, 0, nullptr, 0, 0);
}

// round 12
// speedup vs baseline: 3.9106x; 1.1133x over previous
#include <cuda_runtime.h>
#include <cuda_fp16.h>
#include <math.h>
#include <stdint.h>

#define B_    8
#define C_    512
#define N_    4096
#define MTOT  32768
#define DH    64
#define NSLICE 16

// ---------------------------------------------------------------------------
// helpers (portable PTX only: cp.async, ldmatrix, mma.sync)
// ---------------------------------------------------------------------------
__device__ __forceinline__ uint32_t smem_u32(const void* p) {
    uint32_t a;
    asm("{ .reg .u64 t; cvta.to.shared.u64 t, %1; cvt.u32.u64 %0, t; }" : "=r"(a) : "l"(p));
    return a;
}
__device__ __forceinline__ void cp_async16(uint32_t dst, const void* src) {
    asm volatile("cp.async.cg.shared.global [%0], [%1], 16;" :: "r"(dst), "l"(src));
}
#define CP_COMMIT() asm volatile("cp.async.commit_group;" ::: "memory")
#define CP_WAIT(n)  asm volatile("cp.async.wait_group %0;" :: "n"(n) : "memory")

#define LDSM_X4(r, a)                                                          \
    asm volatile("ldmatrix.sync.aligned.m8n8.x4.shared.b16 {%0,%1,%2,%3},[%4];"\
        : "=r"((r)[0]), "=r"((r)[1]), "=r"((r)[2]), "=r"((r)[3]) : "r"(a))

__device__ __forceinline__ void mma16816(float* d, const uint32_t* a, const uint32_t* b) {
    asm volatile("mma.sync.aligned.m16n8k16.row.col.f32.f16.f16.f32 "
        "{%0,%1,%2,%3},{%4,%5,%6,%7},{%8,%9},{%0,%1,%2,%3};"
        : "+f"(d[0]), "+f"(d[1]), "+f"(d[2]), "+f"(d[3])
        : "r"(a[0]), "r"(a[1]), "r"(a[2]), "r"(a[3]), "r"(b[0]), "r"(b[1]));
}

// ---------------------------------------------------------------------------
// scratch
// ---------------------------------------------------------------------------
__device__ __half g_qkvh [MTOT * 1536];   // q|k|v
__device__ __half g_knvsh[MTOT * 1024];   // kn|vs
__device__ __half g_qnh  [MTOT * C_];
__device__ __half g_wh   [MTOT * C_];     // v * prior
__device__ __half g_oh   [MTOT * C_];
__device__ __half g_p1h  [MTOT * C_];
__device__ __half g_p2h  [MTOT * C_];
__device__ float  g_ab   [B_ * C_ * C_];
__device__ __half g_xh [MTOT * C_];
__device__ __half g_ih [MTOT * C_];
__device__ __half g_sh [MTOT * C_];
__device__ __half g_knTh[B_ * C_ * N_], g_knTl[B_ * C_ * N_];
__device__ __half g_qnTh[B_ * C_ * N_], g_qnTl[B_ * C_ * N_];
__device__ __half g_abh[B_ * C_ * C_],  g_abl[B_ * C_ * C_];
__device__ __half g_w3h[1536 * C_], g_w3l[1536 * C_];
__device__ __half g_w2h[1024 * C_], g_w2l[1024 * C_];
__device__ __half g_wqh[C_ * C_],   g_wql[C_ * C_];
__device__ __half g_wph[C_ * C_],   g_wpl[C_ * C_];
__device__ float g_Gp [NSLICE * 64 * 64 * 64];
__device__ float g_nkp[NSLICE * 64 * 64];
__device__ float g_nqp[NSLICE * 64 * 64];
__device__ __half g_attnh[64 * 64 * 64];
__device__ __half g_attnl[64 * 64 * 64];

// ---------------------------------------------------------------------------
// HMMA GEMM, PASSES = 1 (AhBh), 2 (+AhBl), 3 (+AlBh).
// CTA 128x128, BK=32, 8 warps, 3-stage cp.async, 80B-padded smem rows.
// ---------------------------------------------------------------------------
#define TILE_B   10240            // 128 rows * 80 B

template <int PASSES, int MINB>
__global__ __launch_bounds__(256, MINB) void gemm_h(
    const __half* __restrict__ Ah, const __half* __restrict__ Al,
    const __half* __restrict__ Bh, const __half* __restrict__ Bl,
    float* __restrict__ C, int K, int ldA, int ldB, int ldC,
    long sA, long sB, long sC,
    const float* __restrict__ bias,
    const __half* __restrict__ resH, int ldRes, long sRes,
    float alpha,
    __half* __restrict__ outH, int ldH, long sH,
    const __half* __restrict__ vmulH, int ldV, long sV)
{
    constexpr int NT = PASSES + 1;        // tiles per stage
    constexpr int STAGE_B = NT * TILE_B;
    extern __shared__ char smem[];
    const int m0 = blockIdx.y * 128, n0 = blockIdx.x * 128;
    Ah += blockIdx.z * sA;
    if (PASSES == 3) Al += blockIdx.z * sA;
    Bh += blockIdx.z * sB;
    if (PASSES >= 2) Bl += blockIdx.z * sB;
    if (C)     C     += blockIdx.z * sC;
    if (resH)  resH  += blockIdx.z * sRes;
    if (outH)  outH  += blockIdx.z * sH;
    if (vmulH) vmulH += blockIdx.z * sV;

    const int tid = threadIdx.x;
    const int wid = tid >> 5, lane = tid & 31;
    const int wm = (wid & 1) * 64;
    const int wn = (wid >> 1) * 32;
    const uint32_t sbase = smem_u32(smem);

    float acc[4][4][4];
#pragma unroll
    for (int i = 0; i < 4; i++)
#pragma unroll
        for (int j = 0; j < 4; j++)
#pragma unroll
            for (int p = 0; p < 4; p++) acc[i][j][p] = 0.f;

    const int KB = K >> 5;

#define STAGE_LOAD(kb, buf) do {                                               \
    int k0 = (kb) << 5;                                                        \
    uint32_t st = sbase + (buf) * STAGE_B;                                     \
    _Pragma("unroll")                                                          \
    for (int pos = 0; pos < 2; pos++) {                                        \
        int idx = tid + pos * 256;                                             \
        int r = idx >> 2, cc = idx & 3;                                        \
        uint32_t so = (uint32_t)(r * 80 + cc * 16);                            \
        long ga = (long)(m0 + r) * ldA + k0 + cc * 8;                          \
        long gb = (long)(n0 + r) * ldB + k0 + cc * 8;                          \
        cp_async16(st + so,          Ah + ga);                                 \
        cp_async16(st + TILE_B + so, Bh + gb);                                 \
        if (PASSES >= 2) cp_async16(st + 2 * TILE_B + so, Bl + gb);            \
        if (PASSES == 3) cp_async16(st + 3 * TILE_B + so, Al + ga);            \
    }                                                                          \
    CP_COMMIT();                                                               \
} while (0)

    STAGE_LOAD(0, 0);
    STAGE_LOAD(1, 1);

    const int lg = lane >> 3, lr = lane & 7;
    int cbuf = 0, lbuf = 2;

    for (int kb = 0; kb < KB; kb++) {
        if (kb + 1 < KB) CP_WAIT(1); else CP_WAIT(0);
        __syncthreads();
        if (kb + 2 < KB) STAGE_LOAD(kb + 2, lbuf);
        uint32_t st = sbase + cbuf * STAGE_B;

#pragma unroll
        for (int ks = 0; ks < 2; ks++) {
            const int cb = ks * 2;
            uint32_t ah[4][4], al[4][4], bh[4][2], bl[4][2];
#pragma unroll
            for (int mi = 0; mi < 4; mi++) {
                int row = wm + mi * 16 + lr + (lg & 1) * 8;
                int ch  = cb + (lg >> 1);
                uint32_t a = st + (uint32_t)(row * 80 + ch * 16);
                LDSM_X4(ah[mi], a);
                if (PASSES == 3) LDSM_X4(al[mi], a + 3 * TILE_B);
            }
#pragma unroll
            for (int np = 0; np < 2; np++) {
                int row = wn + np * 16 + lr + (lg >> 1) * 8;
                int ch  = cb + (lg & 1);
                uint32_t a = st + TILE_B + (uint32_t)(row * 80 + ch * 16);
                uint32_t t4[4];
                LDSM_X4(t4, a);
                bh[np * 2][0] = t4[0]; bh[np * 2][1] = t4[1];
                bh[np * 2 + 1][0] = t4[2]; bh[np * 2 + 1][1] = t4[3];
                if (PASSES >= 2) {
                    LDSM_X4(t4, a + TILE_B);
                    bl[np * 2][0] = t4[0]; bl[np * 2][1] = t4[1];
                    bl[np * 2 + 1][0] = t4[2]; bl[np * 2 + 1][1] = t4[3];
                }
            }
#pragma unroll
            for (int mi = 0; mi < 4; mi++)
#pragma unroll
                for (int nj = 0; nj < 4; nj++) {
                    mma16816(acc[mi][nj], ah[mi], bh[nj]);
                    if (PASSES >= 2) mma16816(acc[mi][nj], ah[mi], bl[nj]);
                    if (PASSES == 3) mma16816(acc[mi][nj], al[mi], bh[nj]);
                }
        }
        cbuf = (cbuf == 2) ? 0 : cbuf + 1;
        lbuf = (lbuf == 2) ? 0 : lbuf + 1;
    }

    const int er = lane >> 2, ec = (lane & 3) * 2;
#pragma unroll
    for (int mi = 0; mi < 4; mi++)
#pragma unroll
        for (int nj = 0; nj < 4; nj++) {
            int col = n0 + wn + nj * 8 + ec;
#pragma unroll
            for (int p = 0; p < 2; p++) {
                int row = m0 + wm + mi * 16 + er + p * 8;
                float2 v;
                v.x = acc[mi][nj][p * 2 + 0] * alpha;
                v.y = acc[mi][nj][p * 2 + 1] * alpha;
                if (bias) { v.x += bias[col]; v.y += bias[col + 1]; }
                if (resH) {
                    __half2 r2 = *(const __half2*)(resH + (long)row * ldRes + col);
                    v.x += __half2float(__low2half(r2));
                    v.y += __half2float(__high2half(r2));
                }
                if (vmulH) {
                    __half2 m2 = *(const __half2*)(vmulH + (long)row * ldV + col);
                    v.x *= __half2float(__low2half(m2));
                    v.y *= __half2float(__high2half(m2));
                }
                if (C) *(float2*)(C + (long)row * ldC + col) = v;
                if (outH)
                    *(__half2*)(outH + (long)row * ldH + col) =
                        __halves2half2(__float2half_rn(v.x), __float2half_rn(v.y));
            }
        }
}

// ---------------------------------------------------------------------------
// fused fp32 -> fp16 for x, illu, sem
// ---------------------------------------------------------------------------
__global__ void split_hi3(const float* __restrict__ a, const float* __restrict__ b,
                          const float* __restrict__ c,
                          __half* __restrict__ ha, __half* __restrict__ hb,
                          __half* __restrict__ hc, long n4)
{
    long i = ((long)blockIdx.x * blockDim.x + threadIdx.x);
    if (i >= n4) return;
    i *= 4;
    float4 va = *(const float4*)(a + i);
    float4 vb = *(const float4*)(b + i);
    float4 vc = *(const float4*)(c + i);
    *(__half2*)(ha + i)     = __halves2half2(__float2half_rn(va.x), __float2half_rn(va.y));
    *(__half2*)(ha + i + 2) = __halves2half2(__float2half_rn(va.z), __float2half_rn(va.w));
    *(__half2*)(hb + i)     = __halves2half2(__float2half_rn(vb.x), __float2half_rn(vb.y));
    *(__half2*)(hb + i + 2) = __halves2half2(__float2half_rn(vb.z), __float2half_rn(vb.w));
    *(__half2*)(hc + i)     = __halves2half2(__float2half_rn(vc.x), __float2half_rn(vc.y));
    *(__half2*)(hc + i + 2) = __halves2half2(__float2half_rn(vc.z), __float2half_rn(vc.w));
}

// ---------------------------------------------------------------------------
// transpose + split (weights): fp32 [R,C](ldIn) -> fp16 hi/lo [C,R](ldOut)
// ---------------------------------------------------------------------------
__global__ void transpose_split(const float* __restrict__ in, int ldIn, long sIn,
                                __half* __restrict__ oh, __half* __restrict__ ol,
                                int ldOut, long sOut)
{
    in += blockIdx.z * sIn; oh += blockIdx.z * sOut; ol += blockIdx.z * sOut;
    __shared__ float tile[32][33];
    int c0 = blockIdx.x * 32, r0 = blockIdx.y * 32;
    int tx = threadIdx.x, ty = threadIdx.y;
#pragma unroll
    for (int i = 0; i < 4; i++)
        tile[ty + 8 * i][tx] = in[(long)(r0 + ty + 8 * i) * ldIn + c0 + tx];
    __syncthreads();
#pragma unroll
    for (int i = 0; i < 4; i++) {
        float v = tile[tx][ty + 8 * i];
        __half hh = __float2half_rn(v);
        long o = (long)(c0 + ty + 8 * i) * ldOut + r0 + tx;
        oh[o] = hh;
        ol[o] = __float2half_rn(v - __half2float(hh));
    }
}

// ---------------------------------------------------------------------------
// FUSED: LayerNorm rows (512, fp16 in) + transpose + fp16 hi/lo split.
// ---------------------------------------------------------------------------
#define LDT 516
#define LNT_SMEM (32 * LDT * 4)   // 66048 B

__global__ __launch_bounds__(256) void ln_t_split(
    const __half* __restrict__ in, int ldIn, long sIn,
    const float* __restrict__ gg, const float* __restrict__ bb,
    __half* __restrict__ oh, __half* __restrict__ ol, long sOut)
{
    extern __shared__ float tile[];
    in += blockIdx.y * sIn; oh += blockIdx.y * sOut; ol += blockIdx.y * sOut;
    const int r0 = blockIdx.x * 32;
    const int t = threadIdx.x;

#pragma unroll
    for (int i = 0; i < 8; i++) {
        int lin = t + i * 256;
        int r = lin >> 6, c8 = (lin & 63) * 8;
        uint4 raw = *(const uint4*)(in + (long)(r0 + r) * ldIn + c8);
        const __half2* hp = (const __half2*)&raw;
        float* dst = &tile[r * LDT + c8];
#pragma unroll
        for (int j = 0; j < 4; j++) {
            dst[j * 2 + 0] = __half2float(__low2half(hp[j]));
            dst[j * 2 + 1] = __half2float(__high2half(hp[j]));
        }
    }
    __syncthreads();

    __shared__ float mu_s[32], inv_s[32];
    const int w = t >> 5, lane = t & 31;
#pragma unroll
    for (int rr = 0; rr < 4; rr++) {
        int r = w * 4 + rr;
        float s = 0.f, q = 0.f;
#pragma unroll
        for (int i = 0; i < 16; i++) {
            float v = tile[r * LDT + lane + i * 32];
            s += v; q += v * v;
        }
#pragma unroll
        for (int o = 16; o; o >>= 1) {
            s += __shfl_xor_sync(0xffffffffu, s, o);
            q += __shfl_xor_sync(0xffffffffu, q, o);
        }
        if (lane == 0) {
            float mu = s * (1.f / C_);
            mu_s[r]  = mu;
            inv_s[r] = rsqrtf(q * (1.f / C_) - mu * mu + 1e-5f);
        }
    }
    __syncthreads();

    const int r = t & 31, cg = t >> 5;
    const float mu = mu_s[r], inv = inv_s[r];
#pragma unroll 8
    for (int cc = 0; cc < 64; cc++) {
        int c = cc * 8 + cg;
        float v = (tile[r * LDT + c] - mu) * inv * gg[c] + bb[c];
        __half hh = __float2half_rn(v);
        long o = (long)c * N_ + r0 + r;
        oh[o] = hh;
        ol[o] = __float2half_rn(v - __half2float(hh));
    }
}

// ---------------------------------------------------------------------------
// SIF softmax rows -> fp16 hi/lo (row-major)
// ---------------------------------------------------------------------------
__global__ void softmax_ab(const float* __restrict__ Ab,
                           __half* __restrict__ oh, __half* __restrict__ ol)
{
    long bi = blockIdx.x;
    const float* row = Ab + bi * 512;
    int t = threadIdx.x;
    float4 v = *(const float4*)(row + t * 4);
    float m = fmaxf(fmaxf(v.x, v.y), fmaxf(v.z, v.w));
#pragma unroll
    for (int o = 16; o; o >>= 1) m = fmaxf(m, __shfl_xor_sync(0xffffffffu, m, o));
    __shared__ float rm[4], rs[4];
    if ((t & 31) == 0) rm[t >> 5] = m;
    __syncthreads();
    m = fmaxf(fmaxf(rm[0], rm[1]), fmaxf(rm[2], rm[3]));
    float4 e;
    e.x = expf(v.x - m); e.y = expf(v.y - m);
    e.z = expf(v.z - m); e.w = expf(v.w - m);
    float s = e.x + e.y + e.z + e.w;
#pragma unroll
    for (int o = 16; o; o >>= 1) s += __shfl_xor_sync(0xffffffffu, s, o);
    if ((t & 31) == 0) rs[t >> 5] = s;
    __syncthreads();
    s = rs[0] + rs[1] + rs[2] + rs[3];
    float inv = 1.f / s;
    e.x *= inv; e.y *= inv; e.z *= inv; e.w *= inv;
    long o = bi * 512 + t * 4;
    __half hx = __float2half_rn(e.x), hy = __float2half_rn(e.y);
    __half hz = __float2half_rn(e.z), hw = __float2half_rn(e.w);
    *(__half2*)(oh + o)     = __halves2half2(hx, hy);
    *(__half2*)(oh + o + 2) = __halves2half2(hz, hw);
    *(__half2*)(ol + o) = __halves2half2(
        __float2half_rn(e.x - __half2float(hx)),
        __float2half_rn(e.y - __half2float(hy)));
    *(__half2*)(ol + o + 2) = __halves2half2(
        __float2half_rn(e.z - __half2float(hz)),
        __float2half_rn(e.w - __half2float(hw)));
}

// ---------------------------------------------------------------------------
// FG-MSA Gram (fp32 SIMT partials, reads fp16 q,k from g_qkvh)
// ---------------------------------------------------------------------------
__global__ void msa_g()
{
    int bh = blockIdx.x, sl = blockIdx.y;
    int b = bh >> 3, h = bh & 7;
    const int NS = N_ / NSLICE;
    int n0 = sl * NS;
    __shared__ float ks[16][64];
    __shared__ float qs[16][64];
    int t = threadIdx.x;
    int ty = t >> 4, tx = t & 15;
    const __half* qb = g_qkvh + (long)b * N_ * 1536 + h * DH;
    const __half* kb = qb + 512;
    float acc[4][4];
#pragma unroll
    for (int i = 0; i < 4; i++)
#pragma unroll
        for (int j = 0; j < 4; j++) acc[i][j] = 0.f;
    float ssk = 0.f, ssq = 0.f;
    int lkk = t >> 4, lc4 = (t & 15) << 2;
    for (int nb = 0; nb < NS; nb += 16) {
        long roff = (long)(n0 + nb + lkk) * 1536 + lc4;
        {
            float2 rk = *(const float2*)(kb + roff);
            float2 rq = *(const float2*)(qb + roff);
            const __half2* pk = (const __half2*)&rk;
            const __half2* pq = (const __half2*)&rq;
            ks[lkk][lc4 + 0] = __half2float(__low2half(pk[0]));
            ks[lkk][lc4 + 1] = __half2float(__high2half(pk[0]));
            ks[lkk][lc4 + 2] = __half2float(__low2half(pk[1]));
            ks[lkk][lc4 + 3] = __half2float(__high2half(pk[1]));
            qs[lkk][lc4 + 0] = __half2float(__low2half(pq[0]));
            qs[lkk][lc4 + 1] = __half2float(__high2half(pq[0]));
            qs[lkk][lc4 + 2] = __half2float(__low2half(pq[1]));
            qs[lkk][lc4 + 3] = __half2float(__high2half(pq[1]));
        }
        __syncthreads();
#pragma unroll
        for (int kk = 0; kk < 16; kk++) {
            float a[4], bv[4];
#pragma unroll
            for (int i = 0; i < 4; i++) a[i] = ks[kk][ty * 4 + i];
#pragma unroll
            for (int j = 0; j < 4; j++) bv[j] = qs[kk][tx * 4 + j];
#pragma unroll
            for (int i = 0; i < 4; i++)
#pragma unroll
                for (int j = 0; j < 4; j++) acc[i][j] += a[i] * bv[j];
        }
        if (t < 64) {
#pragma unroll
            for (int kk = 0; kk < 16; kk++) {
                float kv = ks[kk][t], qv = qs[kk][t];
                ssk += kv * kv; ssq += qv * qv;
            }
        }
        __syncthreads();
    }
    float* Gb = g_Gp + ((long)sl * 64 + bh) * 4096;
#pragma unroll
    for (int i = 0; i < 4; i++)
#pragma unroll
        for (int j = 0; j < 4; j++)
            Gb[(ty * 4 + i) * 64 + tx * 4 + j] = acc[i][j];
    if (t < 64) {
        g_nkp[((long)sl * 64 + bh) * 64 + t] = ssk;
        g_nqp[((long)sl * 64 + bh) * 64 + t] = ssq;
    }
}

// reduce partials + softmax -> attn fp16 hi/lo
__global__ void msa_soft(const float* __restrict__ rescale)
{
    int r = blockIdx.x;
    int bh = r >> 6, d = r & 63, h = bh & 7;
    int t = threadIdx.x;
    float gsum = 0.f, nks = 0.f, nqs = 0.f;
#pragma unroll
    for (int sl = 0; sl < NSLICE; sl++) {
        gsum += g_Gp[((long)sl * 64 + bh) * 4096 + d * 64 + t];
        nks  += g_nkp[((long)sl * 64 + bh) * 64 + d];
        nqs  += g_nqp[((long)sl * 64 + bh) * 64 + t];
    }
    float nk = fmaxf(sqrtf(nks), 1e-12f);
    float nq = fmaxf(sqrtf(nqs), 1e-12f);
    float val = gsum * (rescale[h] / (nk * nq));
    float m = val;
#pragma unroll
    for (int o = 16; o; o >>= 1) m = fmaxf(m, __shfl_xor_sync(0xffffffffu, m, o));
    __shared__ float rm[2], rs[2];
    if ((t & 31) == 0) rm[t >> 5] = m;
    __syncthreads();
    m = fmaxf(rm[0], rm[1]);
    float e = expf(val - m);
    float s = e;
#pragma unroll
    for (int o = 16; o; o >>= 1) s += __shfl_xor_sync(0xffffffffu, s, o);
    if ((t & 31) == 0) rs[t >> 5] = s;
    __syncthreads();
    s = rs[0] + rs[1];
    float v = e / s;
    __half hh = __float2half_rn(v);
    long o = (long)bh * 4096 + d * 64 + t;
    g_attnh[o] = hh;
    g_attnl[o] = __float2half_rn(v - __half2float(hh));
}

// ---------------------------------------------------------------------------
// HMMA msa_o: per (bh, m-tile) o[n, h*64+d] = sum_e w[n,e] attn[d,e]
// grid (32, 64), 256 thr; smem: w 128x64 (144B rows) + attn hi/lo 64x64.
// 2-pass B (attn hi + lo) keeps fp32-attn-equivalent precision.
// ---------------------------------------------------------------------------
#define MOW 144   // smem row stride (bytes)

__global__ __launch_bounds__(256, 2) void msa_o_hmma()
{
    __shared__ char sm[128 * MOW + 2 * 64 * MOW];   // 36864 B
    const int mt = blockIdx.x, bh = blockIdx.y;
    const int b = bh >> 3, h = bh & 7;
    const uint32_t sb = smem_u32(sm);
    const int tid = threadIdx.x;
    const int n0 = mt * 128;

    const __half* wb = g_wh + (long)b * N_ * C_ + h * DH;
    // load w tile: 128 rows x 8 chunks(16B)
#pragma unroll
    for (int i = 0; i < 4; i++) {
        int idx = tid + i * 256;
        int r = idx >> 3, cc = idx & 7;
        *(uint4*)(sm + r * MOW + cc * 16) =
            *(const uint4*)(wb + (long)(n0 + r) * C_ + cc * 8);
    }
    // load attn hi/lo: 64 rows x 8 chunks each
    const __half* ah_ = g_attnh + (long)bh * 4096;
    const __half* al_ = g_attnl + (long)bh * 4096;
#pragma unroll
    for (int i = 0; i < 2; i++) {
        int idx = tid + i * 256;
        int r = idx >> 3, cc = idx & 7;
        *(uint4*)(sm + 128 * MOW + r * MOW + cc * 16) =
            *(const uint4*)(ah_ + r * 64 + cc * 8);
        *(uint4*)(sm + 192 * MOW + r * MOW + cc * 16) =
            *(const uint4*)(al_ + r * 64 + cc * 8);
    }
    __syncthreads();

    const int wid = tid >> 5, lane = tid & 31;
    const int wm = wid * 16;
    const int lg = lane >> 3, lr = lane & 7;

    float acc[8][4];
#pragma unroll
    for (int j = 0; j < 8; j++)
#pragma unroll
        for (int p = 0; p < 4; p++) acc[j][p] = 0.f;

#pragma unroll
    for (int ks = 0; ks < 4; ks++) {
        const int cb = ks * 2;
        uint32_t a4[4], bhf[8][2], blf[8][2];
        {
            int row = wm + lr + (lg & 1) * 8;
            int ch  = cb + (lg >> 1);
            LDSM_X4(a4, sb + (uint32_t)(row * MOW + ch * 16));
        }
#pragma unroll
        for (int np = 0; np < 4; np++) {
            int row = np * 16 + lr + (lg >> 1) * 8;
            int ch  = cb + (lg & 1);
            uint32_t a = sb + (uint32_t)(128 * MOW + row * MOW + ch * 16);
            uint32_t t4[4];
            LDSM_X4(t4, a);
            bhf[np * 2][0] = t4[0]; bhf[np * 2][1] = t4[1];
            bhf[np * 2 + 1][0] = t4[2]; bhf[np * 2 + 1][1] = t4[3];
            LDSM_X4(t4, a + 64 * MOW);
            blf[np * 2][0] = t4[0]; blf[np * 2][1] = t4[1];
            blf[np * 2 + 1][0] = t4[2]; blf[np * 2 + 1][1] = t4[3];
        }
#pragma unroll
        for (int nj = 0; nj < 8; nj++) {
            mma16816(acc[nj], a4, bhf[nj]);
            mma16816(acc[nj], a4, blf[nj]);
        }
    }

    const int er = lane >> 2, ec = (lane & 3) * 2;
    const long obase = (long)b * N_ * C_ + h * DH;
#pragma unroll
    for (int nj = 0; nj < 8; nj++) {
        int d = nj * 8 + ec;
#pragma unroll
        for (int p = 0; p < 2; p++) {
            int row = n0 + wm + er + p * 8;
            *(__half2*)(g_oh + obase + (long)row * C_ + d) =
                __halves2half2(__float2half_rn(acc[nj][p * 2 + 0]),
                               __float2half_rn(acc[nj][p * 2 + 1]));
        }
    }
}

// ---------------------------------------------------------------------------
// depthwise conv (fp16 in, fp16 out)
// ---------------------------------------------------------------------------
__device__ __forceinline__ float gelu_exact(float x)
{
    return 0.5f * x * (1.f + erff(x * 0.70710678118654752f));
}

template <bool GELU>
__global__ void dwconv3x3_h(const __half* __restrict__ in, int ldIn,
                            const float* __restrict__ w,
                            __half* __restrict__ outHn)
{
    int t = threadIdx.x;
    int c = t * 4;
    float wr[3][3][4];
#pragma unroll
    for (int ky = 0; ky < 3; ky++)
#pragma unroll
        for (int kx = 0; kx < 3; kx++)
#pragma unroll
            for (int i = 0; i < 4; i++)
                wr[ky][kx][i] = w[(long)(c + i) * 9 + ky * 3 + kx];
    long p0 = (long)blockIdx.x * 8;
    int b = (int)(p0 >> 12);
    int yx0 = (int)(p0 & 4095);
#pragma unroll
    for (int px = 0; px < 8; px++) {
        int yx = yx0 + px;
        int y = yx >> 6, x = yx & 63;
        float ax = 0.f, ay = 0.f, az = 0.f, aw = 0.f;
#pragma unroll
        for (int ky = 0; ky < 3; ky++) {
            int yy = y + ky - 1;
            if (yy < 0 || yy > 63) continue;
#pragma unroll
            for (int kx = 0; kx < 3; kx++) {
                int xx = x + kx - 1;
                if (xx < 0 || xx > 63) continue;
                float2 raw = *(const float2*)(in + ((long)(b << 12) + (yy << 6) + xx) * ldIn + c);
                const __half2* hp = (const __half2*)&raw;
                ax += __half2float(__low2half(hp[0]))  * wr[ky][kx][0];
                ay += __half2float(__high2half(hp[0])) * wr[ky][kx][1];
                az += __half2float(__low2half(hp[1]))  * wr[ky][kx][2];
                aw += __half2float(__high2half(hp[1])) * wr[ky][kx][3];
            }
        }
        if (GELU) {
            ax = gelu_exact(ax); ay = gelu_exact(ay);
            az = gelu_exact(az); aw = gelu_exact(aw);
        }
        long off = ((long)(b << 12) + yx) * C_ + c;
        *(__half2*)(outHn + off)     = __halves2half2(__float2half_rn(ax), __float2half_rn(ay));
        *(__half2*)(outHn + off + 2) = __halves2half2(__float2half_rn(az), __float2half_rn(aw));
    }
}

// ---------------------------------------------------------------------------
// host
// ---------------------------------------------------------------------------
extern "C" void kernel_launch(void* const* d_in, const int* in_sizes, int n_in,
                              void* d_out, int out_size)
{
    const float* x       = (const float*)d_in[0];
    const float* illu    = (const float*)d_in[1];
    const float* sem     = (const float*)d_in[2];
    const float* Wk_sif  = (const float*)d_in[3];
    const float* Wq_sif  = (const float*)d_in[4];
    const float* Wv_sif  = (const float*)d_in[5];
    const float* ln_g    = (const float*)d_in[6];
    const float* ln_b    = (const float*)d_in[7];
    const float* Wq      = (const float*)d_in[8];
    const float* Wk      = (const float*)d_in[9];
    const float* Wv      = (const float*)d_in[10];
    const float* rescale = (const float*)d_in[11];
    const float* proj_w  = (const float*)d_in[12];
    const float* proj_b  = (const float*)d_in[13];
    const float* dw1     = (const float*)d_in[14];
    const float* dw2     = (const float*)d_in[15];
    float* out = (float*)d_out;

    cudaFuncSetAttribute((const void*)gemm_h<1, 2>, cudaFuncAttributeMaxDynamicSharedMemorySize, 3 * 2 * TILE_B);
    cudaFuncSetAttribute((const void*)gemm_h<2, 2>, cudaFuncAttributeMaxDynamicSharedMemorySize, 3 * 3 * TILE_B);
    cudaFuncSetAttribute((const void*)gemm_h<3, 1>, cudaFuncAttributeMaxDynamicSharedMemorySize, 3 * 4 * TILE_B);
    cudaFuncSetAttribute((const void*)ln_t_split, cudaFuncAttributeMaxDynamicSharedMemorySize, LNT_SMEM);

#define SYM(p, s) do { void* _t; cudaGetSymbolAddress(&_t, s); p = (decltype(p))_t; } while (0)
    float *ab;
    __half *qkvh, *knvsh, *qnh, *wh, *oh, *p1h, *p2h;
    __half *xh, *ih, *sh;
    __half *knTh, *knTl, *qnTh, *qnTl, *abh, *abl;
    __half *w3h, *w3l, *w2h, *w2l, *wqh, *wql, *wph, *wpl;
    SYM(ab, g_ab);
    SYM(qkvh, g_qkvh); SYM(knvsh, g_knvsh); SYM(qnh, g_qnh);
    SYM(wh, g_wh); SYM(oh, g_oh); SYM(p1h, g_p1h); SYM(p2h, g_p2h);
    SYM(xh, g_xh); SYM(ih, g_ih); SYM(sh, g_sh);
    SYM(knTh, g_knTh); SYM(knTl, g_knTl); SYM(qnTh, g_qnTh); SYM(qnTl, g_qnTl);
    SYM(abh, g_abh); SYM(abl, g_abl);
    SYM(w3h, g_w3h); SYM(w3l, g_w3l); SYM(w2h, g_w2h); SYM(w2l, g_w2l);
    SYM(wqh, g_wqh); SYM(wql, g_wql); SYM(wph, g_wph); SYM(wpl, g_wpl);

    dim3 tb(32, 8);
    dim3 tw(16, 16, 1);
    transpose_split<<<tw, tb>>>(Wq,     C_, 0, w3h,               w3l,               C_, 0);
    transpose_split<<<tw, tb>>>(Wk,     C_, 0, w3h + C_ * C_,     w3l + C_ * C_,     C_, 0);
    transpose_split<<<tw, tb>>>(Wv,     C_, 0, w3h + 2 * C_ * C_, w3l + 2 * C_ * C_, C_, 0);
    transpose_split<<<tw, tb>>>(Wk_sif, C_, 0, w2h,               w2l,               C_, 0);
    transpose_split<<<tw, tb>>>(Wv_sif, C_, 0, w2h + C_ * C_,     w2l + C_ * C_,     C_, 0);
    transpose_split<<<tw, tb>>>(Wq_sif, C_, 0, wqh,               wql,               C_, 0);
    transpose_split<<<tw, tb>>>(proj_w, C_, 0, wph,               wpl,               C_, 0);

    long n4 = (long)MTOT * C_ / 4;
    split_hi3<<<(unsigned)((n4 + 255) / 256), 256>>>(x, illu, sem, xh, ih, sh, n4);

    // GEMM1 (1-pass): qkv(fp16) = x @ [Wq|Wk|Wv]
    gemm_h<1, 2><<<dim3(12, 256, 1), 256, 3 * 2 * TILE_B>>>(xh, nullptr, w3h, nullptr,
        nullptr, C_, C_, C_, 0, 0, 0, 0, nullptr, nullptr, 0, 0, 1.f,
        qkvh, 1536, 0, nullptr, 0, 0);
    // GEMM2 (1-pass): [kn|vs](fp16) = illu @ [Wk_sif|Wv_sif]
    gemm_h<1, 2><<<dim3(8, 256, 1), 256, 3 * 2 * TILE_B>>>(ih, nullptr, w2h, nullptr,
        nullptr, C_, C_, C_, 0, 0, 0, 0, nullptr, nullptr, 0, 0, 1.f,
        knvsh, 1024, 0, nullptr, 0, 0);
    // GEMM3 (1-pass): qn(fp16) = sem @ Wq_sif
    gemm_h<1, 2><<<dim3(4, 256, 1), 256, 3 * 2 * TILE_B>>>(sh, nullptr, wqh, nullptr,
        nullptr, C_, C_, C_, 0, 0, 0, 0, nullptr, nullptr, 0, 0, 1.f,
        qnh, 512, 0, nullptr, 0, 0);

    // positional branch (independent; consumed by GEMM6 epilogue)
    dwconv3x3_h<true ><<<MTOT / 8, 128>>>(qkvh + 1024, 1536, dw1, p1h);
    dwconv3x3_h<false><<<MTOT / 8, 128>>>(p1h, 512, dw2, p2h);

    // fused LN + transpose + split
    ln_t_split<<<dim3(128, 8), 256, LNT_SMEM>>>(knvsh, 1024, (long)N_ * 1024,
        ln_g, ln_b, knTh, knTl, (long)C_ * N_);
    ln_t_split<<<dim3(128, 8), 256, LNT_SMEM>>>(qnh, 512, (long)N_ * 512,
        ln_g, ln_b, qnTh, qnTl, (long)C_ * N_);

    // GEMM4 (3-pass): Ab[b] = (Qn^T Kn)/sqrt(C)
    gemm_h<3, 1><<<dim3(4, 4, 8), 256, 3 * 4 * TILE_B>>>(qnTh, qnTl, knTh, knTl,
        ab, N_, N_, N_, C_, (long)C_ * N_, (long)C_ * N_, (long)C_ * C_,
        nullptr, nullptr, 0, 0, 0.044194173824159216f, nullptr, 0, 0, nullptr, 0, 0);

    softmax_ab<<<B_ * C_, 128>>>(ab, abh, abl);

    // GEMM5 (1-pass): w(fp16) = (V@Ab^T + V) * v
    gemm_h<1, 2><<<dim3(4, 32, 8), 256, 3 * 2 * TILE_B>>>(knvsh + 512, nullptr, abh, nullptr,
        nullptr, C_, 1024, C_, 0, (long)N_ * 1024, (long)C_ * C_, 0,
        nullptr, knvsh + 512, 1024, (long)N_ * 1024, 1.f,
        wh, 512, (long)N_ * C_, qkvh + 1024, 1536, (long)N_ * 1536);

    // FG-MSA
    msa_g<<<dim3(64, NSLICE), 256>>>();
    msa_soft<<<64 * 64, 64>>>(rescale);
    msa_o_hmma<<<dim3(32, 64), 256>>>();

    // GEMM6 (2-pass): out = o @ proj_w + proj_b + p2  (positional branch fused)
    gemm_h<2, 2><<<dim3(4, 256, 1), 256, 3 * 3 * TILE_B>>>(oh, nullptr, wph, wpl,
        out, C_, C_, C_, C_, 0, 0, 0, proj_b, p2h, C_, 0, 1.f,
        nullptr, 0, 0, nullptr, 0, 0);
}

// round 13
// speedup vs baseline: 4.0676x; 1.0402x over previous
#include <cuda_runtime.h>
#include <cuda_fp16.h>
#include <math.h>
#include <stdint.h>

#define B_    8
#define C_    512
#define N_    4096
#define MTOT  32768
#define DH    64
#define GSLICE 4

// ---------------------------------------------------------------------------
// helpers (portable PTX only: cp.async, ldmatrix, mma.sync)
// ---------------------------------------------------------------------------
__device__ __forceinline__ uint32_t smem_u32(const void* p) {
    uint32_t a;
    asm("{ .reg .u64 t; cvta.to.shared.u64 t, %1; cvt.u32.u64 %0, t; }" : "=r"(a) : "l"(p));
    return a;
}
__device__ __forceinline__ void cp_async16(uint32_t dst, const void* src) {
    asm volatile("cp.async.cg.shared.global [%0], [%1], 16;" :: "r"(dst), "l"(src));
}
#define CP_COMMIT() asm volatile("cp.async.commit_group;" ::: "memory")
#define CP_WAIT(n)  asm volatile("cp.async.wait_group %0;" :: "n"(n) : "memory")

#define LDSM_X4(r, a)                                                          \
    asm volatile("ldmatrix.sync.aligned.m8n8.x4.shared.b16 {%0,%1,%2,%3},[%4];"\
        : "=r"((r)[0]), "=r"((r)[1]), "=r"((r)[2]), "=r"((r)[3]) : "r"(a))

#define LDSM_X4_T(r, a)                                                        \
    asm volatile("ldmatrix.sync.aligned.m8n8.x4.trans.shared.b16 {%0,%1,%2,%3},[%4];"\
        : "=r"((r)[0]), "=r"((r)[1]), "=r"((r)[2]), "=r"((r)[3]) : "r"(a))

__device__ __forceinline__ void mma16816(float* d, const uint32_t* a, const uint32_t* b) {
    asm volatile("mma.sync.aligned.m16n8k16.row.col.f32.f16.f16.f32 "
        "{%0,%1,%2,%3},{%4,%5,%6,%7},{%8,%9},{%0,%1,%2,%3};"
        : "+f"(d[0]), "+f"(d[1]), "+f"(d[2]), "+f"(d[3])
        : "r"(a[0]), "r"(a[1]), "r"(a[2]), "r"(a[3]), "r"(b[0]), "r"(b[1]));
}

// ---------------------------------------------------------------------------
// scratch
// ---------------------------------------------------------------------------
__device__ __half g_qkvh [MTOT * 1536];   // q|k|v
__device__ __half g_knvsh[MTOT * 1024];   // kn|vs
__device__ __half g_qnh  [MTOT * C_];
__device__ __half g_wh   [MTOT * C_];     // v * prior
__device__ __half g_oh   [MTOT * C_];
__device__ __half g_p1h  [MTOT * C_];
__device__ __half g_p2h  [MTOT * C_];
__device__ float  g_ab   [B_ * C_ * C_];
__device__ __half g_xh [MTOT * C_];
__device__ __half g_ih [MTOT * C_];
__device__ __half g_sh [MTOT * C_];
__device__ __half g_knTh[B_ * C_ * N_], g_knTl[B_ * C_ * N_];
__device__ __half g_qnTh[B_ * C_ * N_], g_qnTl[B_ * C_ * N_];
__device__ __half g_abh[B_ * C_ * C_],  g_abl[B_ * C_ * C_];
__device__ __half g_w3h[1536 * C_], g_w3l[1536 * C_];
__device__ __half g_w2h[1024 * C_], g_w2l[1024 * C_];
__device__ __half g_wqh[C_ * C_],   g_wql[C_ * C_];
__device__ __half g_wph[C_ * C_],   g_wpl[C_ * C_];
__device__ float g_Gp [GSLICE * 64 * 64 * 64];
__device__ float g_nkp[GSLICE * 64 * 64];
__device__ float g_nqp[GSLICE * 64 * 64];
__device__ __half g_attnh[64 * 64 * 64];
__device__ __half g_attnl[64 * 64 * 64];

// ---------------------------------------------------------------------------
// HMMA GEMM, PASSES = 1 (AhBh), 2 (+AhBl), 3 (+AlBh).
// CTA 128x128, BK=32, 8 warps, 3-stage cp.async, 80B-padded smem rows.
// ---------------------------------------------------------------------------
#define TILE_B   10240            // 128 rows * 80 B

template <int PASSES, int MINB>
__global__ __launch_bounds__(256, MINB) void gemm_h(
    const __half* __restrict__ Ah, const __half* __restrict__ Al,
    const __half* __restrict__ Bh, const __half* __restrict__ Bl,
    float* __restrict__ C, int K, int ldA, int ldB, int ldC,
    long sA, long sB, long sC,
    const float* __restrict__ bias,
    const __half* __restrict__ resH, int ldRes, long sRes,
    float alpha,
    __half* __restrict__ outH, int ldH, long sH,
    const __half* __restrict__ vmulH, int ldV, long sV)
{
    constexpr int NT = PASSES + 1;        // tiles per stage
    constexpr int STAGE_B = NT * TILE_B;
    extern __shared__ char smem[];
    const int m0 = blockIdx.y * 128, n0 = blockIdx.x * 128;
    Ah += blockIdx.z * sA;
    if (PASSES == 3) Al += blockIdx.z * sA;
    Bh += blockIdx.z * sB;
    if (PASSES >= 2) Bl += blockIdx.z * sB;
    if (C)     C     += blockIdx.z * sC;
    if (resH)  resH  += blockIdx.z * sRes;
    if (outH)  outH  += blockIdx.z * sH;
    if (vmulH) vmulH += blockIdx.z * sV;

    const int tid = threadIdx.x;
    const int wid = tid >> 5, lane = tid & 31;
    const int wm = (wid & 1) * 64;
    const int wn = (wid >> 1) * 32;
    const uint32_t sbase = smem_u32(smem);

    float acc[4][4][4];
#pragma unroll
    for (int i = 0; i < 4; i++)
#pragma unroll
        for (int j = 0; j < 4; j++)
#pragma unroll
            for (int p = 0; p < 4; p++) acc[i][j][p] = 0.f;

    const int KB = K >> 5;

#define STAGE_LOAD(kb, buf) do {                                               \
    int k0 = (kb) << 5;                                                        \
    uint32_t st = sbase + (buf) * STAGE_B;                                     \
    _Pragma("unroll")                                                          \
    for (int pos = 0; pos < 2; pos++) {                                        \
        int idx = tid + pos * 256;                                             \
        int r = idx >> 2, cc = idx & 3;                                        \
        uint32_t so = (uint32_t)(r * 80 + cc * 16);                            \
        long ga = (long)(m0 + r) * ldA + k0 + cc * 8;                          \
        long gb = (long)(n0 + r) * ldB + k0 + cc * 8;                          \
        cp_async16(st + so,          Ah + ga);                                 \
        cp_async16(st + TILE_B + so, Bh + gb);                                 \
        if (PASSES >= 2) cp_async16(st + 2 * TILE_B + so, Bl + gb);            \
        if (PASSES == 3) cp_async16(st + 3 * TILE_B + so, Al + ga);            \
    }                                                                          \
    CP_COMMIT();                                                               \
} while (0)

    STAGE_LOAD(0, 0);
    STAGE_LOAD(1, 1);

    const int lg = lane >> 3, lr = lane & 7;
    int cbuf = 0, lbuf = 2;

    for (int kb = 0; kb < KB; kb++) {
        if (kb + 1 < KB) CP_WAIT(1); else CP_WAIT(0);
        __syncthreads();
        if (kb + 2 < KB) STAGE_LOAD(kb + 2, lbuf);
        uint32_t st = sbase + cbuf * STAGE_B;

#pragma unroll
        for (int ks = 0; ks < 2; ks++) {
            const int cb = ks * 2;
            uint32_t ah[4][4], al[4][4], bh[4][2], bl[4][2];
#pragma unroll
            for (int mi = 0; mi < 4; mi++) {
                int row = wm + mi * 16 + lr + (lg & 1) * 8;
                int ch  = cb + (lg >> 1);
                uint32_t a = st + (uint32_t)(row * 80 + ch * 16);
                LDSM_X4(ah[mi], a);
                if (PASSES == 3) LDSM_X4(al[mi], a + 3 * TILE_B);
            }
#pragma unroll
            for (int np = 0; np < 2; np++) {
                int row = wn + np * 16 + lr + (lg >> 1) * 8;
                int ch  = cb + (lg & 1);
                uint32_t a = st + TILE_B + (uint32_t)(row * 80 + ch * 16);
                uint32_t t4[4];
                LDSM_X4(t4, a);
                bh[np * 2][0] = t4[0]; bh[np * 2][1] = t4[1];
                bh[np * 2 + 1][0] = t4[2]; bh[np * 2 + 1][1] = t4[3];
                if (PASSES >= 2) {
                    LDSM_X4(t4, a + TILE_B);
                    bl[np * 2][0] = t4[0]; bl[np * 2][1] = t4[1];
                    bl[np * 2 + 1][0] = t4[2]; bl[np * 2 + 1][1] = t4[3];
                }
            }
#pragma unroll
            for (int mi = 0; mi < 4; mi++)
#pragma unroll
                for (int nj = 0; nj < 4; nj++) {
                    mma16816(acc[mi][nj], ah[mi], bh[nj]);
                    if (PASSES >= 2) mma16816(acc[mi][nj], ah[mi], bl[nj]);
                    if (PASSES == 3) mma16816(acc[mi][nj], al[mi], bh[nj]);
                }
        }
        cbuf = (cbuf == 2) ? 0 : cbuf + 1;
        lbuf = (lbuf == 2) ? 0 : lbuf + 1;
    }

    const int er = lane >> 2, ec = (lane & 3) * 2;
#pragma unroll
    for (int mi = 0; mi < 4; mi++)
#pragma unroll
        for (int nj = 0; nj < 4; nj++) {
            int col = n0 + wn + nj * 8 + ec;
#pragma unroll
            for (int p = 0; p < 2; p++) {
                int row = m0 + wm + mi * 16 + er + p * 8;
                float2 v;
                v.x = acc[mi][nj][p * 2 + 0] * alpha;
                v.y = acc[mi][nj][p * 2 + 1] * alpha;
                if (bias) { v.x += bias[col]; v.y += bias[col + 1]; }
                if (resH) {
                    __half2 r2 = *(const __half2*)(resH + (long)row * ldRes + col);
                    v.x += __half2float(__low2half(r2));
                    v.y += __half2float(__high2half(r2));
                }
                if (vmulH) {
                    __half2 m2 = *(const __half2*)(vmulH + (long)row * ldV + col);
                    v.x *= __half2float(__low2half(m2));
                    v.y *= __half2float(__high2half(m2));
                }
                if (C) *(float2*)(C + (long)row * ldC + col) = v;
                if (outH)
                    *(__half2*)(outH + (long)row * ldH + col) =
                        __halves2half2(__float2half_rn(v.x), __float2half_rn(v.y));
            }
        }
}

// ---------------------------------------------------------------------------
// fused fp32 -> fp16 for x, illu, sem
// ---------------------------------------------------------------------------
__global__ void split_hi3(const float* __restrict__ a, const float* __restrict__ b,
                          const float* __restrict__ c,
                          __half* __restrict__ ha, __half* __restrict__ hb,
                          __half* __restrict__ hc, long n4)
{
    long i = ((long)blockIdx.x * blockDim.x + threadIdx.x);
    if (i >= n4) return;
    i *= 4;
    float4 va = *(const float4*)(a + i);
    float4 vb = *(const float4*)(b + i);
    float4 vc = *(const float4*)(c + i);
    *(__half2*)(ha + i)     = __halves2half2(__float2half_rn(va.x), __float2half_rn(va.y));
    *(__half2*)(ha + i + 2) = __halves2half2(__float2half_rn(va.z), __float2half_rn(va.w));
    *(__half2*)(hb + i)     = __halves2half2(__float2half_rn(vb.x), __float2half_rn(vb.y));
    *(__half2*)(hb + i + 2) = __halves2half2(__float2half_rn(vb.z), __float2half_rn(vb.w));
    *(__half2*)(hc + i)     = __halves2half2(__float2half_rn(vc.x), __float2half_rn(vc.y));
    *(__half2*)(hc + i + 2) = __halves2half2(__float2half_rn(vc.z), __float2half_rn(vc.w));
}

// ---------------------------------------------------------------------------
// transpose + split (weights): fp32 [R,C](ldIn) -> fp16 hi/lo [C,R](ldOut)
// ---------------------------------------------------------------------------
__global__ void transpose_split(const float* __restrict__ in, int ldIn, long sIn,
                                __half* __restrict__ oh, __half* __restrict__ ol,
                                int ldOut, long sOut)
{
    in += blockIdx.z * sIn; oh += blockIdx.z * sOut; ol += blockIdx.z * sOut;
    __shared__ float tile[32][33];
    int c0 = blockIdx.x * 32, r0 = blockIdx.y * 32;
    int tx = threadIdx.x, ty = threadIdx.y;
#pragma unroll
    for (int i = 0; i < 4; i++)
        tile[ty + 8 * i][tx] = in[(long)(r0 + ty + 8 * i) * ldIn + c0 + tx];
    __syncthreads();
#pragma unroll
    for (int i = 0; i < 4; i++) {
        float v = tile[tx][ty + 8 * i];
        __half hh = __float2half_rn(v);
        long o = (long)(c0 + ty + 8 * i) * ldOut + r0 + tx;
        oh[o] = hh;
        ol[o] = __float2half_rn(v - __half2float(hh));
    }
}

// ---------------------------------------------------------------------------
// FUSED: LayerNorm rows (512, fp16 in) + transpose + fp16 hi/lo split.
// ---------------------------------------------------------------------------
#define LDT 516
#define LNT_SMEM (32 * LDT * 4)   // 66048 B

__global__ __launch_bounds__(256) void ln_t_split(
    const __half* __restrict__ in, int ldIn, long sIn,
    const float* __restrict__ gg, const float* __restrict__ bb,
    __half* __restrict__ oh, __half* __restrict__ ol, long sOut)
{
    extern __shared__ float tile[];
    in += blockIdx.y * sIn; oh += blockIdx.y * sOut; ol += blockIdx.y * sOut;
    const int r0 = blockIdx.x * 32;
    const int t = threadIdx.x;

#pragma unroll
    for (int i = 0; i < 8; i++) {
        int lin = t + i * 256;
        int r = lin >> 6, c8 = (lin & 63) * 8;
        uint4 raw = *(const uint4*)(in + (long)(r0 + r) * ldIn + c8);
        const __half2* hp = (const __half2*)&raw;
        float* dst = &tile[r * LDT + c8];
#pragma unroll
        for (int j = 0; j < 4; j++) {
            dst[j * 2 + 0] = __half2float(__low2half(hp[j]));
            dst[j * 2 + 1] = __half2float(__high2half(hp[j]));
        }
    }
    __syncthreads();

    __shared__ float mu_s[32], inv_s[32];
    const int w = t >> 5, lane = t & 31;
#pragma unroll
    for (int rr = 0; rr < 4; rr++) {
        int r = w * 4 + rr;
        float s = 0.f, q = 0.f;
#pragma unroll
        for (int i = 0; i < 16; i++) {
            float v = tile[r * LDT + lane + i * 32];
            s += v; q += v * v;
        }
#pragma unroll
        for (int o = 16; o; o >>= 1) {
            s += __shfl_xor_sync(0xffffffffu, s, o);
            q += __shfl_xor_sync(0xffffffffu, q, o);
        }
        if (lane == 0) {
            float mu = s * (1.f / C_);
            mu_s[r]  = mu;
            inv_s[r] = rsqrtf(q * (1.f / C_) - mu * mu + 1e-5f);
        }
    }
    __syncthreads();

    const int r = t & 31, cg = t >> 5;
    const float mu = mu_s[r], inv = inv_s[r];
#pragma unroll 8
    for (int cc = 0; cc < 64; cc++) {
        int c = cc * 8 + cg;
        float v = (tile[r * LDT + c] - mu) * inv * gg[c] + bb[c];
        __half hh = __float2half_rn(v);
        long o = (long)c * N_ + r0 + r;
        oh[o] = hh;
        ol[o] = __float2half_rn(v - __half2float(hh));
    }
}

// ---------------------------------------------------------------------------
// SIF softmax rows -> fp16 hi/lo (row-major)
// ---------------------------------------------------------------------------
__global__ void softmax_ab(const float* __restrict__ Ab,
                           __half* __restrict__ oh, __half* __restrict__ ol)
{
    long bi = blockIdx.x;
    const float* row = Ab + bi * 512;
    int t = threadIdx.x;
    float4 v = *(const float4*)(row + t * 4);
    float m = fmaxf(fmaxf(v.x, v.y), fmaxf(v.z, v.w));
#pragma unroll
    for (int o = 16; o; o >>= 1) m = fmaxf(m, __shfl_xor_sync(0xffffffffu, m, o));
    __shared__ float rm[4], rs[4];
    if ((t & 31) == 0) rm[t >> 5] = m;
    __syncthreads();
    m = fmaxf(fmaxf(rm[0], rm[1]), fmaxf(rm[2], rm[3]));
    float4 e;
    e.x = expf(v.x - m); e.y = expf(v.y - m);
    e.z = expf(v.z - m); e.w = expf(v.w - m);
    float s = e.x + e.y + e.z + e.w;
#pragma unroll
    for (int o = 16; o; o >>= 1) s += __shfl_xor_sync(0xffffffffu, s, o);
    if ((t & 31) == 0) rs[t >> 5] = s;
    __syncthreads();
    s = rs[0] + rs[1] + rs[2] + rs[3];
    float inv = 1.f / s;
    e.x *= inv; e.y *= inv; e.z *= inv; e.w *= inv;
    long o = bi * 512 + t * 4;
    __half hx = __float2half_rn(e.x), hy = __float2half_rn(e.y);
    __half hz = __float2half_rn(e.z), hw = __float2half_rn(e.w);
    *(__half2*)(oh + o)     = __halves2half2(hx, hy);
    *(__half2*)(oh + o + 2) = __halves2half2(hz, hw);
    *(__half2*)(ol + o) = __halves2half2(
        __float2half_rn(e.x - __half2float(hx)),
        __float2half_rn(e.y - __half2float(hy)));
    *(__half2*)(ol + o + 2) = __halves2half2(
        __float2half_rn(e.z - __half2float(hz)),
        __float2half_rn(e.w - __half2float(hw)));
}

// ---------------------------------------------------------------------------
// HMMA msa_g: Gram partials G[d,e] = sum_n k[n,d] q[n,e] + norms.
// grid (64 bh, GSLICE), 256 thr. smem tiles [64 n x 64 c] (144B rows).
// A = k^T via ldmatrix.trans, B = q^T via ldmatrix.trans. fp32 acc (exact).
// ---------------------------------------------------------------------------
#define GW 144

__global__ __launch_bounds__(256, 2) void msa_g_hmma()
{
    __shared__ char sm[2 * 64 * GW];            // k tile, q tile
    __shared__ float nk_s[4][64], nq_s[4][64];
    const int bh = blockIdx.x, sl = blockIdx.y;
    const int b = bh >> 3, h = bh & 7;
    const int NS = N_ / GSLICE;                 // 1024
    const int n0 = sl * NS;
    const uint32_t sb = smem_u32(sm);
    const int tid = threadIdx.x;
    const __half* qb = g_qkvh + (long)b * N_ * 1536 + h * DH;
    const __half* kb = qb + 512;

    const int wid = tid >> 5, lane = tid & 31;
    const int mi = (wid & 3) * 16;              // d tile base
    const int wn = (wid >> 2) * 32;             // e group base
    const int lg = lane >> 3, lr = lane & 7;

    float acc[4][4];
#pragma unroll
    for (int j = 0; j < 4; j++)
#pragma unroll
        for (int p = 0; p < 4; p++) acc[j][p] = 0.f;
    float ssk = 0.f, ssq = 0.f;
    const int ncol = tid & 63, ng = tid >> 6;

    for (int nb = 0; nb < NS; nb += 64) {
#pragma unroll
        for (int i = 0; i < 2; i++) {
            int idx = tid + i * 256;
            int r = idx >> 3, cc = idx & 7;
            long g = (long)(n0 + nb + r) * 1536 + cc * 8;
            cp_async16(sb + (uint32_t)(r * GW + cc * 16),           kb + g);
            cp_async16(sb + (uint32_t)(64 * GW + r * GW + cc * 16), qb + g);
        }
        CP_COMMIT();
        CP_WAIT(0);
        __syncthreads();

        // norms (interleaved rows, 4 groups)
#pragma unroll
        for (int i = 0; i < 16; i++) {
            int r = ng * 16 + i;
            float kv = __half2float(*(const __half*)(sm + r * GW + ncol * 2));
            float qv = __half2float(*(const __half*)(sm + 64 * GW + r * GW + ncol * 2));
            ssk += kv * kv; ssq += qv * qv;
        }

        // Gram via trans-loaded fragments
#pragma unroll
        for (int ks = 0; ks < 4; ks++) {
            uint32_t aT[4];
            {   // A[d][n]: row = n-half by lg>>1, col = d-half by lg&1
                uint32_t a = sb + (uint32_t)((ks * 16 + lr + (lg >> 1) * 8) * GW
                                             + (mi + (lg & 1) * 8) * 2);
                LDSM_X4_T(aT, a);
            }
#pragma unroll
            for (int np = 0; np < 2; np++) {
                uint32_t t4[4];
                {   // B[e][n]: row = n-half by lg&1, col = e-half by lg>>1
                    uint32_t a = sb + (uint32_t)(64 * GW
                        + (ks * 16 + lr + (lg & 1) * 8) * GW
                        + (wn + np * 16 + (lg >> 1) * 8) * 2);
                    LDSM_X4_T(t4, a);
                }
                uint32_t b0[2] = { t4[0], t4[1] };   // e-frag np*2
                uint32_t b1[2] = { t4[2], t4[3] };   // e-frag np*2+1
                mma16816(acc[np * 2],     aT, b0);
                mma16816(acc[np * 2 + 1], aT, b1);
            }
        }
        __syncthreads();
    }

    // write Gram partial
    const int er = lane >> 2, ec = (lane & 3) * 2;
    float* Gb = g_Gp + ((long)sl * 64 + bh) * 4096;
#pragma unroll
    for (int nj = 0; nj < 4; nj++) {
        int e = wn + nj * 8 + ec;
#pragma unroll
        for (int p = 0; p < 2; p++) {
            int d = mi + er + p * 8;
            *(float2*)(Gb + d * 64 + e) =
                make_float2(acc[nj][p * 2 + 0], acc[nj][p * 2 + 1]);
        }
    }
    // reduce norms
    nk_s[ng][ncol] = ssk;
    nq_s[ng][ncol] = ssq;
    __syncthreads();
    if (tid < 64) {
        float sk = nk_s[0][tid] + nk_s[1][tid] + nk_s[2][tid] + nk_s[3][tid];
        float sq = nq_s[0][tid] + nq_s[1][tid] + nq_s[2][tid] + nq_s[3][tid];
        g_nkp[((long)sl * 64 + bh) * 64 + tid] = sk;
        g_nqp[((long)sl * 64 + bh) * 64 + tid] = sq;
    }
}

// reduce partials + softmax -> attn fp16 hi/lo
__global__ void msa_soft(const float* __restrict__ rescale)
{
    int r = blockIdx.x;
    int bh = r >> 6, d = r & 63, h = bh & 7;
    int t = threadIdx.x;
    float gsum = 0.f, nks = 0.f, nqs = 0.f;
#pragma unroll
    for (int sl = 0; sl < GSLICE; sl++) {
        gsum += g_Gp[((long)sl * 64 + bh) * 4096 + d * 64 + t];
        nks  += g_nkp[((long)sl * 64 + bh) * 64 + d];
        nqs  += g_nqp[((long)sl * 64 + bh) * 64 + t];
    }
    float nk = fmaxf(sqrtf(nks), 1e-12f);
    float nq = fmaxf(sqrtf(nqs), 1e-12f);
    float val = gsum * (rescale[h] / (nk * nq));
    float m = val;
#pragma unroll
    for (int o = 16; o; o >>= 1) m = fmaxf(m, __shfl_xor_sync(0xffffffffu, m, o));
    __shared__ float rm[2], rs[2];
    if ((t & 31) == 0) rm[t >> 5] = m;
    __syncthreads();
    m = fmaxf(rm[0], rm[1]);
    float e = expf(val - m);
    float s = e;
#pragma unroll
    for (int o = 16; o; o >>= 1) s += __shfl_xor_sync(0xffffffffu, s, o);
    if ((t & 31) == 0) rs[t >> 5] = s;
    __syncthreads();
    s = rs[0] + rs[1];
    float v = e / s;
    __half hh = __float2half_rn(v);
    long o = (long)bh * 4096 + d * 64 + t;
    g_attnh[o] = hh;
    g_attnl[o] = __float2half_rn(v - __half2float(hh));
}

// ---------------------------------------------------------------------------
// HMMA msa_o: per (bh, m-tile) o[n, h*64+d] = sum_e w[n,e] attn[d,e]
// ---------------------------------------------------------------------------
#define MOW 144

__global__ __launch_bounds__(256, 2) void msa_o_hmma()
{
    __shared__ char sm[128 * MOW + 2 * 64 * MOW];
    const int mt = blockIdx.x, bh = blockIdx.y;
    const int b = bh >> 3, h = bh & 7;
    const uint32_t sb = smem_u32(sm);
    const int tid = threadIdx.x;
    const int n0 = mt * 128;

    const __half* wb = g_wh + (long)b * N_ * C_ + h * DH;
#pragma unroll
    for (int i = 0; i < 4; i++) {
        int idx = tid + i * 256;
        int r = idx >> 3, cc = idx & 7;
        *(uint4*)(sm + r * MOW + cc * 16) =
            *(const uint4*)(wb + (long)(n0 + r) * C_ + cc * 8);
    }
    const __half* ah_ = g_attnh + (long)bh * 4096;
    const __half* al_ = g_attnl + (long)bh * 4096;
#pragma unroll
    for (int i = 0; i < 2; i++) {
        int idx = tid + i * 256;
        int r = idx >> 3, cc = idx & 7;
        *(uint4*)(sm + 128 * MOW + r * MOW + cc * 16) =
            *(const uint4*)(ah_ + r * 64 + cc * 8);
        *(uint4*)(sm + 192 * MOW + r * MOW + cc * 16) =
            *(const uint4*)(al_ + r * 64 + cc * 8);
    }
    __syncthreads();

    const int wid = tid >> 5, lane = tid & 31;
    const int wm = wid * 16;
    const int lg = lane >> 3, lr = lane & 7;

    float acc[8][4];
#pragma unroll
    for (int j = 0; j < 8; j++)
#pragma unroll
        for (int p = 0; p < 4; p++) acc[j][p] = 0.f;

#pragma unroll
    for (int ks = 0; ks < 4; ks++) {
        const int cb = ks * 2;
        uint32_t a4[4], bhf[8][2], blf[8][2];
        {
            int row = wm + lr + (lg & 1) * 8;
            int ch  = cb + (lg >> 1);
            LDSM_X4(a4, sb + (uint32_t)(row * MOW + ch * 16));
        }
#pragma unroll
        for (int np = 0; np < 4; np++) {
            int row = np * 16 + lr + (lg >> 1) * 8;
            int ch  = cb + (lg & 1);
            uint32_t a = sb + (uint32_t)(128 * MOW + row * MOW + ch * 16);
            uint32_t t4[4];
            LDSM_X4(t4, a);
            bhf[np * 2][0] = t4[0]; bhf[np * 2][1] = t4[1];
            bhf[np * 2 + 1][0] = t4[2]; bhf[np * 2 + 1][1] = t4[3];
            LDSM_X4(t4, a + 64 * MOW);
            blf[np * 2][0] = t4[0]; blf[np * 2][1] = t4[1];
            blf[np * 2 + 1][0] = t4[2]; blf[np * 2 + 1][1] = t4[3];
        }
#pragma unroll
        for (int nj = 0; nj < 8; nj++) {
            mma16816(acc[nj], a4, bhf[nj]);
            mma16816(acc[nj], a4, blf[nj]);
        }
    }

    const int er = lane >> 2, ec = (lane & 3) * 2;
    const long obase = (long)b * N_ * C_ + h * DH;
#pragma unroll
    for (int nj = 0; nj < 8; nj++) {
        int d = nj * 8 + ec;
#pragma unroll
        for (int p = 0; p < 2; p++) {
            int row = n0 + wm + er + p * 8;
            *(__half2*)(g_oh + obase + (long)row * C_ + d) =
                __halves2half2(__float2half_rn(acc[nj][p * 2 + 0]),
                               __float2half_rn(acc[nj][p * 2 + 1]));
        }
    }
}

// ---------------------------------------------------------------------------
// depthwise conv (fp16 in, fp16 out)
// ---------------------------------------------------------------------------
__device__ __forceinline__ float gelu_exact(float x)
{
    return 0.5f * x * (1.f + erff(x * 0.70710678118654752f));
}

template <bool GELU>
__global__ void dwconv3x3_h(const __half* __restrict__ in, int ldIn,
                            const float* __restrict__ w,
                            __half* __restrict__ outHn)
{
    int t = threadIdx.x;
    int c = t * 4;
    float wr[3][3][4];
#pragma unroll
    for (int ky = 0; ky < 3; ky++)
#pragma unroll
        for (int kx = 0; kx < 3; kx++)
#pragma unroll
            for (int i = 0; i < 4; i++)
                wr[ky][kx][i] = w[(long)(c + i) * 9 + ky * 3 + kx];
    long p0 = (long)blockIdx.x * 8;
    int b = (int)(p0 >> 12);
    int yx0 = (int)(p0 & 4095);
#pragma unroll
    for (int px = 0; px < 8; px++) {
        int yx = yx0 + px;
        int y = yx >> 6, x = yx & 63;
        float ax = 0.f, ay = 0.f, az = 0.f, aw = 0.f;
#pragma unroll
        for (int ky = 0; ky < 3; ky++) {
            int yy = y + ky - 1;
            if (yy < 0 || yy > 63) continue;
#pragma unroll
            for (int kx = 0; kx < 3; kx++) {
                int xx = x + kx - 1;
                if (xx < 0 || xx > 63) continue;
                float2 raw = *(const float2*)(in + ((long)(b << 12) + (yy << 6) + xx) * ldIn + c);
                const __half2* hp = (const __half2*)&raw;
                ax += __half2float(__low2half(hp[0]))  * wr[ky][kx][0];
                ay += __half2float(__high2half(hp[0])) * wr[ky][kx][1];
                az += __half2float(__low2half(hp[1]))  * wr[ky][kx][2];
                aw += __half2float(__high2half(hp[1])) * wr[ky][kx][3];
            }
        }
        if (GELU) {
            ax = gelu_exact(ax); ay = gelu_exact(ay);
            az = gelu_exact(az); aw = gelu_exact(aw);
        }
        long off = ((long)(b << 12) + yx) * C_ + c;
        *(__half2*)(outHn + off)     = __halves2half2(__float2half_rn(ax), __float2half_rn(ay));
        *(__half2*)(outHn + off + 2) = __halves2half2(__float2half_rn(az), __float2half_rn(aw));
    }
}

// ---------------------------------------------------------------------------
// host
// ---------------------------------------------------------------------------
extern "C" void kernel_launch(void* const* d_in, const int* in_sizes, int n_in,
                              void* d_out, int out_size)
{
    const float* x       = (const float*)d_in[0];
    const float* illu    = (const float*)d_in[1];
    const float* sem     = (const float*)d_in[2];
    const float* Wk_sif  = (const float*)d_in[3];
    const float* Wq_sif  = (const float*)d_in[4];
    const float* Wv_sif  = (const float*)d_in[5];
    const float* ln_g    = (const float*)d_in[6];
    const float* ln_b    = (const float*)d_in[7];
    const float* Wq      = (const float*)d_in[8];
    const float* Wk      = (const float*)d_in[9];
    const float* Wv      = (const float*)d_in[10];
    const float* rescale = (const float*)d_in[11];
    const float* proj_w  = (const float*)d_in[12];
    const float* proj_b  = (const float*)d_in[13];
    const float* dw1     = (const float*)d_in[14];
    const float* dw2     = (const float*)d_in[15];
    float* out = (float*)d_out;

    cudaFuncSetAttribute((const void*)gemm_h<1, 2>, cudaFuncAttributeMaxDynamicSharedMemorySize, 3 * 2 * TILE_B);
    cudaFuncSetAttribute((const void*)gemm_h<2, 2>, cudaFuncAttributeMaxDynamicSharedMemorySize, 3 * 3 * TILE_B);
    cudaFuncSetAttribute((const void*)gemm_h<3, 1>, cudaFuncAttributeMaxDynamicSharedMemorySize, 3 * 4 * TILE_B);
    cudaFuncSetAttribute((const void*)ln_t_split, cudaFuncAttributeMaxDynamicSharedMemorySize, LNT_SMEM);

#define SYM(p, s) do { void* _t; cudaGetSymbolAddress(&_t, s); p = (decltype(p))_t; } while (0)
    float *ab;
    __half *qkvh, *knvsh, *qnh, *wh, *oh, *p1h, *p2h;
    __half *xh, *ih, *sh;
    __half *knTh, *knTl, *qnTh, *qnTl, *abh, *abl;
    __half *w3h, *w3l, *w2h, *w2l, *wqh, *wql, *wph, *wpl;
    SYM(ab, g_ab);
    SYM(qkvh, g_qkvh); SYM(knvsh, g_knvsh); SYM(qnh, g_qnh);
    SYM(wh, g_wh); SYM(oh, g_oh); SYM(p1h, g_p1h); SYM(p2h, g_p2h);
    SYM(xh, g_xh); SYM(ih, g_ih); SYM(sh, g_sh);
    SYM(knTh, g_knTh); SYM(knTl, g_knTl); SYM(qnTh, g_qnTh); SYM(qnTl, g_qnTl);
    SYM(abh, g_abh); SYM(abl, g_abl);
    SYM(w3h, g_w3h); SYM(w3l, g_w3l); SYM(w2h, g_w2h); SYM(w2l, g_w2l);
    SYM(wqh, g_wqh); SYM(wql, g_wql); SYM(wph, g_wph); SYM(wpl, g_wpl);

    dim3 tb(32, 8);
    dim3 tw(16, 16, 1);
    transpose_split<<<tw, tb>>>(Wq,     C_, 0, w3h,               w3l,               C_, 0);
    transpose_split<<<tw, tb>>>(Wk,     C_, 0, w3h + C_ * C_,     w3l + C_ * C_,     C_, 0);
    transpose_split<<<tw, tb>>>(Wv,     C_, 0, w3h + 2 * C_ * C_, w3l + 2 * C_ * C_, C_, 0);
    transpose_split<<<tw, tb>>>(Wk_sif, C_, 0, w2h,               w2l,               C_, 0);
    transpose_split<<<tw, tb>>>(Wv_sif, C_, 0, w2h + C_ * C_,     w2l + C_ * C_,     C_, 0);
    transpose_split<<<tw, tb>>>(Wq_sif, C_, 0, wqh,               wql,               C_, 0);
    transpose_split<<<tw, tb>>>(proj_w, C_, 0, wph,               wpl,               C_, 0);

    long n4 = (long)MTOT * C_ / 4;
    split_hi3<<<(unsigned)((n4 + 255) / 256), 256>>>(x, illu, sem, xh, ih, sh, n4);

    // GEMM1 (1-pass): qkv(fp16) = x @ [Wq|Wk|Wv]
    gemm_h<1, 2><<<dim3(12, 256, 1), 256, 3 * 2 * TILE_B>>>(xh, nullptr, w3h, nullptr,
        nullptr, C_, C_, C_, 0, 0, 0, 0, nullptr, nullptr, 0, 0, 1.f,
        qkvh, 1536, 0, nullptr, 0, 0);
    // GEMM2 (1-pass): [kn|vs](fp16) = illu @ [Wk_sif|Wv_sif]
    gemm_h<1, 2><<<dim3(8, 256, 1), 256, 3 * 2 * TILE_B>>>(ih, nullptr, w2h, nullptr,
        nullptr, C_, C_, C_, 0, 0, 0, 0, nullptr, nullptr, 0, 0, 1.f,
        knvsh, 1024, 0, nullptr, 0, 0);
    // GEMM3 (1-pass): qn(fp16) = sem @ Wq_sif
    gemm_h<1, 2><<<dim3(4, 256, 1), 256, 3 * 2 * TILE_B>>>(sh, nullptr, wqh, nullptr,
        nullptr, C_, C_, C_, 0, 0, 0, 0, nullptr, nullptr, 0, 0, 1.f,
        qnh, 512, 0, nullptr, 0, 0);

    // positional branch (independent; consumed by GEMM6 epilogue)
    dwconv3x3_h<true ><<<MTOT / 8, 128>>>(qkvh + 1024, 1536, dw1, p1h);
    dwconv3x3_h<false><<<MTOT / 8, 128>>>(p1h, 512, dw2, p2h);

    // fused LN + transpose + split
    ln_t_split<<<dim3(128, 8), 256, LNT_SMEM>>>(knvsh, 1024, (long)N_ * 1024,
        ln_g, ln_b, knTh, knTl, (long)C_ * N_);
    ln_t_split<<<dim3(128, 8), 256, LNT_SMEM>>>(qnh, 512, (long)N_ * 512,
        ln_g, ln_b, qnTh, qnTl, (long)C_ * N_);

    // GEMM4 (3-pass): Ab[b] = (Qn^T Kn)/sqrt(C)
    gemm_h<3, 1><<<dim3(4, 4, 8), 256, 3 * 4 * TILE_B>>>(qnTh, qnTl, knTh, knTl,
        ab, N_, N_, N_, C_, (long)C_ * N_, (long)C_ * N_, (long)C_ * C_,
        nullptr, nullptr, 0, 0, 0.044194173824159216f, nullptr, 0, 0, nullptr, 0, 0);

    softmax_ab<<<B_ * C_, 128>>>(ab, abh, abl);

    // GEMM5 (1-pass): w(fp16) = (V@Ab^T + V) * v
    gemm_h<1, 2><<<dim3(4, 32, 8), 256, 3 * 2 * TILE_B>>>(knvsh + 512, nullptr, abh, nullptr,
        nullptr, C_, 1024, C_, 0, (long)N_ * 1024, (long)C_ * C_, 0,
        nullptr, knvsh + 512, 1024, (long)N_ * 1024, 1.f,
        wh, 512, (long)N_ * C_, qkvh + 1024, 1536, (long)N_ * 1536);

    // FG-MSA (all HMMA now)
    msa_g_hmma<<<dim3(64, GSLICE), 256>>>();
    msa_soft<<<64 * 64, 64>>>(rescale);
    msa_o_hmma<<<dim3(32, 64), 256>>>();

    // GEMM6 (2-pass): out = o @ proj_w + proj_b + p2  (positional branch fused)
    gemm_h<2, 2><<<dim3(4, 256, 1), 256, 3 * 3 * TILE_B>>>(oh, nullptr, wph, wpl,
        out, C_, C_, C_, C_, 0, 0, 0, proj_b, p2h, C_, 0, 1.f,
        nullptr, 0, 0, nullptr, 0, 0);
}

// round 14
// speedup vs baseline: 4.1951x; 1.0313x over previous
#include <cuda_runtime.h>
#include <cuda_fp16.h>
#include <math.h>
#include <stdint.h>

#define B_    8
#define C_    512
#define N_    4096
#define MTOT  32768
#define DH    64
#define GSLICE 4

// ---------------------------------------------------------------------------
// helpers (portable PTX only: cp.async, ldmatrix, mma.sync)
// ---------------------------------------------------------------------------
__device__ __forceinline__ uint32_t smem_u32(const void* p) {
    uint32_t a;
    asm("{ .reg .u64 t; cvta.to.shared.u64 t, %1; cvt.u32.u64 %0, t; }" : "=r"(a) : "l"(p));
    return a;
}
__device__ __forceinline__ void cp_async16(uint32_t dst, const void* src) {
    asm volatile("cp.async.cg.shared.global [%0], [%1], 16;" :: "r"(dst), "l"(src));
}
#define CP_COMMIT() asm volatile("cp.async.commit_group;" ::: "memory")
#define CP_WAIT(n)  asm volatile("cp.async.wait_group %0;" :: "n"(n) : "memory")

#define LDSM_X4(r, a)                                                          \
    asm volatile("ldmatrix.sync.aligned.m8n8.x4.shared.b16 {%0,%1,%2,%3},[%4];"\
        : "=r"((r)[0]), "=r"((r)[1]), "=r"((r)[2]), "=r"((r)[3]) : "r"(a))

#define LDSM_X4_T(r, a)                                                        \
    asm volatile("ldmatrix.sync.aligned.m8n8.x4.trans.shared.b16 {%0,%1,%2,%3},[%4];"\
        : "=r"((r)[0]), "=r"((r)[1]), "=r"((r)[2]), "=r"((r)[3]) : "r"(a))

__device__ __forceinline__ void mma16816(float* d, const uint32_t* a, const uint32_t* b) {
    asm volatile("mma.sync.aligned.m16n8k16.row.col.f32.f16.f16.f32 "
        "{%0,%1,%2,%3},{%4,%5,%6,%7},{%8,%9},{%0,%1,%2,%3};"
        : "+f"(d[0]), "+f"(d[1]), "+f"(d[2]), "+f"(d[3])
        : "r"(a[0]), "r"(a[1]), "r"(a[2]), "r"(a[3]), "r"(b[0]), "r"(b[1]));
}

// ---------------------------------------------------------------------------
// scratch
// ---------------------------------------------------------------------------
__device__ __half g_qkvh [MTOT * 1536];   // q|k|v
__device__ __half g_knvsh[MTOT * 1024];   // kn|vs
__device__ __half g_qnh  [MTOT * C_];
__device__ __half g_wh   [MTOT * C_];     // v * prior
__device__ __half g_oh   [MTOT * C_];
__device__ __half g_p1h  [MTOT * C_];
__device__ __half g_p2h  [MTOT * C_];
__device__ float  g_ab   [B_ * C_ * C_];
__device__ __half g_xh [MTOT * C_];
__device__ __half g_ih [MTOT * C_];
__device__ __half g_sh [MTOT * C_];
__device__ __half g_knTh[B_ * C_ * N_], g_knTl[B_ * C_ * N_];
__device__ __half g_qnTh[B_ * C_ * N_], g_qnTl[B_ * C_ * N_];
__device__ __half g_abh[B_ * C_ * C_],  g_abl[B_ * C_ * C_];
__device__ __half g_w3h[1536 * C_], g_w3l[1536 * C_];
__device__ __half g_w2h[1024 * C_], g_w2l[1024 * C_];
__device__ __half g_wqh[C_ * C_],   g_wql[C_ * C_];
__device__ __half g_wph[C_ * C_],   g_wpl[C_ * C_];
__device__ float g_Gp [GSLICE * 64 * 64 * 64];
__device__ float g_nkp[GSLICE * 64 * 64];
__device__ float g_nqp[GSLICE * 64 * 64];
__device__ __half g_attnh[64 * 64 * 64];
__device__ __half g_attnl[64 * 64 * 64];

// ---------------------------------------------------------------------------
// HMMA GEMM, PASSES = 1 (AhBh), 2 (+AhBl), 3 (+AlBh).
// CTA 128x128, BK=32, 8 warps, 3-stage cp.async, 80B-padded smem rows.
// ---------------------------------------------------------------------------
#define TILE_B   10240            // 128 rows * 80 B

template <int PASSES, int MINB>
__global__ __launch_bounds__(256, MINB) void gemm_h(
    const __half* __restrict__ Ah, const __half* __restrict__ Al,
    const __half* __restrict__ Bh, const __half* __restrict__ Bl,
    float* __restrict__ C, int K, int ldA, int ldB, int ldC,
    long sA, long sB, long sC,
    const float* __restrict__ bias,
    const __half* __restrict__ resH, int ldRes, long sRes,
    float alpha,
    __half* __restrict__ outH, int ldH, long sH,
    const __half* __restrict__ vmulH, int ldV, long sV)
{
    constexpr int NT = PASSES + 1;        // tiles per stage
    constexpr int STAGE_B = NT * TILE_B;
    extern __shared__ char smem[];
    const int m0 = blockIdx.y * 128, n0 = blockIdx.x * 128;
    Ah += blockIdx.z * sA;
    if (PASSES == 3) Al += blockIdx.z * sA;
    Bh += blockIdx.z * sB;
    if (PASSES >= 2) Bl += blockIdx.z * sB;
    if (C)     C     += blockIdx.z * sC;
    if (resH)  resH  += blockIdx.z * sRes;
    if (outH)  outH  += blockIdx.z * sH;
    if (vmulH) vmulH += blockIdx.z * sV;

    const int tid = threadIdx.x;
    const int wid = tid >> 5, lane = tid & 31;
    const int wm = (wid & 1) * 64;
    const int wn = (wid >> 1) * 32;
    const uint32_t sbase = smem_u32(smem);

    float acc[4][4][4];
#pragma unroll
    for (int i = 0; i < 4; i++)
#pragma unroll
        for (int j = 0; j < 4; j++)
#pragma unroll
            for (int p = 0; p < 4; p++) acc[i][j][p] = 0.f;

    const int KB = K >> 5;

#define STAGE_LOAD(kb, buf) do {                                               \
    int k0 = (kb) << 5;                                                        \
    uint32_t st = sbase + (buf) * STAGE_B;                                     \
    _Pragma("unroll")                                                          \
    for (int pos = 0; pos < 2; pos++) {                                        \
        int idx = tid + pos * 256;                                             \
        int r = idx >> 2, cc = idx & 3;                                        \
        uint32_t so = (uint32_t)(r * 80 + cc * 16);                            \
        long ga = (long)(m0 + r) * ldA + k0 + cc * 8;                          \
        long gb = (long)(n0 + r) * ldB + k0 + cc * 8;                          \
        cp_async16(st + so,          Ah + ga);                                 \
        cp_async16(st + TILE_B + so, Bh + gb);                                 \
        if (PASSES >= 2) cp_async16(st + 2 * TILE_B + so, Bl + gb);            \
        if (PASSES == 3) cp_async16(st + 3 * TILE_B + so, Al + ga);            \
    }                                                                          \
    CP_COMMIT();                                                               \
} while (0)

    STAGE_LOAD(0, 0);
    STAGE_LOAD(1, 1);

    const int lg = lane >> 3, lr = lane & 7;
    int cbuf = 0, lbuf = 2;

    for (int kb = 0; kb < KB; kb++) {
        if (kb + 1 < KB) CP_WAIT(1); else CP_WAIT(0);
        __syncthreads();
        if (kb + 2 < KB) STAGE_LOAD(kb + 2, lbuf);
        uint32_t st = sbase + cbuf * STAGE_B;

#pragma unroll
        for (int ks = 0; ks < 2; ks++) {
            const int cb = ks * 2;
            uint32_t ah[4][4], al[4][4], bh[4][2], bl[4][2];
#pragma unroll
            for (int mi = 0; mi < 4; mi++) {
                int row = wm + mi * 16 + lr + (lg & 1) * 8;
                int ch  = cb + (lg >> 1);
                uint32_t a = st + (uint32_t)(row * 80 + ch * 16);
                LDSM_X4(ah[mi], a);
                if (PASSES == 3) LDSM_X4(al[mi], a + 3 * TILE_B);
            }
#pragma unroll
            for (int np = 0; np < 2; np++) {
                int row = wn + np * 16 + lr + (lg >> 1) * 8;
                int ch  = cb + (lg & 1);
                uint32_t a = st + TILE_B + (uint32_t)(row * 80 + ch * 16);
                uint32_t t4[4];
                LDSM_X4(t4, a);
                bh[np * 2][0] = t4[0]; bh[np * 2][1] = t4[1];
                bh[np * 2 + 1][0] = t4[2]; bh[np * 2 + 1][1] = t4[3];
                if (PASSES >= 2) {
                    LDSM_X4(t4, a + TILE_B);
                    bl[np * 2][0] = t4[0]; bl[np * 2][1] = t4[1];
                    bl[np * 2 + 1][0] = t4[2]; bl[np * 2 + 1][1] = t4[3];
                }
            }
#pragma unroll
            for (int mi = 0; mi < 4; mi++)
#pragma unroll
                for (int nj = 0; nj < 4; nj++) {
                    mma16816(acc[mi][nj], ah[mi], bh[nj]);
                    if (PASSES >= 2) mma16816(acc[mi][nj], ah[mi], bl[nj]);
                    if (PASSES == 3) mma16816(acc[mi][nj], al[mi], bh[nj]);
                }
        }
        cbuf = (cbuf == 2) ? 0 : cbuf + 1;
        lbuf = (lbuf == 2) ? 0 : lbuf + 1;
    }

    const int er = lane >> 2, ec = (lane & 3) * 2;
#pragma unroll
    for (int mi = 0; mi < 4; mi++)
#pragma unroll
        for (int nj = 0; nj < 4; nj++) {
            int col = n0 + wn + nj * 8 + ec;
#pragma unroll
            for (int p = 0; p < 2; p++) {
                int row = m0 + wm + mi * 16 + er + p * 8;
                float2 v;
                v.x = acc[mi][nj][p * 2 + 0] * alpha;
                v.y = acc[mi][nj][p * 2 + 1] * alpha;
                if (bias) { v.x += bias[col]; v.y += bias[col + 1]; }
                if (resH) {
                    __half2 r2 = *(const __half2*)(resH + (long)row * ldRes + col);
                    v.x += __half2float(__low2half(r2));
                    v.y += __half2float(__high2half(r2));
                }
                if (vmulH) {
                    __half2 m2 = *(const __half2*)(vmulH + (long)row * ldV + col);
                    v.x *= __half2float(__low2half(m2));
                    v.y *= __half2float(__high2half(m2));
                }
                if (C) *(float2*)(C + (long)row * ldC + col) = v;
                if (outH)
                    *(__half2*)(outH + (long)row * ldH + col) =
                        __halves2half2(__float2half_rn(v.x), __float2half_rn(v.y));
            }
        }
}

// ---------------------------------------------------------------------------
// fused fp32 -> fp16 for x, illu, sem
// ---------------------------------------------------------------------------
__global__ void split_hi3(const float* __restrict__ a, const float* __restrict__ b,
                          const float* __restrict__ c,
                          __half* __restrict__ ha, __half* __restrict__ hb,
                          __half* __restrict__ hc, long n4)
{
    long i = ((long)blockIdx.x * blockDim.x + threadIdx.x);
    if (i >= n4) return;
    i *= 4;
    float4 va = *(const float4*)(a + i);
    float4 vb = *(const float4*)(b + i);
    float4 vc = *(const float4*)(c + i);
    *(__half2*)(ha + i)     = __halves2half2(__float2half_rn(va.x), __float2half_rn(va.y));
    *(__half2*)(ha + i + 2) = __halves2half2(__float2half_rn(va.z), __float2half_rn(va.w));
    *(__half2*)(hb + i)     = __halves2half2(__float2half_rn(vb.x), __float2half_rn(vb.y));
    *(__half2*)(hb + i + 2) = __halves2half2(__float2half_rn(vb.z), __float2half_rn(vb.w));
    *(__half2*)(hc + i)     = __halves2half2(__float2half_rn(vc.x), __float2half_rn(vc.y));
    *(__half2*)(hc + i + 2) = __halves2half2(__float2half_rn(vc.z), __float2half_rn(vc.w));
}

// ---------------------------------------------------------------------------
// transpose + split (weights): fp32 [R,C](ldIn) -> fp16 hi/lo [C,R](ldOut)
// ---------------------------------------------------------------------------
__global__ void transpose_split(const float* __restrict__ in, int ldIn, long sIn,
                                __half* __restrict__ oh, __half* __restrict__ ol,
                                int ldOut, long sOut)
{
    in += blockIdx.z * sIn; oh += blockIdx.z * sOut; ol += blockIdx.z * sOut;
    __shared__ float tile[32][33];
    int c0 = blockIdx.x * 32, r0 = blockIdx.y * 32;
    int tx = threadIdx.x, ty = threadIdx.y;
#pragma unroll
    for (int i = 0; i < 4; i++)
        tile[ty + 8 * i][tx] = in[(long)(r0 + ty + 8 * i) * ldIn + c0 + tx];
    __syncthreads();
#pragma unroll
    for (int i = 0; i < 4; i++) {
        float v = tile[tx][ty + 8 * i];
        __half hh = __float2half_rn(v);
        long o = (long)(c0 + ty + 8 * i) * ldOut + r0 + tx;
        oh[o] = hh;
        ol[o] = __float2half_rn(v - __half2float(hh));
    }
}

// ---------------------------------------------------------------------------
// FUSED: LayerNorm rows (512, fp16 in) + transpose + fp16 hi/lo split.
// ---------------------------------------------------------------------------
#define LDT 516
#define LNT_SMEM (32 * LDT * 4)   // 66048 B

__global__ __launch_bounds__(256) void ln_t_split(
    const __half* __restrict__ in, int ldIn, long sIn,
    const float* __restrict__ gg, const float* __restrict__ bb,
    __half* __restrict__ oh, __half* __restrict__ ol, long sOut)
{
    extern __shared__ float tile[];
    in += blockIdx.y * sIn; oh += blockIdx.y * sOut; ol += blockIdx.y * sOut;
    const int r0 = blockIdx.x * 32;
    const int t = threadIdx.x;

#pragma unroll
    for (int i = 0; i < 8; i++) {
        int lin = t + i * 256;
        int r = lin >> 6, c8 = (lin & 63) * 8;
        uint4 raw = *(const uint4*)(in + (long)(r0 + r) * ldIn + c8);
        const __half2* hp = (const __half2*)&raw;
        float* dst = &tile[r * LDT + c8];
#pragma unroll
        for (int j = 0; j < 4; j++) {
            dst[j * 2 + 0] = __half2float(__low2half(hp[j]));
            dst[j * 2 + 1] = __half2float(__high2half(hp[j]));
        }
    }
    __syncthreads();

    __shared__ float mu_s[32], inv_s[32];
    const int w = t >> 5, lane = t & 31;
#pragma unroll
    for (int rr = 0; rr < 4; rr++) {
        int r = w * 4 + rr;
        float s = 0.f, q = 0.f;
#pragma unroll
        for (int i = 0; i < 16; i++) {
            float v = tile[r * LDT + lane + i * 32];
            s += v; q += v * v;
        }
#pragma unroll
        for (int o = 16; o; o >>= 1) {
            s += __shfl_xor_sync(0xffffffffu, s, o);
            q += __shfl_xor_sync(0xffffffffu, q, o);
        }
        if (lane == 0) {
            float mu = s * (1.f / C_);
            mu_s[r]  = mu;
            inv_s[r] = rsqrtf(q * (1.f / C_) - mu * mu + 1e-5f);
        }
    }
    __syncthreads();

    const int r = t & 31, cg = t >> 5;
    const float mu = mu_s[r], inv = inv_s[r];
#pragma unroll 8
    for (int cc = 0; cc < 64; cc++) {
        int c = cc * 8 + cg;
        float v = (tile[r * LDT + c] - mu) * inv * gg[c] + bb[c];
        __half hh = __float2half_rn(v);
        long o = (long)c * N_ + r0 + r;
        oh[o] = hh;
        ol[o] = __float2half_rn(v - __half2float(hh));
    }
}

// ---------------------------------------------------------------------------
// SIF softmax rows -> fp16 hi/lo (row-major)
// ---------------------------------------------------------------------------
__global__ void softmax_ab(const float* __restrict__ Ab,
                           __half* __restrict__ oh, __half* __restrict__ ol)
{
    long bi = blockIdx.x;
    const float* row = Ab + bi * 512;
    int t = threadIdx.x;
    float4 v = *(const float4*)(row + t * 4);
    float m = fmaxf(fmaxf(v.x, v.y), fmaxf(v.z, v.w));
#pragma unroll
    for (int o = 16; o; o >>= 1) m = fmaxf(m, __shfl_xor_sync(0xffffffffu, m, o));
    __shared__ float rm[4], rs[4];
    if ((t & 31) == 0) rm[t >> 5] = m;
    __syncthreads();
    m = fmaxf(fmaxf(rm[0], rm[1]), fmaxf(rm[2], rm[3]));
    float4 e;
    e.x = expf(v.x - m); e.y = expf(v.y - m);
    e.z = expf(v.z - m); e.w = expf(v.w - m);
    float s = e.x + e.y + e.z + e.w;
#pragma unroll
    for (int o = 16; o; o >>= 1) s += __shfl_xor_sync(0xffffffffu, s, o);
    if ((t & 31) == 0) rs[t >> 5] = s;
    __syncthreads();
    s = rs[0] + rs[1] + rs[2] + rs[3];
    float inv = 1.f / s;
    e.x *= inv; e.y *= inv; e.z *= inv; e.w *= inv;
    long o = bi * 512 + t * 4;
    __half hx = __float2half_rn(e.x), hy = __float2half_rn(e.y);
    __half hz = __float2half_rn(e.z), hw = __float2half_rn(e.w);
    *(__half2*)(oh + o)     = __halves2half2(hx, hy);
    *(__half2*)(oh + o + 2) = __halves2half2(hz, hw);
    *(__half2*)(ol + o) = __halves2half2(
        __float2half_rn(e.x - __half2float(hx)),
        __float2half_rn(e.y - __half2float(hy)));
    *(__half2*)(ol + o + 2) = __halves2half2(
        __float2half_rn(e.z - __half2float(hz)),
        __float2half_rn(e.w - __half2float(hw)));
}

// ---------------------------------------------------------------------------
// HMMA msa_g: Gram partials G[d,e] = sum_n k[n,d] q[n,e] + norms.
// ---------------------------------------------------------------------------
#define GW 144

__global__ __launch_bounds__(256, 2) void msa_g_hmma()
{
    __shared__ char sm[2 * 64 * GW];            // k tile, q tile
    __shared__ float nk_s[4][64], nq_s[4][64];
    const int bh = blockIdx.x, sl = blockIdx.y;
    const int b = bh >> 3, h = bh & 7;
    const int NS = N_ / GSLICE;                 // 1024
    const int n0 = sl * NS;
    const uint32_t sb = smem_u32(sm);
    const int tid = threadIdx.x;
    const __half* qb = g_qkvh + (long)b * N_ * 1536 + h * DH;
    const __half* kb = qb + 512;

    const int wid = tid >> 5, lane = tid & 31;
    const int mi = (wid & 3) * 16;              // d tile base
    const int wn = (wid >> 2) * 32;             // e group base
    const int lg = lane >> 3, lr = lane & 7;

    float acc[4][4];
#pragma unroll
    for (int j = 0; j < 4; j++)
#pragma unroll
        for (int p = 0; p < 4; p++) acc[j][p] = 0.f;
    float ssk = 0.f, ssq = 0.f;
    const int ncol = tid & 63, ng = tid >> 6;

    for (int nb = 0; nb < NS; nb += 64) {
#pragma unroll
        for (int i = 0; i < 2; i++) {
            int idx = tid + i * 256;
            int r = idx >> 3, cc = idx & 7;
            long g = (long)(n0 + nb + r) * 1536 + cc * 8;
            cp_async16(sb + (uint32_t)(r * GW + cc * 16),           kb + g);
            cp_async16(sb + (uint32_t)(64 * GW + r * GW + cc * 16), qb + g);
        }
        CP_COMMIT();
        CP_WAIT(0);
        __syncthreads();

#pragma unroll
        for (int i = 0; i < 16; i++) {
            int r = ng * 16 + i;
            float kv = __half2float(*(const __half*)(sm + r * GW + ncol * 2));
            float qv = __half2float(*(const __half*)(sm + 64 * GW + r * GW + ncol * 2));
            ssk += kv * kv; ssq += qv * qv;
        }

#pragma unroll
        for (int ks = 0; ks < 4; ks++) {
            uint32_t aT[4];
            {
                uint32_t a = sb + (uint32_t)((ks * 16 + lr + (lg >> 1) * 8) * GW
                                             + (mi + (lg & 1) * 8) * 2);
                LDSM_X4_T(aT, a);
            }
#pragma unroll
            for (int np = 0; np < 2; np++) {
                uint32_t t4[4];
                {
                    uint32_t a = sb + (uint32_t)(64 * GW
                        + (ks * 16 + lr + (lg & 1) * 8) * GW
                        + (wn + np * 16 + (lg >> 1) * 8) * 2);
                    LDSM_X4_T(t4, a);
                }
                uint32_t b0[2] = { t4[0], t4[1] };
                uint32_t b1[2] = { t4[2], t4[3] };
                mma16816(acc[np * 2],     aT, b0);
                mma16816(acc[np * 2 + 1], aT, b1);
            }
        }
        __syncthreads();
    }

    const int er = lane >> 2, ec = (lane & 3) * 2;
    float* Gb = g_Gp + ((long)sl * 64 + bh) * 4096;
#pragma unroll
    for (int nj = 0; nj < 4; nj++) {
        int e = wn + nj * 8 + ec;
#pragma unroll
        for (int p = 0; p < 2; p++) {
            int d = mi + er + p * 8;
            *(float2*)(Gb + d * 64 + e) =
                make_float2(acc[nj][p * 2 + 0], acc[nj][p * 2 + 1]);
        }
    }
    nk_s[ng][ncol] = ssk;
    nq_s[ng][ncol] = ssq;
    __syncthreads();
    if (tid < 64) {
        float sk = nk_s[0][tid] + nk_s[1][tid] + nk_s[2][tid] + nk_s[3][tid];
        float sq = nq_s[0][tid] + nq_s[1][tid] + nq_s[2][tid] + nq_s[3][tid];
        g_nkp[((long)sl * 64 + bh) * 64 + tid] = sk;
        g_nqp[((long)sl * 64 + bh) * 64 + tid] = sq;
    }
}

// reduce partials + softmax -> attn fp16 hi/lo
__global__ void msa_soft(const float* __restrict__ rescale)
{
    int r = blockIdx.x;
    int bh = r >> 6, d = r & 63, h = bh & 7;
    int t = threadIdx.x;
    float gsum = 0.f, nks = 0.f, nqs = 0.f;
#pragma unroll
    for (int sl = 0; sl < GSLICE; sl++) {
        gsum += g_Gp[((long)sl * 64 + bh) * 4096 + d * 64 + t];
        nks  += g_nkp[((long)sl * 64 + bh) * 64 + d];
        nqs  += g_nqp[((long)sl * 64 + bh) * 64 + t];
    }
    float nk = fmaxf(sqrtf(nks), 1e-12f);
    float nq = fmaxf(sqrtf(nqs), 1e-12f);
    float val = gsum * (rescale[h] / (nk * nq));
    float m = val;
#pragma unroll
    for (int o = 16; o; o >>= 1) m = fmaxf(m, __shfl_xor_sync(0xffffffffu, m, o));
    __shared__ float rm[2], rs[2];
    if ((t & 31) == 0) rm[t >> 5] = m;
    __syncthreads();
    m = fmaxf(rm[0], rm[1]);
    float e = expf(val - m);
    float s = e;
#pragma unroll
    for (int o = 16; o; o >>= 1) s += __shfl_xor_sync(0xffffffffu, s, o);
    if ((t & 31) == 0) rs[t >> 5] = s;
    __syncthreads();
    s = rs[0] + rs[1];
    float v = e / s;
    __half hh = __float2half_rn(v);
    long o = (long)bh * 4096 + d * 64 + t;
    g_attnh[o] = hh;
    g_attnl[o] = __float2half_rn(v - __half2float(hh));
}

// ---------------------------------------------------------------------------
// HMMA msa_o: per (bh, m-tile) o[n, h*64+d] = sum_e w[n,e] attn[d,e]
// ---------------------------------------------------------------------------
#define MOW 144

__global__ __launch_bounds__(256, 2) void msa_o_hmma()
{
    __shared__ char sm[128 * MOW + 2 * 64 * MOW];
    const int mt = blockIdx.x, bh = blockIdx.y;
    const int b = bh >> 3, h = bh & 7;
    const uint32_t sb = smem_u32(sm);
    const int tid = threadIdx.x;
    const int n0 = mt * 128;

    const __half* wb = g_wh + (long)b * N_ * C_ + h * DH;
#pragma unroll
    for (int i = 0; i < 4; i++) {
        int idx = tid + i * 256;
        int r = idx >> 3, cc = idx & 7;
        *(uint4*)(sm + r * MOW + cc * 16) =
            *(const uint4*)(wb + (long)(n0 + r) * C_ + cc * 8);
    }
    const __half* ah_ = g_attnh + (long)bh * 4096;
    const __half* al_ = g_attnl + (long)bh * 4096;
#pragma unroll
    for (int i = 0; i < 2; i++) {
        int idx = tid + i * 256;
        int r = idx >> 3, cc = idx & 7;
        *(uint4*)(sm + 128 * MOW + r * MOW + cc * 16) =
            *(const uint4*)(ah_ + r * 64 + cc * 8);
        *(uint4*)(sm + 192 * MOW + r * MOW + cc * 16) =
            *(const uint4*)(al_ + r * 64 + cc * 8);
    }
    __syncthreads();

    const int wid = tid >> 5, lane = tid & 31;
    const int wm = wid * 16;
    const int lg = lane >> 3, lr = lane & 7;

    float acc[8][4];
#pragma unroll
    for (int j = 0; j < 8; j++)
#pragma unroll
        for (int p = 0; p < 4; p++) acc[j][p] = 0.f;

#pragma unroll
    for (int ks = 0; ks < 4; ks++) {
        const int cb = ks * 2;
        uint32_t a4[4], bhf[8][2], blf[8][2];
        {
            int row = wm + lr + (lg & 1) * 8;
            int ch  = cb + (lg >> 1);
            LDSM_X4(a4, sb + (uint32_t)(row * MOW + ch * 16));
        }
#pragma unroll
        for (int np = 0; np < 4; np++) {
            int row = np * 16 + lr + (lg >> 1) * 8;
            int ch  = cb + (lg & 1);
            uint32_t a = sb + (uint32_t)(128 * MOW + row * MOW + ch * 16);
            uint32_t t4[4];
            LDSM_X4(t4, a);
            bhf[np * 2][0] = t4[0]; bhf[np * 2][1] = t4[1];
            bhf[np * 2 + 1][0] = t4[2]; bhf[np * 2 + 1][1] = t4[3];
            LDSM_X4(t4, a + 64 * MOW);
            blf[np * 2][0] = t4[0]; blf[np * 2][1] = t4[1];
            blf[np * 2 + 1][0] = t4[2]; blf[np * 2 + 1][1] = t4[3];
        }
#pragma unroll
        for (int nj = 0; nj < 8; nj++) {
            mma16816(acc[nj], a4, bhf[nj]);
            mma16816(acc[nj], a4, blf[nj]);
        }
    }

    const int er = lane >> 2, ec = (lane & 3) * 2;
    const long obase = (long)b * N_ * C_ + h * DH;
#pragma unroll
    for (int nj = 0; nj < 8; nj++) {
        int d = nj * 8 + ec;
#pragma unroll
        for (int p = 0; p < 2; p++) {
            int row = n0 + wm + er + p * 8;
            *(__half2*)(g_oh + obase + (long)row * C_ + d) =
                __halves2half2(__float2half_rn(acc[nj][p * 2 + 0]),
                               __float2half_rn(acc[nj][p * 2 + 1]));
        }
    }
}

// ---------------------------------------------------------------------------
// depthwise conv (fp16 in, fp16 out)
// ---------------------------------------------------------------------------
__device__ __forceinline__ float gelu_exact(float x)
{
    return 0.5f * x * (1.f + erff(x * 0.70710678118654752f));
}

template <bool GELU>
__global__ void dwconv3x3_h(const __half* __restrict__ in, int ldIn,
                            const float* __restrict__ w,
                            __half* __restrict__ outHn)
{
    int t = threadIdx.x;
    int c = t * 4;
    float wr[3][3][4];
#pragma unroll
    for (int ky = 0; ky < 3; ky++)
#pragma unroll
        for (int kx = 0; kx < 3; kx++)
#pragma unroll
            for (int i = 0; i < 4; i++)
                wr[ky][kx][i] = w[(long)(c + i) * 9 + ky * 3 + kx];
    long p0 = (long)blockIdx.x * 8;
    int b = (int)(p0 >> 12);
    int yx0 = (int)(p0 & 4095);
#pragma unroll
    for (int px = 0; px < 8; px++) {
        int yx = yx0 + px;
        int y = yx >> 6, x = yx & 63;
        float ax = 0.f, ay = 0.f, az = 0.f, aw = 0.f;
#pragma unroll
        for (int ky = 0; ky < 3; ky++) {
            int yy = y + ky - 1;
            if (yy < 0 || yy > 63) continue;
#pragma unroll
            for (int kx = 0; kx < 3; kx++) {
                int xx = x + kx - 1;
                if (xx < 0 || xx > 63) continue;
                float2 raw = *(const float2*)(in + ((long)(b << 12) + (yy << 6) + xx) * ldIn + c);
                const __half2* hp = (const __half2*)&raw;
                ax += __half2float(__low2half(hp[0]))  * wr[ky][kx][0];
                ay += __half2float(__high2half(hp[0])) * wr[ky][kx][1];
                az += __half2float(__low2half(hp[1]))  * wr[ky][kx][2];
                aw += __half2float(__high2half(hp[1])) * wr[ky][kx][3];
            }
        }
        if (GELU) {
            ax = gelu_exact(ax); ay = gelu_exact(ay);
            az = gelu_exact(az); aw = gelu_exact(aw);
        }
        long off = ((long)(b << 12) + yx) * C_ + c;
        *(__half2*)(outHn + off)     = __halves2half2(__float2half_rn(ax), __float2half_rn(ay));
        *(__half2*)(outHn + off + 2) = __halves2half2(__float2half_rn(az), __float2half_rn(aw));
    }
}

// ---------------------------------------------------------------------------
// host
// ---------------------------------------------------------------------------
extern "C" void kernel_launch(void* const* d_in, const int* in_sizes, int n_in,
                              void* d_out, int out_size)
{
    const float* x       = (const float*)d_in[0];
    const float* illu    = (const float*)d_in[1];
    const float* sem     = (const float*)d_in[2];
    const float* Wk_sif  = (const float*)d_in[3];
    const float* Wq_sif  = (const float*)d_in[4];
    const float* Wv_sif  = (const float*)d_in[5];
    const float* ln_g    = (const float*)d_in[6];
    const float* ln_b    = (const float*)d_in[7];
    const float* Wq      = (const float*)d_in[8];
    const float* Wk      = (const float*)d_in[9];
    const float* Wv      = (const float*)d_in[10];
    const float* rescale = (const float*)d_in[11];
    const float* proj_w  = (const float*)d_in[12];
    const float* proj_b  = (const float*)d_in[13];
    const float* dw1     = (const float*)d_in[14];
    const float* dw2     = (const float*)d_in[15];
    float* out = (float*)d_out;

    // side streams + fork/join events (host objects; created once, reused —
    // identical captured graph on every call)
    static cudaStream_t s1 = nullptr, s2 = nullptr;
    static cudaEvent_t evA = nullptr, evP = nullptr, evM = nullptr;
    if (s1 == nullptr) {
        cudaStreamCreateWithFlags(&s1, cudaStreamNonBlocking);
        cudaStreamCreateWithFlags(&s2, cudaStreamNonBlocking);
        cudaEventCreateWithFlags(&evA, cudaEventDisableTiming);
        cudaEventCreateWithFlags(&evP, cudaEventDisableTiming);
        cudaEventCreateWithFlags(&evM, cudaEventDisableTiming);
    }

    cudaFuncSetAttribute((const void*)gemm_h<1, 2>, cudaFuncAttributeMaxDynamicSharedMemorySize, 3 * 2 * TILE_B);
    cudaFuncSetAttribute((const void*)gemm_h<2, 2>, cudaFuncAttributeMaxDynamicSharedMemorySize, 3 * 3 * TILE_B);
    cudaFuncSetAttribute((const void*)gemm_h<3, 1>, cudaFuncAttributeMaxDynamicSharedMemorySize, 3 * 4 * TILE_B);
    cudaFuncSetAttribute((const void*)ln_t_split, cudaFuncAttributeMaxDynamicSharedMemorySize, LNT_SMEM);

#define SYM(p, s) do { void* _t; cudaGetSymbolAddress(&_t, s); p = (decltype(p))_t; } while (0)
    float *ab;
    __half *qkvh, *knvsh, *qnh, *wh, *oh, *p1h, *p2h;
    __half *xh, *ih, *sh;
    __half *knTh, *knTl, *qnTh, *qnTl, *abh, *abl;
    __half *w3h, *w3l, *w2h, *w2l, *wqh, *wql, *wph, *wpl;
    SYM(ab, g_ab);
    SYM(qkvh, g_qkvh); SYM(knvsh, g_knvsh); SYM(qnh, g_qnh);
    SYM(wh, g_wh); SYM(oh, g_oh); SYM(p1h, g_p1h); SYM(p2h, g_p2h);
    SYM(xh, g_xh); SYM(ih, g_ih); SYM(sh, g_sh);
    SYM(knTh, g_knTh); SYM(knTl, g_knTl); SYM(qnTh, g_qnTh); SYM(qnTl, g_qnTl);
    SYM(abh, g_abh); SYM(abl, g_abl);
    SYM(w3h, g_w3h); SYM(w3l, g_w3l); SYM(w2h, g_w2h); SYM(w2l, g_w2l);
    SYM(wqh, g_wqh); SYM(wql, g_wql); SYM(wph, g_wph); SYM(wpl, g_wpl);

    dim3 tb(32, 8);
    dim3 tw(16, 16, 1);
    transpose_split<<<tw, tb>>>(Wq,     C_, 0, w3h,               w3l,               C_, 0);
    transpose_split<<<tw, tb>>>(Wk,     C_, 0, w3h + C_ * C_,     w3l + C_ * C_,     C_, 0);
    transpose_split<<<tw, tb>>>(Wv,     C_, 0, w3h + 2 * C_ * C_, w3l + 2 * C_ * C_, C_, 0);
    transpose_split<<<tw, tb>>>(Wk_sif, C_, 0, w2h,               w2l,               C_, 0);
    transpose_split<<<tw, tb>>>(Wv_sif, C_, 0, w2h + C_ * C_,     w2l + C_ * C_,     C_, 0);
    transpose_split<<<tw, tb>>>(Wq_sif, C_, 0, wqh,               wql,               C_, 0);
    transpose_split<<<tw, tb>>>(proj_w, C_, 0, wph,               wpl,               C_, 0);

    long n4 = (long)MTOT * C_ / 4;
    split_hi3<<<(unsigned)((n4 + 255) / 256), 256>>>(x, illu, sem, xh, ih, sh, n4);

    // GEMM1 (1-pass): qkv(fp16) = x @ [Wq|Wk|Wv]
    gemm_h<1, 2><<<dim3(12, 256, 1), 256, 3 * 2 * TILE_B>>>(xh, nullptr, w3h, nullptr,
        nullptr, C_, C_, C_, 0, 0, 0, 0, nullptr, nullptr, 0, 0, 1.f,
        qkvh, 1536, 0, nullptr, 0, 0);
    cudaEventRecord(evA, 0);

    // --- fork: positional branch on s1 (needs v from GEMM1) ---
    cudaStreamWaitEvent(s1, evA, 0);
    dwconv3x3_h<true ><<<MTOT / 8, 128, 0, s1>>>(qkvh + 1024, 1536, dw1, p1h);
    dwconv3x3_h<false><<<MTOT / 8, 128, 0, s1>>>(p1h, 512, dw2, p2h);
    cudaEventRecord(evP, s1);

    // --- fork: MSA Gram branch on s2 (needs q,k from GEMM1) ---
    cudaStreamWaitEvent(s2, evA, 0);
    msa_g_hmma<<<dim3(64, GSLICE), 256, 0, s2>>>();
    msa_soft<<<64 * 64, 64, 0, s2>>>(rescale);
    cudaEventRecord(evM, s2);

    // --- SIF spine on default stream ---
    // GEMM2 (1-pass): [kn|vs](fp16) = illu @ [Wk_sif|Wv_sif]
    gemm_h<1, 2><<<dim3(8, 256, 1), 256, 3 * 2 * TILE_B>>>(ih, nullptr, w2h, nullptr,
        nullptr, C_, C_, C_, 0, 0, 0, 0, nullptr, nullptr, 0, 0, 1.f,
        knvsh, 1024, 0, nullptr, 0, 0);
    // GEMM3 (1-pass): qn(fp16) = sem @ Wq_sif
    gemm_h<1, 2><<<dim3(4, 256, 1), 256, 3 * 2 * TILE_B>>>(sh, nullptr, wqh, nullptr,
        nullptr, C_, C_, C_, 0, 0, 0, 0, nullptr, nullptr, 0, 0, 1.f,
        qnh, 512, 0, nullptr, 0, 0);

    ln_t_split<<<dim3(128, 8), 256, LNT_SMEM>>>(knvsh, 1024, (long)N_ * 1024,
        ln_g, ln_b, knTh, knTl, (long)C_ * N_);
    ln_t_split<<<dim3(128, 8), 256, LNT_SMEM>>>(qnh, 512, (long)N_ * 512,
        ln_g, ln_b, qnTh, qnTl, (long)C_ * N_);

    // GEMM4 (3-pass): Ab[b] = (Qn^T Kn)/sqrt(C)
    gemm_h<3, 1><<<dim3(4, 4, 8), 256, 3 * 4 * TILE_B>>>(qnTh, qnTl, knTh, knTl,
        ab, N_, N_, N_, C_, (long)C_ * N_, (long)C_ * N_, (long)C_ * C_,
        nullptr, nullptr, 0, 0, 0.044194173824159216f, nullptr, 0, 0, nullptr, 0, 0);

    softmax_ab<<<B_ * C_, 128>>>(ab, abh, abl);

    // GEMM5 (1-pass): w(fp16) = (V@Ab^T + V) * v
    gemm_h<1, 2><<<dim3(4, 32, 8), 256, 3 * 2 * TILE_B>>>(knvsh + 512, nullptr, abh, nullptr,
        nullptr, C_, 1024, C_, 0, (long)N_ * 1024, (long)C_ * C_, 0,
        nullptr, knvsh + 512, 1024, (long)N_ * 1024, 1.f,
        wh, 512, (long)N_ * C_, qkvh + 1024, 1536, (long)N_ * 1536);

    // --- join: msa_o needs attn (s2) + w (default) ---
    cudaStreamWaitEvent(0, evM, 0);
    msa_o_hmma<<<dim3(32, 64), 256>>>();

    // --- join: GEMM6 needs p2 (s1) + o (default) ---
    cudaStreamWaitEvent(0, evP, 0);
    gemm_h<2, 2><<<dim3(4, 256, 1), 256, 3 * 3 * TILE_B>>>(oh, nullptr, wph, wpl,
        out, C_, C_, C_, C_, 0, 0, 0, proj_b, p2h, C_, 0, 1.f,
        nullptr, 0, 0, nullptr, 0, 0);
}